// round 5
// baseline (speedup 1.0000x reference)
#include <cuda_runtime.h>

// Fused transformer decoder block, one CTA per batch element, fp32, 512 threads.
// B=512, T=128, D=128, H=6, Dh=21, Dcat=126, D_FF=512.

#define NB 512
#define TT 128
#define DM 128
#define NH 6
#define DF 512
#define EPSF 1e-5f
#define SCALE 0.21821789023599236f   // 1/sqrt(21)
#define SS 132                        // S/P row stride
#define THREADS 512

typedef unsigned long long u64;

__device__ __forceinline__ u64 pack2(float lo, float hi){
  u64 r; asm("mov.b64 %0,{%1,%2};" : "=l"(r) : "f"(lo), "f"(hi)); return r;
}
__device__ __forceinline__ void unpack2(u64 v, float& lo, float& hi){
  asm("mov.b64 {%0,%1},%2;" : "=f"(lo), "=f"(hi) : "l"(v));
}
__device__ __forceinline__ u64 ffma2(u64 a, u64 b, u64 c){
  u64 d; asm("fma.rn.f32x2 %0,%1,%2,%3;" : "=l"(d) : "l"(a), "l"(b), "l"(c)); return d;
}
__device__ __forceinline__ float wredsum(float v){
  #pragma unroll
  for (int o = 16; o > 0; o >>= 1) v += __shfl_xor_sync(0xffffffffu, v, o);
  return v;
}
__device__ __forceinline__ float wredmax(float v){
  #pragma unroll
  for (int o = 16; o > 0; o >>= 1) v = fmaxf(v, __shfl_xor_sync(0xffffffffu, v, o));
  return v;
}
#define GBAR(id) asm volatile("bar.sync %0, %1;" :: "r"(id), "r"(256) : "memory")

// smem layout (floats):
//  xs     [0     ,16384)  residual stream x / x2
//  hs     [16384 ,32768)  ln1(x), ln2(x2), then FFN kg1 partial C
//  wb     [32768 ,49664)  16896: qkvs(68-stride)+wqkv | Ssm(132-stride) | wos(24x128) | ffn kg0+kg1-w1t
//  region [49664 ,58112)  8448: q(21)|kt(21x128)|v(24-stride)  /  osm(24)  /  ffn kg1 w2t+ub
#define SMEM_FLOATS 58112   // 232448 bytes

extern "C" __global__ void __launch_bounds__(THREADS, 1)
decoder_block_kernel(const float* __restrict__ gx,
                     const float* __restrict__ Wq,
                     const float* __restrict__ Wk,
                     const float* __restrict__ Wv,
                     const float* __restrict__ Wo,
                     const float* __restrict__ bo,
                     const float* __restrict__ W1,
                     const float* __restrict__ b1,
                     const float* __restrict__ W2,
                     const float* __restrict__ b2,
                     const float* __restrict__ g1,
                     const float* __restrict__ be1,
                     const float* __restrict__ g2,
                     const float* __restrict__ be2,
                     float* __restrict__ gout)
{
  extern __shared__ float sm[];
  float* xs     = sm;
  float* hs     = sm + 16384;
  float* wb     = sm + 32768;
  float* region = sm + 49664;

  float* qkvs = wb;              // 128 x 68
  float* wqkv = wb + 8704;       // 128 x 64
  float* Ssm  = wb;              // 128 x 132
  float* wosm = wb;              // 24 x 128 (fold phase)
  float* qsm  = region;          // 128 x 21
  float* kts  = region + 2688;   // 21 x 128
  float* vsm  = region + 5376;   // 128 x 24 (cols 21..23 zero)
  float* osm  = region;          // 128 x 24 (overlays q/kt after S done)

  const int tid  = threadIdx.x;
  const int lane = tid & 31;
  const int w    = tid >> 5;
  const int b    = blockIdx.x;

  const float* xb = gx   + (size_t)b * (TT * DM);
  float*       ob = gout + (size_t)b * (TT * DM);

  // ---------------- load x ----------------
  {
    const float4* src = (const float4*)xb;
    float4* dst = (float4*)xs;
    #pragma unroll
    for (int i = 0; i < 8; i++) dst[tid + THREADS * i] = src[tid + THREADS * i];
  }
  __syncthreads();

  // ---------------- LN1 -> hs ----------------
  {
    float gv[4], bv[4];
    #pragma unroll
    for (int c = 0; c < 4; c++){ gv[c] = g1[c*32 + lane]; bv[c] = be1[c*32 + lane]; }
    for (int r = w; r < TT; r += 16){
      float v[4], s = 0.f, s2 = 0.f;
      #pragma unroll
      for (int c = 0; c < 4; c++){
        v[c] = xs[r*DM + c*32 + lane];
        s += v[c]; s2 += v[c]*v[c];
      }
      s = wredsum(s); s2 = wredsum(s2);
      float mu = s * (1.f/DM);
      float rs = rsqrtf(s2 * (1.f/DM) - mu*mu + EPSF);
      #pragma unroll
      for (int c = 0; c < 4; c++)
        hs[r*DM + c*32 + lane] = (v[c] - mu) * rs * gv[c] + bv[c];
    }
  }
  __syncthreads();

  // ---------------- attention, per head ----------------
  for (int hh = 0; hh < NH; hh++){
    // stage wqkv (128 x 64 = [Wq|Wk|Wv|0])
    for (int idx = tid; idx < 2688; idx += THREADS){
      int d = idx / 21, e = idx - d*21;
      wqkv[d*64 +      e] = Wq[hh*2688 + idx];
      wqkv[d*64 + 21 + e] = Wk[hh*2688 + idx];
      wqkv[d*64 + 42 + e] = Wv[hh*2688 + idx];
    }
    if (tid < 128) wqkv[tid*64 + 63] = 0.f;
    __syncthreads();

    // qkv GEMM: qkvs(128x64,str68) = hs(128x128) @ wqkv(128x64); 4x4 tiles
    {
      u64 acc[4][2];
      #pragma unroll
      for (int i = 0; i < 4; i++){ acc[i][0] = 0ull; acc[i][1] = 0ull; }
      const int row = (tid >> 4) * 4, col = (tid & 15) * 4;
      for (int k = 0; k < DM; k += 4){
        float4 a4[4];
        #pragma unroll
        for (int i = 0; i < 4; i++) a4[i] = *(const float4*)&hs[(row+i)*DM + k];
        u64 bb[4][2];
        #pragma unroll
        for (int kk = 0; kk < 4; kk++){
          float4 b4 = *(const float4*)&wqkv[(k+kk)*64 + col];
          bb[kk][0] = pack2(b4.x, b4.y); bb[kk][1] = pack2(b4.z, b4.w);
        }
        #pragma unroll
        for (int kk = 0; kk < 4; kk++){
          #pragma unroll
          for (int i = 0; i < 4; i++){
            float av = (kk==0) ? a4[i].x : (kk==1) ? a4[i].y : (kk==2) ? a4[i].z : a4[i].w;
            u64 aa = pack2(av, av);
            acc[i][0] = ffma2(aa, bb[kk][0], acc[i][0]);
            acc[i][1] = ffma2(aa, bb[kk][1], acc[i][1]);
          }
        }
      }
      #pragma unroll
      for (int i = 0; i < 4; i++){
        float f0,f1,f2,f3;
        unpack2(acc[i][0], f0, f1); unpack2(acc[i][1], f2, f3);
        *(float4*)&qkvs[(row+i)*68 + col] = make_float4(f0,f1,f2,f3);
      }
    }
    __syncthreads();

    // scatter: q(scaled), k^T, v (padded 24)
    for (int idx = tid; idx < 2688; idx += THREADS){
      int t = idx / 21, e = idx - t*21;
      qsm[idx] = qkvs[t*68 + e] * SCALE;
    }
    for (int idx = tid; idx < 2688; idx += THREADS){
      int e = idx >> 7, t = idx & 127;
      kts[idx] = qkvs[t*68 + 21 + e];
    }
    for (int idx = tid; idx < 3072; idx += THREADS){
      int t = idx / 24, e = idx - t*24;
      vsm[idx] = (e < 21) ? qkvs[t*68 + 42 + e] : 0.f;
    }
    __syncthreads();

    // S(128x128) = q @ k^T ; 4x8 tiles
    {
      u64 acc[4][4];
      #pragma unroll
      for (int i = 0; i < 4; i++)
        #pragma unroll
        for (int j = 0; j < 4; j++) acc[i][j] = 0ull;
      const int row = (tid >> 4) * 4, col = (tid & 15) * 8;
      #pragma unroll
      for (int e = 0; e < 21; e++){
        float qv[4];
        #pragma unroll
        for (int i = 0; i < 4; i++) qv[i] = qsm[(row+i)*21 + e];
        float4 k0 = *(const float4*)&kts[e*128 + col];
        float4 k1 = *(const float4*)&kts[e*128 + col + 4];
        u64 kb[4] = { pack2(k0.x,k0.y), pack2(k0.z,k0.w),
                      pack2(k1.x,k1.y), pack2(k1.z,k1.w) };
        #pragma unroll
        for (int i = 0; i < 4; i++){
          u64 aa = pack2(qv[i], qv[i]);
          #pragma unroll
          for (int j = 0; j < 4; j++) acc[i][j] = ffma2(aa, kb[j], acc[i][j]);
        }
      }
      #pragma unroll
      for (int i = 0; i < 4; i++){
        float f[8];
        #pragma unroll
        for (int j = 0; j < 4; j++) unpack2(acc[i][j], f[2*j], f[2*j+1]);
        *(float4*)&Ssm[(row+i)*SS + col]     = make_float4(f[0],f[1],f[2],f[3]);
        *(float4*)&Ssm[(row+i)*SS + col + 4] = make_float4(f[4],f[5],f[6],f[7]);
      }
    }
    __syncthreads();

    // masked softmax (warp per row)
    for (int r = w; r < TT; r += 16){
      float v[4];
      #pragma unroll
      for (int kb = 0; kb < 4; kb++){
        int c = kb*32 + lane;
        float s = Ssm[r*SS + c];
        v[kb] = (c <= r) ? s : -1e30f;
      }
      float m = fmaxf(fmaxf(v[0], v[1]), fmaxf(v[2], v[3]));
      m = wredmax(m);
      float p[4], psum = 0.f;
      #pragma unroll
      for (int kb = 0; kb < 4; kb++){ p[kb] = __expf(v[kb] - m); psum += p[kb]; }
      psum = wredsum(psum);
      float inv = 1.f / psum;
      #pragma unroll
      for (int kb = 0; kb < 4; kb++){
        int c = kb*32 + lane;
        Ssm[r*SS + c] = p[kb] * inv;
      }
    }
    __syncthreads();

    // O(128x24) = P @ v ; 1x6 tiles, FFMA2
    {
      const int row = tid >> 2;
      const int col = (tid & 3) * 6;
      u64 acc[3] = {0ull, 0ull, 0ull};
      for (int j = 0; j < 128; j += 4){
        float4 pr = *(const float4*)&Ssm[row*SS + j];
        #pragma unroll
        for (int jj = 0; jj < 4; jj++){
          float pv = (jj==0) ? pr.x : (jj==1) ? pr.y : (jj==2) ? pr.z : pr.w;
          const float* vr = &vsm[(j+jj)*24 + col];
          float2 v0 = *(const float2*)(vr);
          float2 v1 = *(const float2*)(vr + 2);
          float2 v2 = *(const float2*)(vr + 4);
          u64 pp = pack2(pv, pv);
          acc[0] = ffma2(pp, pack2(v0.x, v0.y), acc[0]);
          acc[1] = ffma2(pp, pack2(v1.x, v1.y), acc[1]);
          acc[2] = ffma2(pp, pack2(v2.x, v2.y), acc[2]);
        }
      }
      // osm overlays q/kt: both dead after S GEMM (synced). Safe to write now.
      float f[6];
      unpack2(acc[0], f[0], f[1]); unpack2(acc[1], f[2], f[3]); unpack2(acc[2], f[4], f[5]);
      float* od = &osm[row*24 + col];
      *(float2*)(od)     = make_float2(f[0], f[1]);
      *(float2*)(od + 2) = make_float2(f[2], f[3]);
      *(float2*)(od + 4) = make_float2(f[4], f[5]);
    }
    __syncthreads();

    // stage wos (24 x 128, rows 21..23 zero) into wb (Ssm dead)
    for (int idx = tid; idx < 3072; idx += THREADS){
      int e = idx >> 7, c = idx & 127;
      wosm[idx] = (e < 21) ? Wo[(hh*21 + e)*DM + c] : 0.f;
    }
    __syncthreads();

    // fold: xs += O(128x24) @ wos(24x128) ; 4x8 tiles, k=24 (pads zero)
    {
      u64 acc[4][4];
      #pragma unroll
      for (int i = 0; i < 4; i++)
        #pragma unroll
        for (int j = 0; j < 4; j++) acc[i][j] = 0ull;
      const int row = (tid >> 4) * 4, col = (tid & 15) * 8;
      #pragma unroll
      for (int eb = 0; eb < 24; eb += 4){
        float4 a4[4];
        #pragma unroll
        for (int i = 0; i < 4; i++) a4[i] = *(const float4*)&osm[(row+i)*24 + eb];
        #pragma unroll
        for (int ee = 0; ee < 4; ee++){
          float4 w0 = *(const float4*)&wosm[(eb+ee)*128 + col];
          float4 w1 = *(const float4*)&wosm[(eb+ee)*128 + col + 4];
          u64 wp[4] = { pack2(w0.x,w0.y), pack2(w0.z,w0.w),
                        pack2(w1.x,w1.y), pack2(w1.z,w1.w) };
          #pragma unroll
          for (int i = 0; i < 4; i++){
            float av = (ee==0) ? a4[i].x : (ee==1) ? a4[i].y : (ee==2) ? a4[i].z : a4[i].w;
            u64 aa = pack2(av, av);
            #pragma unroll
            for (int j = 0; j < 4; j++) acc[i][j] = ffma2(aa, wp[j], acc[i][j]);
          }
        }
      }
      #pragma unroll
      for (int i = 0; i < 4; i++){
        float f[8];
        #pragma unroll
        for (int j = 0; j < 4; j++) unpack2(acc[i][j], f[2*j], f[2*j+1]);
        float4 x0 = *(const float4*)&xs[(row+i)*DM + col];
        float4 x1 = *(const float4*)&xs[(row+i)*DM + col + 4];
        x0.x += f[0]; x0.y += f[1]; x0.z += f[2]; x0.w += f[3];
        x1.x += f[4]; x1.y += f[5]; x1.z += f[6]; x1.w += f[7];
        *(float4*)&xs[(row+i)*DM + col]     = x0;
        *(float4*)&xs[(row+i)*DM + col + 4] = x1;
      }
    }
    __syncthreads();
  }

  // ---------------- add bo, LN2 -> hs ----------------
  {
    float gv[4], bv[4], bov[4];
    #pragma unroll
    for (int c = 0; c < 4; c++){
      gv[c] = g2[c*32 + lane]; bv[c] = be2[c*32 + lane]; bov[c] = bo[c*32 + lane];
    }
    for (int r = w; r < TT; r += 16){
      float v[4], s = 0.f, s2 = 0.f;
      #pragma unroll
      for (int c = 0; c < 4; c++){
        v[c] = xs[r*DM + c*32 + lane] + bov[c];
        xs[r*DM + c*32 + lane] = v[c];            // xs now x2
        s += v[c]; s2 += v[c]*v[c];
      }
      s = wredsum(s); s2 = wredsum(s2);
      float mu = s * (1.f/DM);
      float rs = rsqrtf(s2 * (1.f/DM) - mu*mu + EPSF);
      #pragma unroll
      for (int c = 0; c < 4; c++)
        hs[r*DM + c*32 + lane] = (v[c] - mu) * rs * gv[c] + bv[c];
    }
  }
  __syncthreads();

  // ---------------- FFN: split-kt across two 256-thread groups ----------------
  {
    const int kg   = tid >> 8;        // 0 or 1
    const int stid = tid & 255;
    const int barid = 1 + kg;
    float* w1t = kg ? (wb + 12288)    : wb;            // 128 x 32
    float* w2t = kg ? region          : (wb + 4096);   // 32 x 128
    float* ub  = kg ? (region + 4096) : (wb + 8192);   // 128 x 32

    const int ty = stid >> 4, tx = stid & 15;
    const int row = ty*8, col = tx*8;
    const int urow = (stid >> 3) * 4, ucol = (stid & 7) * 4;

    u64 cacc[8][4];
    #pragma unroll
    for (int i = 0; i < 8; i++)
      #pragma unroll
      for (int j = 0; j < 4; j++) cacc[i][j] = 0ull;

    for (int it = 0; it < 8; it++){
      const int kt = kg*8 + it;
      for (int idx = stid; idx < 4096; idx += 256){
        int d = idx >> 5, c = idx & 31;
        w1t[idx] = W1[d*DF + kt*32 + c];
        w2t[idx] = W2[kt*32*DM + idx];
      }
      GBAR(barid);

      // U(128x32) = relu(hs @ w1t + b1); 4x4 tiles
      {
        u64 cu[4][2];
        #pragma unroll
        for (int i = 0; i < 4; i++){ cu[i][0] = 0ull; cu[i][1] = 0ull; }
        for (int k = 0; k < DM; k += 4){
          float4 a4[4];
          #pragma unroll
          for (int i = 0; i < 4; i++) a4[i] = *(const float4*)&hs[(urow+i)*DM + k];
          u64 bb[4][2];
          #pragma unroll
          for (int kk = 0; kk < 4; kk++){
            float4 b4 = *(const float4*)&w1t[(k+kk)*32 + ucol];
            bb[kk][0] = pack2(b4.x, b4.y); bb[kk][1] = pack2(b4.z, b4.w);
          }
          #pragma unroll
          for (int kk = 0; kk < 4; kk++){
            #pragma unroll
            for (int i = 0; i < 4; i++){
              float av = (kk==0) ? a4[i].x : (kk==1) ? a4[i].y : (kk==2) ? a4[i].z : a4[i].w;
              u64 aa = pack2(av, av);
              cu[i][0] = ffma2(aa, bb[kk][0], cu[i][0]);
              cu[i][1] = ffma2(aa, bb[kk][1], cu[i][1]);
            }
          }
        }
        float4 b1v = *(const float4*)&b1[kt*32 + ucol];
        #pragma unroll
        for (int i = 0; i < 4; i++){
          float f0,f1,f2,f3;
          unpack2(cu[i][0], f0, f1); unpack2(cu[i][1], f2, f3);
          f0 = fmaxf(f0 + b1v.x, 0.f); f1 = fmaxf(f1 + b1v.y, 0.f);
          f2 = fmaxf(f2 + b1v.z, 0.f); f3 = fmaxf(f3 + b1v.w, 0.f);
          *(float4*)&ub[(urow+i)*32 + ucol] = make_float4(f0,f1,f2,f3);
        }
      }
      GBAR(barid);

      // cacc += ub(128x32) @ w2t(32x128); 8x8 tiles
      for (int k = 0; k < 32; k += 4){
        float4 a4[8];
        #pragma unroll
        for (int i = 0; i < 8; i++) a4[i] = *(const float4*)&ub[(row+i)*32 + k];
        u64 bb[4][4];
        #pragma unroll
        for (int kk = 0; kk < 4; kk++){
          float4 x0 = *(const float4*)&w2t[(k+kk)*DM + col];
          float4 x1 = *(const float4*)&w2t[(k+kk)*DM + col + 4];
          bb[kk][0] = pack2(x0.x, x0.y); bb[kk][1] = pack2(x0.z, x0.w);
          bb[kk][2] = pack2(x1.x, x1.y); bb[kk][3] = pack2(x1.z, x1.w);
        }
        #pragma unroll
        for (int kk = 0; kk < 4; kk++){
          #pragma unroll
          for (int i = 0; i < 8; i++){
            float av = (kk==0) ? a4[i].x : (kk==1) ? a4[i].y : (kk==2) ? a4[i].z : a4[i].w;
            u64 aa = pack2(av, av);
            #pragma unroll
            for (int j = 0; j < 4; j++) cacc[i][j] = ffma2(aa, bb[kk][j], cacc[i][j]);
          }
        }
      }
      GBAR(barid);
    }

    __syncthreads();           // both groups done; hs now dead
    if (kg == 1){
      #pragma unroll
      for (int i = 0; i < 8; i++){
        float f[8];
        #pragma unroll
        for (int j = 0; j < 4; j++) unpack2(cacc[i][j], f[2*j], f[2*j+1]);
        *(float4*)&hs[(row+i)*DM + col]     = make_float4(f[0],f[1],f[2],f[3]);
        *(float4*)&hs[(row+i)*DM + col + 4] = make_float4(f[4],f[5],f[6],f[7]);
      }
    }
    __syncthreads();
    if (kg == 0){
      float4 b2a = *(const float4*)&b2[col];
      float4 b2b = *(const float4*)&b2[col + 4];
      #pragma unroll
      for (int i = 0; i < 8; i++){
        float f[8];
        #pragma unroll
        for (int j = 0; j < 4; j++) unpack2(cacc[i][j], f[2*j], f[2*j+1]);
        float4 p0 = *(const float4*)&hs[(row+i)*DM + col];
        float4 p1 = *(const float4*)&hs[(row+i)*DM + col + 4];
        float4 x0 = *(const float4*)&xs[(row+i)*DM + col];
        float4 x1 = *(const float4*)&xs[(row+i)*DM + col + 4];
        float4 o0 = make_float4(x0.x + p0.x + f[0] + b2a.x, x0.y + p0.y + f[1] + b2a.y,
                                x0.z + p0.z + f[2] + b2a.z, x0.w + p0.w + f[3] + b2a.w);
        float4 o1 = make_float4(x1.x + p1.x + f[4] + b2b.x, x1.y + p1.y + f[5] + b2b.y,
                                x1.z + p1.z + f[6] + b2b.z, x1.w + p1.w + f[7] + b2b.w);
        *(float4*)&ob[(row+i)*DM + col]     = o0;
        *(float4*)&ob[(row+i)*DM + col + 4] = o1;
      }
    }
  }
}

extern "C" void kernel_launch(void* const* d_in, const int* in_sizes, int n_in,
                              void* d_out, int out_size)
{
  (void)in_sizes; (void)n_in; (void)out_size;
  cudaFuncSetAttribute(decoder_block_kernel,
                       cudaFuncAttributeMaxDynamicSharedMemorySize,
                       SMEM_FLOATS * 4);
  decoder_block_kernel<<<NB, THREADS, SMEM_FLOATS * 4>>>(
      (const float*)d_in[0],  (const float*)d_in[1],  (const float*)d_in[2],
      (const float*)d_in[3],  (const float*)d_in[4],  (const float*)d_in[5],
      (const float*)d_in[6],  (const float*)d_in[7],  (const float*)d_in[8],
      (const float*)d_in[9],  (const float*)d_in[10], (const float*)d_in[11],
      (const float*)d_in[12], (const float*)d_in[13],
      (float*)d_out);
}

// round 7
// speedup vs baseline: 1.4089x; 1.4089x over previous
#include <cuda_runtime.h>
#include <cstdint>

// Fused transformer decoder block, one CTA per batch element.
// QKV + FFN: warp-level mma.sync m16n8k8 tf32 (fp32 accumulate).
// S / softmax / O / Wo-fold: fp32 FFMA2 register-tiled.
// B=512, T=128, D=128, H=6, Dh=21, D_FF=512.

#define NB 512
#define TT 128
#define DM 128
#define NH 6
#define DF 512
#define EPSF 1e-5f
#define SCALE 0.21821789023599236f   // 1/sqrt(21)
#define SS 128                        // S/P row stride
#define HSS 132                       // hs row stride (mma-A conflict-free)

typedef unsigned long long u64;

__device__ __forceinline__ u64 pack2(float lo, float hi){
  u64 r; asm("mov.b64 %0,{%1,%2};" : "=l"(r) : "f"(lo), "f"(hi)); return r;
}
__device__ __forceinline__ void unpack2(u64 v, float& lo, float& hi){
  asm("mov.b64 {%0,%1},%2;" : "=f"(lo), "=f"(hi) : "l"(v));
}
__device__ __forceinline__ u64 ffma2(u64 a, u64 b, u64 c){
  u64 d; asm("fma.rn.f32x2 %0,%1,%2,%3;" : "=l"(d) : "l"(a), "l"(b), "l"(c)); return d;
}
__device__ __forceinline__ float wredsum(float v){
  #pragma unroll
  for (int o = 16; o > 0; o >>= 1) v += __shfl_xor_sync(0xffffffffu, v, o);
  return v;
}
__device__ __forceinline__ float wredmax(float v){
  #pragma unroll
  for (int o = 16; o > 0; o >>= 1) v = fmaxf(v, __shfl_xor_sync(0xffffffffu, v, o));
  return v;
}
__device__ __forceinline__ uint32_t f2tf(float f){
  uint32_t r; asm("cvt.rna.tf32.f32 %0, %1;" : "=r"(r) : "f"(f)); return r;
}
__device__ __forceinline__ float tfbits(float f){
  return __uint_as_float(f2tf(f));
}
// D(16x8) += A(16x8,row) * B(8x8,col); tf32 in, fp32 out.
__device__ __forceinline__ void mma8(float* d, uint32_t a0, uint32_t a1,
                                     uint32_t a2, uint32_t a3,
                                     uint32_t b0, uint32_t b1){
  asm volatile("mma.sync.aligned.m16n8k8.row.col.f32.tf32.tf32.f32 "
    "{%0,%1,%2,%3},{%4,%5,%6,%7},{%8,%9},{%0,%1,%2,%3};"
    : "+f"(d[0]), "+f"(d[1]), "+f"(d[2]), "+f"(d[3])
    : "r"(a0), "r"(a1), "r"(a2), "r"(a3), "r"(b0), "r"(b1));
}

// smem layout (floats):
//  xs   [0     ,16384)  residual stream
//  hs   [16384 ,33280)  ln output, stride 132
//  scr  [33280 ,49664)  Ssm(str128) / wqkvT[64][132] / wosm(21x128) / FFN wt[64][136]
//  qsm  [49664 ,52352)  q 128x21 (osm 128x24 overlays q..kt)
//  kts  [52352 ,55040)  k^T 21x128
//  vsm  [55040 ,57728)  v 128x21 (+slack overread ok)
//  FFN: Ubuf [41984, 50688) [128][68]
#define SMEM_FLOATS 58112   // 232448 bytes

extern "C" __global__ void __launch_bounds__(256, 1)
decoder_block_kernel(const float* __restrict__ gx,
                     const float* __restrict__ Wq,
                     const float* __restrict__ Wk,
                     const float* __restrict__ Wv,
                     const float* __restrict__ Wo,
                     const float* __restrict__ bo,
                     const float* __restrict__ W1,
                     const float* __restrict__ b1,
                     const float* __restrict__ W2,
                     const float* __restrict__ b2,
                     const float* __restrict__ g1,
                     const float* __restrict__ be1,
                     const float* __restrict__ g2,
                     const float* __restrict__ be2,
                     float* __restrict__ gout)
{
  extern __shared__ float sm[];
  float* xs    = sm;
  float* hs    = sm + 16384;       // stride HSS=132
  float* scr   = sm + 33280;
  float* Ssm   = scr;              // stride 128
  float* wqkvT = scr;              // [64][132]
  float* wosm  = scr;              // 21 x 128
  float* wt    = scr;              // FFN weight chunk (<= [64][136])
  float* Ubuf  = sm + 41984;       // [128][68]
  float* qsm   = sm + 49664;       // 128 x 21
  float* kts   = sm + 52352;       // 21 x 128
  float* vsm   = sm + 55040;       // 128 x 21
  float* osm   = qsm;              // 128 x 24, overlays q/kt after S

  const int tid  = threadIdx.x;
  const int lane = tid & 31;
  const int w    = tid >> 5;
  const int tx   = tid & 15;
  const int ty   = tid >> 4;
  const int b    = blockIdx.x;

  const int qr   = lane >> 2;      // mma quad row 0..7
  const int qc   = lane & 3;       // mma quad col 0..3
  const int row0 = w * 16;         // mma warp row base

  const float* xb = gx   + (size_t)b * (TT * DM);
  float*       ob = gout + (size_t)b * (TT * DM);

  // ---------------- load x ----------------
  {
    const float4* src = (const float4*)xb;
    float4* dst = (float4*)xs;
    #pragma unroll
    for (int i = 0; i < 16; i++) dst[tid + 256 * i] = src[tid + 256 * i];
  }
  __syncthreads();

  // ---------------- LN1 -> hs (tf32-rounded, stride 132) ----------------
  {
    float gv[4], bv[4];
    #pragma unroll
    for (int c = 0; c < 4; c++){ gv[c] = g1[c*32 + lane]; bv[c] = be1[c*32 + lane]; }
    for (int r = w; r < TT; r += 8){
      float v[4], s = 0.f, s2 = 0.f;
      #pragma unroll
      for (int c = 0; c < 4; c++){
        v[c] = xs[r*DM + c*32 + lane];
        s += v[c]; s2 += v[c]*v[c];
      }
      s = wredsum(s); s2 = wredsum(s2);
      float mu = s * (1.f/DM);
      float rs = rsqrtf(s2 * (1.f/DM) - mu*mu + EPSF);
      #pragma unroll
      for (int c = 0; c < 4; c++)
        hs[r*HSS + c*32 + lane] = tfbits((v[c] - mu) * rs * gv[c] + bv[c]);
    }
  }
  __syncthreads();

  // ---------------- attention, head by head ----------------
  for (int hh = 0; hh < NH; hh++){
    // stage wqkvT[n][k] (n: 0..20 q, 21..41 k, 42..62 v, 63 zero), tf32
    for (int idx = tid; idx < 8192; idx += 256){
      int n = idx & 63, k = idx >> 6;
      float v;
      if (n < 21)      v = Wq[hh*2688 + k*21 + n];
      else if (n < 42) v = Wk[hh*2688 + k*21 + (n-21)];
      else if (n < 63) v = Wv[hh*2688 + k*21 + (n-42)];
      else             v = 0.f;
      wqkvT[n*HSS + k] = tfbits(v);
    }
    __syncthreads();

    // qkv = hs(128x128) @ wqkv(128x64) via mma; scatter C-frags to q/kT/v
    {
      float qacc[8][4];
      #pragma unroll
      for (int nf = 0; nf < 8; nf++)
        #pragma unroll
        for (int j = 0; j < 4; j++) qacc[nf][j] = 0.f;

      for (int ks = 0; ks < 16; ks++){
        const float* ap = &hs[(row0 + qr)*HSS + ks*8 + qc];
        uint32_t a0 = __float_as_uint(ap[0]);
        uint32_t a1 = __float_as_uint(ap[8*HSS]);
        uint32_t a2 = __float_as_uint(ap[4]);
        uint32_t a3 = __float_as_uint(ap[8*HSS + 4]);
        #pragma unroll
        for (int nf = 0; nf < 8; nf++){
          const float* bp = &wqkvT[(nf*8 + qr)*HSS + ks*8 + qc];
          uint32_t b0 = __float_as_uint(bp[0]);
          uint32_t b1 = __float_as_uint(bp[4]);
          mma8(qacc[nf], a0, a1, a2, a3, b0, b1);
        }
      }
      // scatter
      #pragma unroll
      for (int nf = 0; nf < 8; nf++){
        int c0 = nf*8 + 2*qc;
        int r0 = row0 + qr;
        #pragma unroll
        for (int part = 0; part < 4; part++){
          int cc = c0 + (part & 1);
          int rr = r0 + (part >> 1) * 8;
          float vv = qacc[nf][part];
          if (cc < 21)       qsm[rr*21 + cc] = vv * SCALE;
          else if (cc < 42)  kts[(cc-21)*128 + rr] = vv;
          else if (cc < 63)  vsm[rr*21 + (cc-42)] = vv;
        }
      }
    }
    __syncthreads();

    // S(128x128) = q @ k^T (k=21); FFMA2 8x8 tiles
    {
      u64 acc[8][4];
      #pragma unroll
      for (int i = 0; i < 8; i++)
        #pragma unroll
        for (int j = 0; j < 4; j++) acc[i][j] = 0ull;
      const int row = ty*8, col = tx*8;
      #pragma unroll
      for (int e = 0; e < 21; e++){
        float qv[8];
        #pragma unroll
        for (int i = 0; i < 8; i++) qv[i] = qsm[(row+i)*21 + e];
        float4 k0 = *(const float4*)&kts[e*128 + col];
        float4 k1 = *(const float4*)&kts[e*128 + col + 4];
        u64 kb[4] = { pack2(k0.x,k0.y), pack2(k0.z,k0.w),
                      pack2(k1.x,k1.y), pack2(k1.z,k1.w) };
        #pragma unroll
        for (int i = 0; i < 8; i++){
          u64 aa = pack2(qv[i], qv[i]);
          #pragma unroll
          for (int j = 0; j < 4; j++) acc[i][j] = ffma2(aa, kb[j], acc[i][j]);
        }
      }
      #pragma unroll
      for (int i = 0; i < 8; i++){
        float f[8];
        #pragma unroll
        for (int j = 0; j < 4; j++) unpack2(acc[i][j], f[2*j], f[2*j+1]);
        *(float4*)&Ssm[(row+i)*SS + col]     = make_float4(f[0],f[1],f[2],f[3]);
        *(float4*)&Ssm[(row+i)*SS + col + 4] = make_float4(f[4],f[5],f[6],f[7]);
      }
    }
    __syncthreads();

    // masked softmax (warp per row)
    for (int r = w; r < TT; r += 8){
      float v[4];
      #pragma unroll
      for (int kb = 0; kb < 4; kb++){
        int c = kb*32 + lane;
        float s = Ssm[r*SS + c];
        v[kb] = (c <= r) ? s : -1e30f;
      }
      float m = fmaxf(fmaxf(v[0], v[1]), fmaxf(v[2], v[3]));
      m = wredmax(m);
      float p[4], psum = 0.f;
      #pragma unroll
      for (int kb = 0; kb < 4; kb++){ p[kb] = __expf(v[kb] - m); psum += p[kb]; }
      psum = wredsum(psum);
      float inv = 1.f / psum;
      #pragma unroll
      for (int kb = 0; kb < 4; kb++){
        int c = kb*32 + lane;
        Ssm[r*SS + c] = p[kb] * inv;
      }
    }
    __syncthreads();

    // O(128x24) = P @ v (cols >= 21 garbage, unused)
    {
      const int rg = tid >> 3, cg = tid & 7;
      const int r0 = rg*4, c0 = cg*3;
      float acc[4][3];
      #pragma unroll
      for (int i = 0; i < 4; i++)
        #pragma unroll
        for (int u = 0; u < 3; u++) acc[i][u] = 0.f;
      for (int j = 0; j < 128; j += 4){
        float4 pr[4];
        #pragma unroll
        for (int i = 0; i < 4; i++) pr[i] = *(const float4*)&Ssm[(r0+i)*SS + j];
        float vv[4][3];
        #pragma unroll
        for (int jj = 0; jj < 4; jj++)
          #pragma unroll
          for (int u = 0; u < 3; u++) vv[jj][u] = vsm[(j+jj)*21 + c0 + u];
        #pragma unroll
        for (int jj = 0; jj < 4; jj++){
          #pragma unroll
          for (int i = 0; i < 4; i++){
            float pv = (jj==0) ? pr[i].x : (jj==1) ? pr[i].y : (jj==2) ? pr[i].z : pr[i].w;
            #pragma unroll
            for (int u = 0; u < 3; u++) acc[i][u] += pv * vv[jj][u];
          }
        }
      }
      __syncthreads();   // P/q/kt dead; osm overlays q/kt
      #pragma unroll
      for (int i = 0; i < 4; i++)
        #pragma unroll
        for (int u = 0; u < 3; u++) osm[(r0+i)*24 + c0 + u] = acc[i][u];
    }
    __syncthreads();

    // stage wosm (21 x 128)
    for (int idx = tid; idx < 2688; idx += 256)
      wosm[idx] = Wo[hh*21*DM + idx];
    __syncthreads();

    // xs += O @ Wo-slice (k=21); FFMA2 8x8 tiles
    {
      u64 acc[8][4];
      #pragma unroll
      for (int i = 0; i < 8; i++)
        #pragma unroll
        for (int j = 0; j < 4; j++) acc[i][j] = 0ull;
      const int row = ty*8, col = tx*8;
      #pragma unroll
      for (int e = 0; e < 21; e++){
        float ov[8];
        #pragma unroll
        for (int i = 0; i < 8; i++) ov[i] = osm[(row+i)*24 + e];
        float4 w0 = *(const float4*)&wosm[e*128 + col];
        float4 w1 = *(const float4*)&wosm[e*128 + col + 4];
        u64 kb[4] = { pack2(w0.x,w0.y), pack2(w0.z,w0.w),
                      pack2(w1.x,w1.y), pack2(w1.z,w1.w) };
        #pragma unroll
        for (int i = 0; i < 8; i++){
          u64 aa = pack2(ov[i], ov[i]);
          #pragma unroll
          for (int j = 0; j < 4; j++) acc[i][j] = ffma2(aa, kb[j], acc[i][j]);
        }
      }
      #pragma unroll
      for (int i = 0; i < 8; i++){
        float f[8];
        #pragma unroll
        for (int j = 0; j < 4; j++) unpack2(acc[i][j], f[2*j], f[2*j+1]);
        float4 x0 = *(const float4*)&xs[(row+i)*DM + col];
        float4 x1 = *(const float4*)&xs[(row+i)*DM + col + 4];
        x0.x += f[0]; x0.y += f[1]; x0.z += f[2]; x0.w += f[3];
        x1.x += f[4]; x1.y += f[5]; x1.z += f[6]; x1.w += f[7];
        *(float4*)&xs[(row+i)*DM + col]     = x0;
        *(float4*)&xs[(row+i)*DM + col + 4] = x1;
      }
    }
    __syncthreads();
  }

  // ---------------- add bo, LN2 -> hs (tf32, stride 132); xs := x2 ----------------
  {
    float gv[4], bv[4], bov[4];
    #pragma unroll
    for (int c = 0; c < 4; c++){
      gv[c] = g2[c*32 + lane]; bv[c] = be2[c*32 + lane]; bov[c] = bo[c*32 + lane];
    }
    for (int r = w; r < TT; r += 8){
      float v[4], s = 0.f, s2 = 0.f;
      #pragma unroll
      for (int c = 0; c < 4; c++){
        v[c] = xs[r*DM + c*32 + lane] + bov[c];
        xs[r*DM + c*32 + lane] = v[c];
        s += v[c]; s2 += v[c]*v[c];
      }
      s = wredsum(s); s2 = wredsum(s2);
      float mu = s * (1.f/DM);
      float rs = rsqrtf(s2 * (1.f/DM) - mu*mu + EPSF);
      #pragma unroll
      for (int c = 0; c < 4; c++)
        hs[r*HSS + c*32 + lane] = tfbits((v[c] - mu) * rs * gv[c] + bv[c]);
    }
  }
  __syncthreads();

  // ---------------- FFN via warp mma tf32 ----------------
  {
    float dacc[16][4];
    #pragma unroll
    for (int nf = 0; nf < 16; nf++)
      #pragma unroll
      for (int j = 0; j < 4; j++) dacc[nf][j] = 0.f;

    for (int cb = 0; cb < 8; cb++){
      // stage w1t[n][k] = W1[k][cb*64+n], tf32, stride 132
      for (int idx = tid; idx < 8192; idx += 256){
        int n = idx & 63, k = idx >> 6;
        wt[n*HSS + k] = tfbits(W1[k*DF + cb*64 + n]);
      }
      __syncthreads();

      // U(128x64) = relu(hs @ w1chunk + b1); store tf32 to Ubuf stride 68
      {
        float uacc[8][4];
        #pragma unroll
        for (int nf = 0; nf < 8; nf++)
          #pragma unroll
          for (int j = 0; j < 4; j++) uacc[nf][j] = 0.f;

        for (int ks = 0; ks < 16; ks++){
          const float* ap = &hs[(row0 + qr)*HSS + ks*8 + qc];
          uint32_t a0 = __float_as_uint(ap[0]);
          uint32_t a1 = __float_as_uint(ap[8*HSS]);
          uint32_t a2 = __float_as_uint(ap[4]);
          uint32_t a3 = __float_as_uint(ap[8*HSS + 4]);
          #pragma unroll
          for (int nf = 0; nf < 8; nf++){
            const float* bp = &wt[(nf*8 + qr)*HSS + ks*8 + qc];
            uint32_t b0 = __float_as_uint(bp[0]);
            uint32_t b1r = __float_as_uint(bp[4]);
            mma8(uacc[nf], a0, a1, a2, a3, b0, b1r);
          }
        }
        __syncthreads();   // all reads of wt (w1t) done before restage
        #pragma unroll
        for (int nf = 0; nf < 8; nf++){
          int c0 = nf*8 + 2*qc;
          int r0 = row0 + qr;
          float2 bb = *(const float2*)&b1[cb*64 + c0];
          float u0 = fmaxf(uacc[nf][0] + bb.x, 0.f);
          float u1 = fmaxf(uacc[nf][1] + bb.y, 0.f);
          float u2 = fmaxf(uacc[nf][2] + bb.x, 0.f);
          float u3 = fmaxf(uacc[nf][3] + bb.y, 0.f);
          Ubuf[r0*68 + c0]       = tfbits(u0);
          Ubuf[r0*68 + c0 + 1]   = tfbits(u1);
          Ubuf[(r0+8)*68 + c0]   = tfbits(u2);
          Ubuf[(r0+8)*68 + c0+1] = tfbits(u3);
        }
      }

      // stage w2t[k][n] = W2[cb*64+k][n], tf32, stride 136
      for (int idx = tid; idx < 8192; idx += 256){
        int n = idx & 127, k = idx >> 7;
        wt[k*136 + n] = tfbits(W2[(cb*64 + k)*DM + n]);
      }
      __syncthreads();

      // D2(128x128) += U @ w2chunk (k=64)
      for (int ks = 0; ks < 8; ks++){
        const float* ap = &Ubuf[(row0 + qr)*68 + ks*8 + qc];
        uint32_t a0 = __float_as_uint(ap[0]);
        uint32_t a1 = __float_as_uint(ap[8*68]);
        uint32_t a2 = __float_as_uint(ap[4]);
        uint32_t a3 = __float_as_uint(ap[8*68 + 4]);
        #pragma unroll
        for (int nf = 0; nf < 16; nf++){
          const float* bp = &wt[(ks*8 + qc)*136 + nf*8 + qr];
          uint32_t b0 = __float_as_uint(bp[0]);
          uint32_t b1r = __float_as_uint(bp[4*136]);
          mma8(dacc[nf], a0, a1, a2, a3, b0, b1r);
        }
      }
      __syncthreads();   // wt/Ubuf reads done before next chunk restage
    }

    // epilogue: out = x2 + D2 + b2
    {
      int r0 = row0 + qr;
      #pragma unroll
      for (int nf = 0; nf < 16; nf++){
        int c0 = nf*8 + 2*qc;
        float2 bb = *(const float2*)&b2[c0];
        float2 o0, o1;
        o0.x = xs[r0*DM + c0]     + dacc[nf][0] + bb.x;
        o0.y = xs[r0*DM + c0 + 1] + dacc[nf][1] + bb.y;
        o1.x = xs[(r0+8)*DM + c0]     + dacc[nf][2] + bb.x;
        o1.y = xs[(r0+8)*DM + c0 + 1] + dacc[nf][3] + bb.y;
        *(float2*)&ob[r0*DM + c0]     = o0;
        *(float2*)&ob[(r0+8)*DM + c0] = o1;
      }
    }
  }
}

extern "C" void kernel_launch(void* const* d_in, const int* in_sizes, int n_in,
                              void* d_out, int out_size)
{
  (void)in_sizes; (void)n_in; (void)out_size;
  cudaFuncSetAttribute(decoder_block_kernel,
                       cudaFuncAttributeMaxDynamicSharedMemorySize,
                       SMEM_FLOATS * 4);
  decoder_block_kernel<<<NB, 256, SMEM_FLOATS * 4>>>(
      (const float*)d_in[0],  (const float*)d_in[1],  (const float*)d_in[2],
      (const float*)d_in[3],  (const float*)d_in[4],  (const float*)d_in[5],
      (const float*)d_in[6],  (const float*)d_in[7],  (const float*)d_in[8],
      (const float*)d_in[9],  (const float*)d_in[10], (const float*)d_in[11],
      (const float*)d_in[12], (const float*)d_in[13],
      (float*)d_out);
}

// round 8
// speedup vs baseline: 1.7641x; 1.2521x over previous
#include <cuda_runtime.h>
#include <cstdint>

// Fused transformer decoder block, one CTA per batch element, 512 threads.
// ALL GEMMs (QKV, S, O, Wo-fold, FFN1, FFN2) on mma.sync m16n8k8 tf32.
// B=512, T=128, D=128, H=6, Dh=21, D_FF=512.

#define NB 512
#define TT 128
#define DM 128
#define NH 6
#define DF 512
#define EPSF 1e-5f
#define SCALE 0.21821789023599236f   // 1/sqrt(21)
#define THREADS 512

__device__ __forceinline__ float wredsum(float v){
  #pragma unroll
  for (int o = 16; o > 0; o >>= 1) v += __shfl_xor_sync(0xffffffffu, v, o);
  return v;
}
__device__ __forceinline__ float wredmax(float v){
  #pragma unroll
  for (int o = 16; o > 0; o >>= 1) v = fmaxf(v, __shfl_xor_sync(0xffffffffu, v, o));
  return v;
}
__device__ __forceinline__ uint32_t f2tf(float f){
  uint32_t r; asm("cvt.rna.tf32.f32 %0, %1;" : "=r"(r) : "f"(f)); return r;
}
__device__ __forceinline__ float tfbits(float f){ return __uint_as_float(f2tf(f)); }

// D(16x8) += A(16x8,row) * B(8x8,col); tf32 in, fp32 accum.
__device__ __forceinline__ void mma8(float* d, uint32_t a0, uint32_t a1,
                                     uint32_t a2, uint32_t a3,
                                     uint32_t b0, uint32_t b1){
  asm volatile("mma.sync.aligned.m16n8k8.row.col.f32.tf32.tf32.f32 "
    "{%0,%1,%2,%3},{%4,%5,%6,%7},{%8,%9},{%0,%1,%2,%3};"
    : "+f"(d[0]), "+f"(d[1]), "+f"(d[2]), "+f"(d[3])
    : "r"(a0), "r"(a1), "r"(a2), "r"(a3), "r"(b0), "r"(b1));
}

// A-fragment load from a swizzled 128-stride buffer (swizzle = col ^ 4*(row&7)).
__device__ __forceinline__ void lda_sw(const float* buf, int r, int k0, int sw,
                                       uint32_t& a0, uint32_t& a1,
                                       uint32_t& a2, uint32_t& a3){
  a0 = __float_as_uint(buf[ r     *128 + ( k0      ^ sw)]);
  a1 = __float_as_uint(buf[(r+8)  *128 + ( k0      ^ sw)]);
  a2 = __float_as_uint(buf[ r     *128 + ((k0 + 4) ^ sw)]);
  a3 = __float_as_uint(buf[(r+8)  *128 + ((k0 + 4) ^ sw)]);
}

// smem layout (floats):
//  xs   [0     ,16384)  residual stream (stride 128, plain)
//  hs   [16384 ,32768)  ln output, stride 128 SWIZZLED
//  SCR  [32768 ,49152)  wqkvT[64][132] / Ssm 128x128 swizzled / wosT[128][28] /
//                        FFN: w1t[32][132]@0 | Ubuf[128][36]@4224 | w2tB[128][36]@8832
//  qsm  [49152 ,52224)  q 128x24 (pads zero); O overlays after S
//  ksm  [52224 ,54912)  k 128x21  ([n=t][k=e])
//  vts  [54912 ,57984)  v^T 24x128 swizzled (rows 21..23 zero)
#define SMEM_FLOATS 57984   // 231936 bytes

extern "C" __global__ void __launch_bounds__(THREADS, 1)
decoder_block_kernel(const float* __restrict__ gx,
                     const float* __restrict__ Wq,
                     const float* __restrict__ Wk,
                     const float* __restrict__ Wv,
                     const float* __restrict__ Wo,
                     const float* __restrict__ bo,
                     const float* __restrict__ W1,
                     const float* __restrict__ b1,
                     const float* __restrict__ W2,
                     const float* __restrict__ b2,
                     const float* __restrict__ g1,
                     const float* __restrict__ be1,
                     const float* __restrict__ g2,
                     const float* __restrict__ be2,
                     float* __restrict__ gout)
{
  extern __shared__ float sm[];
  float* xs    = sm;
  float* hs    = sm + 16384;
  float* SCR   = sm + 32768;
  float* qsm   = sm + 49152;     // 128 x 24
  float* ksm   = sm + 52224;     // 128 x 21
  float* vts   = sm + 54912;     // 24 x 128 swizzled

  float* wqkvT = SCR;            // [64][132]
  float* Ssm   = SCR;            // 128x128 swizzled
  float* wosT  = SCR;            // [128][28]
  float* w1t   = SCR;            // [32][132]
  float* Ubuf  = SCR + 4224;     // [128][36]
  float* w2tB  = SCR + 8832;     // [128][36]

  const int tid   = threadIdx.x;
  const int lane  = tid & 31;
  const int w     = tid >> 5;
  const int b     = blockIdx.x;
  const int qr    = lane >> 2;         // 0..7
  const int qc    = lane & 3;          // 0..3
  const int mrow  = (w & 7) * 16;      // row base
  const int nhalf = w >> 3;            // 0/1: N-half
  const int swq   = qr << 2;           // swizzle for rows r with r&7==qr

  const float* xb = gx   + (size_t)b * (TT * DM);
  float*       ob = gout + (size_t)b * (TT * DM);

  // ---------------- load x; zero pads ----------------
  {
    const float4* src = (const float4*)xb;
    float4* dst = (float4*)xs;
    #pragma unroll
    for (int i = 0; i < 8; i++) dst[tid + THREADS * i] = src[tid + THREADS * i];
    // q pads (cols 21..23) zero
    for (int idx = tid; idx < 384; idx += THREADS){
      int t = idx / 3, e = 21 + idx % 3;
      qsm[t*24 + e] = 0.f;
    }
    // v^T rows 21..23 zero
    for (int idx = tid; idx < 384; idx += THREADS)
      vts[(21 + idx/128)*128 + (idx & 127)] = 0.f;
  }
  __syncthreads();

  // ---------------- LN1 -> hs (tf32, swizzled stride 128) ----------------
  {
    float gv[4], bv[4];
    #pragma unroll
    for (int c = 0; c < 4; c++){ gv[c] = g1[c*32 + lane]; bv[c] = be1[c*32 + lane]; }
    for (int r = w; r < TT; r += 16){
      int sw = (r & 7) << 2;
      float v[4], s = 0.f, s2 = 0.f;
      #pragma unroll
      for (int c = 0; c < 4; c++){
        v[c] = xs[r*DM + c*32 + lane];
        s += v[c]; s2 += v[c]*v[c];
      }
      s = wredsum(s); s2 = wredsum(s2);
      float mu = s * (1.f/DM);
      float rs = rsqrtf(s2 * (1.f/DM) - mu*mu + EPSF);
      #pragma unroll
      for (int c = 0; c < 4; c++)
        hs[r*DM + ((c*32 + lane) ^ sw)] = tfbits((v[c] - mu) * rs * gv[c] + bv[c]);
    }
  }
  __syncthreads();

  // ---------------- attention, head by head ----------------
  for (int hh = 0; hh < NH; hh++){
    // stage wqkvT[n][k] (n: 0..20 Wq, 21..41 Wk, 42..62 Wv, 63 zero), tf32
    for (int idx = tid; idx < 8192; idx += THREADS){
      int n = idx & 63, k = idx >> 6;
      float v;
      if (n < 21)      v = Wq[hh*2688 + k*21 + n];
      else if (n < 42) v = Wk[hh*2688 + k*21 + (n-21)];
      else if (n < 63) v = Wv[hh*2688 + k*21 + (n-42)];
      else             v = 0.f;
      wqkvT[n*132 + k] = tfbits(v);
    }
    __syncthreads();

    // QKV: (128x64) = hs @ wqkv, each warp 16 rows x 32 cols
    {
      float qacc[4][4];
      #pragma unroll
      for (int f = 0; f < 4; f++)
        #pragma unroll
        for (int j = 0; j < 4; j++) qacc[f][j] = 0.f;

      for (int ks = 0; ks < 16; ks++){
        uint32_t a0,a1,a2,a3;
        lda_sw(hs, mrow + qr, ks*8 + qc, swq, a0,a1,a2,a3);
        #pragma unroll
        for (int f = 0; f < 4; f++){
          const float* bp = &wqkvT[(nhalf*32 + f*8 + qr)*132 + ks*8 + qc];
          mma8(qacc[f], a0,a1,a2,a3,
               __float_as_uint(bp[0]), __float_as_uint(bp[4]));
        }
      }
      // scatter C-frags -> q(scaled), k, v^T(swizzled), all tf32
      #pragma unroll
      for (int f = 0; f < 4; f++){
        #pragma unroll
        for (int part = 0; part < 4; part++){
          int cc = nhalf*32 + f*8 + 2*qc + (part & 1);
          int rr = mrow + qr + 8*(part >> 1);
          float vv = qacc[f][part];
          if (cc < 21)       qsm[rr*24 + cc] = tfbits(vv * SCALE);
          else if (cc < 42)  ksm[rr*21 + (cc-21)] = tfbits(vv);
          else if (cc < 63){
            int e = cc - 42;
            vts[e*128 + (rr ^ ((e & 7) << 2))] = tfbits(vv);
          }
        }
      }
    }
    __syncthreads();

    // S(128x128) = q @ k^T, K=24 (q pads zero); each warp 16 rows x 64 cols
    {
      float sacc[8][4];
      #pragma unroll
      for (int f = 0; f < 8; f++)
        #pragma unroll
        for (int j = 0; j < 4; j++) sacc[f][j] = 0.f;

      #pragma unroll
      for (int ks = 0; ks < 3; ks++){
        const float* ap = &qsm[(mrow + qr)*24 + ks*8 + qc];
        uint32_t a0 = __float_as_uint(ap[0]);
        uint32_t a1 = __float_as_uint(ap[8*24]);
        uint32_t a2 = __float_as_uint(ap[4]);
        uint32_t a3 = __float_as_uint(ap[8*24 + 4]);
        #pragma unroll
        for (int f = 0; f < 8; f++){
          const float* bp = &ksm[(nhalf*64 + f*8 + qr)*21 + ks*8 + qc];
          mma8(sacc[f], a0,a1,a2,a3,
               __float_as_uint(bp[0]), __float_as_uint(bp[4]));
        }
      }
      int r = mrow + qr;
      #pragma unroll
      for (int f = 0; f < 8; f++){
        int c0 = nhalf*64 + f*8 + 2*qc;
        *(float2*)&Ssm[ r    *128 + (c0 ^ swq)] = make_float2(sacc[f][0], sacc[f][1]);
        *(float2*)&Ssm[(r+8) *128 + (c0 ^ swq)] = make_float2(sacc[f][2], sacc[f][3]);
      }
    }
    __syncthreads();

    // masked softmax (warp per row), write tf32 P in place
    for (int r = w; r < TT; r += 16){
      int sw = (r & 7) << 2;
      float v[4];
      #pragma unroll
      for (int kb = 0; kb < 4; kb++){
        int c = kb*32 + lane;
        float s = Ssm[r*128 + (c ^ sw)];
        v[kb] = (c <= r) ? s : -1e30f;
      }
      float m = fmaxf(fmaxf(v[0], v[1]), fmaxf(v[2], v[3]));
      m = wredmax(m);
      float p[4], psum = 0.f;
      #pragma unroll
      for (int kb = 0; kb < 4; kb++){ p[kb] = __expf(v[kb] - m); psum += p[kb]; }
      psum = wredsum(psum);
      float inv = 1.f / psum;
      #pragma unroll
      for (int kb = 0; kb < 4; kb++){
        int c = kb*32 + lane;
        Ssm[r*128 + (c ^ sw)] = tfbits(p[kb] * inv);
      }
    }
    __syncthreads();

    // O(128x24) = P @ v, K=128; nhalf0 -> cols 0..15 (2 frags), nhalf1 -> 16..23 (1)
    {
      const int nfc = nhalf ? 1 : 2;
      float oacc[2][4];
      #pragma unroll
      for (int f = 0; f < 2; f++)
        #pragma unroll
        for (int j = 0; j < 4; j++) oacc[f][j] = 0.f;

      for (int ks = 0; ks < 16; ks++){
        uint32_t a0,a1,a2,a3;
        lda_sw(Ssm, mrow + qr, ks*8 + qc, swq, a0,a1,a2,a3);
        #pragma unroll
        for (int f = 0; f < 2; f++){
          if (f < nfc){
            int n = (nhalf*2 + f)*8 + qr;           // 0..23
            uint32_t b0 = __float_as_uint(vts[n*128 + ((ks*8 + qc)     ^ swq)]);
            uint32_t b1 = __float_as_uint(vts[n*128 + ((ks*8 + qc + 4) ^ swq)]);
            mma8(oacc[f], a0,a1,a2,a3, b0, b1);
          }
        }
      }
      __syncthreads();   // all P reads done before O overwrites q-slot? (distinct
                         // regions, but also gates wosT staging over Ssm below)
      #pragma unroll
      for (int f = 0; f < 2; f++){
        if (f < nfc){
          #pragma unroll
          for (int part = 0; part < 4; part++){
            int cc = (nhalf*2 + f)*8 + 2*qc + (part & 1);
            int rr = mrow + qr + 8*(part >> 1);
            qsm[rr*24 + cc] = tfbits(oacc[f][part]);   // O overlays q
          }
        }
      }
    }
    __syncthreads();

    // stage wosT[n][e] (e>=21 zero), stride 28
    for (int idx = tid; idx < 3072; idx += THREADS){
      int n = idx / 24, e = idx - (idx/24)*24;
      wosT[n*28 + e] = (e < 21) ? tfbits(Wo[(hh*21 + e)*DM + n]) : 0.f;
    }
    __syncthreads();

    // fold: xs += O @ Wo^T, K=24 (wosT rows 21..23 zero kill O garbage)
    {
      float facc[8][4];
      #pragma unroll
      for (int f = 0; f < 8; f++)
        #pragma unroll
        for (int j = 0; j < 4; j++) facc[f][j] = 0.f;

      #pragma unroll
      for (int ks = 0; ks < 3; ks++){
        const float* ap = &qsm[(mrow + qr)*24 + ks*8 + qc];
        uint32_t a0 = __float_as_uint(ap[0]);
        uint32_t a1 = __float_as_uint(ap[8*24]);
        uint32_t a2 = __float_as_uint(ap[4]);
        uint32_t a3 = __float_as_uint(ap[8*24 + 4]);
        #pragma unroll
        for (int f = 0; f < 8; f++){
          const float* bp = &wosT[(nhalf*64 + f*8 + qr)*28 + ks*8 + qc];
          mma8(facc[f], a0,a1,a2,a3,
               __float_as_uint(bp[0]), __float_as_uint(bp[4]));
        }
      }
      int rr = mrow + qr;
      #pragma unroll
      for (int f = 0; f < 8; f++){
        int cc = nhalf*64 + f*8 + 2*qc;
        xs[ rr   *DM + cc]     += facc[f][0];
        xs[ rr   *DM + cc + 1] += facc[f][1];
        xs[(rr+8)*DM + cc]     += facc[f][2];
        xs[(rr+8)*DM + cc + 1] += facc[f][3];
      }
    }
    __syncthreads();
  }

  // ---------------- add bo, LN2 -> hs (tf32, swizzled); xs := x2 ----------------
  {
    float gv[4], bv[4], bov[4];
    #pragma unroll
    for (int c = 0; c < 4; c++){
      gv[c] = g2[c*32 + lane]; bv[c] = be2[c*32 + lane]; bov[c] = bo[c*32 + lane];
    }
    for (int r = w; r < TT; r += 16){
      int sw = (r & 7) << 2;
      float v[4], s = 0.f, s2 = 0.f;
      #pragma unroll
      for (int c = 0; c < 4; c++){
        v[c] = xs[r*DM + c*32 + lane] + bov[c];
        xs[r*DM + c*32 + lane] = v[c];
        s += v[c]; s2 += v[c]*v[c];
      }
      s = wredsum(s); s2 = wredsum(s2);
      float mu = s * (1.f/DM);
      float rs = rsqrtf(s2 * (1.f/DM) - mu*mu + EPSF);
      #pragma unroll
      for (int c = 0; c < 4; c++)
        hs[r*DM + ((c*32 + lane) ^ sw)] = tfbits((v[c] - mu) * rs * gv[c] + bv[c]);
    }
  }
  __syncthreads();

  // ---------------- FFN: 16 chunks of 32 ----------------
  {
    float dacc[8][4];
    #pragma unroll
    for (int f = 0; f < 8; f++)
      #pragma unroll
      for (int j = 0; j < 4; j++) dacc[f][j] = 0.f;

    for (int cb = 0; cb < 16; cb++){
      // stage w1t[n][k] = W1[k][cb*32+n] and w2tB[n][kk] = W2[cb*32+kk][n]
      for (int idx = tid; idx < 4096; idx += THREADS){
        int n = idx & 31, k = idx >> 5;
        w1t[n*132 + k] = tfbits(W1[k*DF + cb*32 + n]);
      }
      for (int idx = tid; idx < 4096; idx += THREADS){
        int n = idx & 127, kk = idx >> 7;
        w2tB[n*36 + kk] = tfbits(W2[(cb*32 + kk)*DM + n]);
      }
      __syncthreads();

      // U(128x32) = relu(hs @ w1chunk + b1); each warp 16 rows x 16 cols
      {
        float uacc[2][4];
        #pragma unroll
        for (int f = 0; f < 2; f++)
          #pragma unroll
          for (int j = 0; j < 4; j++) uacc[f][j] = 0.f;

        for (int ks = 0; ks < 16; ks++){
          uint32_t a0,a1,a2,a3;
          lda_sw(hs, mrow + qr, ks*8 + qc, swq, a0,a1,a2,a3);
          #pragma unroll
          for (int f = 0; f < 2; f++){
            const float* bp = &w1t[(nhalf*16 + f*8 + qr)*132 + ks*8 + qc];
            mma8(uacc[f], a0,a1,a2,a3,
                 __float_as_uint(bp[0]), __float_as_uint(bp[4]));
          }
        }
        int rr = mrow + qr;
        #pragma unroll
        for (int f = 0; f < 2; f++){
          int c0 = nhalf*16 + f*8 + 2*qc;
          float2 bb = *(const float2*)&b1[cb*32 + c0];
          float2 u0 = make_float2(tfbits(fmaxf(uacc[f][0] + bb.x, 0.f)),
                                  tfbits(fmaxf(uacc[f][1] + bb.y, 0.f)));
          float2 u1 = make_float2(tfbits(fmaxf(uacc[f][2] + bb.x, 0.f)),
                                  tfbits(fmaxf(uacc[f][3] + bb.y, 0.f)));
          *(float2*)&Ubuf[ rr   *36 + c0] = u0;
          *(float2*)&Ubuf[(rr+8)*36 + c0] = u1;
        }
      }
      __syncthreads();

      // D2(128x128) += U @ w2chunk, K=32
      #pragma unroll
      for (int ks = 0; ks < 4; ks++){
        const float* ap = &Ubuf[(mrow + qr)*36 + ks*8 + qc];
        uint32_t a0 = __float_as_uint(ap[0]);
        uint32_t a1 = __float_as_uint(ap[8*36]);
        uint32_t a2 = __float_as_uint(ap[4]);
        uint32_t a3 = __float_as_uint(ap[8*36 + 4]);
        #pragma unroll
        for (int f = 0; f < 8; f++){
          const float* bp = &w2tB[(nhalf*64 + f*8 + qr)*36 + ks*8 + qc];
          mma8(dacc[f], a0,a1,a2,a3,
               __float_as_uint(bp[0]), __float_as_uint(bp[4]));
        }
      }
      __syncthreads();
    }

    // epilogue: out = x2 + D2 + b2
    int rr = mrow + qr;
    #pragma unroll
    for (int f = 0; f < 8; f++){
      int cc = nhalf*64 + f*8 + 2*qc;
      float2 bb = *(const float2*)&b2[cc];
      float2 o0 = make_float2(xs[ rr   *DM + cc]     + dacc[f][0] + bb.x,
                              xs[ rr   *DM + cc + 1] + dacc[f][1] + bb.y);
      float2 o1 = make_float2(xs[(rr+8)*DM + cc]     + dacc[f][2] + bb.x,
                              xs[(rr+8)*DM + cc + 1] + dacc[f][3] + bb.y);
      *(float2*)&ob[ rr   *DM + cc] = o0;
      *(float2*)&ob[(rr+8)*DM + cc] = o1;
    }
  }
}

extern "C" void kernel_launch(void* const* d_in, const int* in_sizes, int n_in,
                              void* d_out, int out_size)
{
  (void)in_sizes; (void)n_in; (void)out_size;
  cudaFuncSetAttribute(decoder_block_kernel,
                       cudaFuncAttributeMaxDynamicSharedMemorySize,
                       SMEM_FLOATS * 4);
  decoder_block_kernel<<<NB, THREADS, SMEM_FLOATS * 4>>>(
      (const float*)d_in[0],  (const float*)d_in[1],  (const float*)d_in[2],
      (const float*)d_in[3],  (const float*)d_in[4],  (const float*)d_in[5],
      (const float*)d_in[6],  (const float*)d_in[7],  (const float*)d_in[8],
      (const float*)d_in[9],  (const float*)d_in[10], (const float*)d_in[11],
      (const float*)d_in[12], (const float*)d_in[13],
      (float*)d_out);
}

// round 9
// speedup vs baseline: 1.9389x; 1.0990x over previous
#include <cuda_runtime.h>
#include <cstdint>

// Fused transformer decoder block, one CTA per batch element, 512 threads.
// ALL GEMMs on mma.sync m16n8k16 bf16 (fp32 accumulate), operands packed
// 2-bf16-per-u32 along K. Softmax/LN/residual in fp32.
// B=512, T=128, D=128, H=6, Dh=21, D_FF=512.

#define NB 512
#define TT 128
#define DM 128
#define NH 6
#define DF 512
#define EPSF 1e-5f
#define SCALE 0.21821789023599236f   // 1/sqrt(21)
#define THREADS 512

__device__ __forceinline__ float wredsum(float v){
  #pragma unroll
  for (int o = 16; o > 0; o >>= 1) v += __shfl_xor_sync(0xffffffffu, v, o);
  return v;
}
__device__ __forceinline__ float wredmax(float v){
  #pragma unroll
  for (int o = 16; o > 0; o >>= 1) v = fmaxf(v, __shfl_xor_sync(0xffffffffu, v, o));
  return v;
}
// pack two fp32 -> bf16x2 (lo -> low half, hi -> high half)
__device__ __forceinline__ uint32_t pkbf(float lo, float hi){
  uint32_t r; asm("cvt.rn.bf16x2.f32 %0, %1, %2;" : "=r"(r) : "f"(hi), "f"(lo));
  return r;
}
// D(16x8) += A(16x16,row) * B(16x8,col); bf16 in, fp32 accum.
__device__ __forceinline__ void mma16(float* d, uint32_t a0, uint32_t a1,
                                      uint32_t a2, uint32_t a3,
                                      uint32_t b0, uint32_t b1){
  asm volatile("mma.sync.aligned.m16n8k16.row.col.f32.bf16.bf16.f32 "
    "{%0,%1,%2,%3},{%4,%5,%6,%7},{%8,%9},{%0,%1,%2,%3};"
    : "+f"(d[0]), "+f"(d[1]), "+f"(d[2]), "+f"(d[3])
    : "r"(a0), "r"(a1), "r"(a2), "r"(a3), "r"(b0), "r"(b1));
}

// smem layout (u32 units):
//  XS   0      16384  residual stream fp32 (stride 128)
//  HS   16384  8704   ln output bf16x2 [128][68]
//  SCR  25088  16896  Ssm fp32[128][132] / wqkvT[80][68] / wosT[128][20] /
//                      FFN: w1t[32][68]@0 + w2t[128][20]@2176
//  P32  41984  8704   P bf16x2 [128][68] / vsm_f fp32[24][132] / Ubuf[128][20]
//  QS   50688  2560   q / O bf16x2 [128][20] (u32 cols 12..15 zero)
//  KS   53248  2560   k bf16x2 [128][20] (u32 cols 12..15 zero)
//  VT   55808  1632   v^T bf16x2 [24][68]
#define XSO  0
#define HSO  16384
#define SCRO 25088
#define P32O 41984
#define QSO  50688
#define KSO  53248
#define VTO  55808
#define SMEM_U32 57440   // 229760 bytes

extern "C" __global__ void __launch_bounds__(THREADS, 1)
decoder_block_kernel(const float* __restrict__ gx,
                     const float* __restrict__ Wq,
                     const float* __restrict__ Wk,
                     const float* __restrict__ Wv,
                     const float* __restrict__ Wo,
                     const float* __restrict__ bo,
                     const float* __restrict__ W1,
                     const float* __restrict__ b1,
                     const float* __restrict__ W2,
                     const float* __restrict__ b2,
                     const float* __restrict__ g1,
                     const float* __restrict__ be1,
                     const float* __restrict__ g2,
                     const float* __restrict__ be2,
                     float* __restrict__ gout)
{
  extern __shared__ float sm[];
  uint32_t* u  = (uint32_t*)sm;
  float*    xs = sm;                       // XSO

  const int tid   = threadIdx.x;
  const int lane  = tid & 31;
  const int w     = tid >> 5;
  const int b     = blockIdx.x;
  const int qr    = lane >> 2;             // 0..7
  const int qc    = lane & 3;              // 0..3
  const int mrow  = (w & 7) * 16;          // row base
  const int nhalf = w >> 3;                // 0/1

  const float* xb = gx   + (size_t)b * (TT * DM);
  float*       ob = gout + (size_t)b * (TT * DM);

  // ---------------- load x; zero q/k K-pads ----------------
  {
    const float4* src = (const float4*)xb;
    float4* dst = (float4*)xs;
    #pragma unroll
    for (int i = 0; i < 8; i++) dst[tid + THREADS * i] = src[tid + THREADS * i];
    for (int idx = tid; idx < 512; idx += THREADS){
      int r = idx >> 2, j = idx & 3;
      u[QSO + r*20 + 12 + j] = 0u;
      u[KSO + r*20 + 12 + j] = 0u;
    }
  }
  __syncthreads();

  // ---------------- LN1 -> HS (bf16x2) ----------------
  {
    float2 ga = *(const float2*)&g1[2*lane];
    float2 gb = *(const float2*)&g1[64 + 2*lane];
    float2 ea = *(const float2*)&be1[2*lane];
    float2 eb = *(const float2*)&be1[64 + 2*lane];
    for (int r = w; r < TT; r += 16){
      float2 xa = *(const float2*)&xs[r*DM + 2*lane];
      float2 xc = *(const float2*)&xs[r*DM + 64 + 2*lane];
      float s  = xa.x + xa.y + xc.x + xc.y;
      float s2 = xa.x*xa.x + xa.y*xa.y + xc.x*xc.x + xc.y*xc.y;
      s = wredsum(s); s2 = wredsum(s2);
      float mu = s * (1.f/DM);
      float rs = rsqrtf(s2 * (1.f/DM) - mu*mu + EPSF);
      float h0 = (xa.x - mu)*rs*ga.x + ea.x;
      float h1 = (xa.y - mu)*rs*ga.y + ea.y;
      float h2 = (xc.x - mu)*rs*gb.x + eb.x;
      float h3 = (xc.y - mu)*rs*gb.y + eb.y;
      u[HSO + r*68 + lane]      = pkbf(h0, h1);
      u[HSO + r*68 + 32 + lane] = pkbf(h2, h3);
    }
  }
  __syncthreads();

  // ---------------- attention, head by head ----------------
  for (int hh = 0; hh < NH; hh++){
    // stage wqkvT[n][k2]: n 0..20 Wq, 24..44 Wk, 48..68 Wv, else 0
    for (int idx = tid; idx < 5120; idx += THREADS){
      int k2 = idx & 63, n = idx >> 6;
      float lo = 0.f, hi = 0.f;
      const float* Wsrc = 0; int col = 0;
      if (n < 21)                 { Wsrc = Wq + hh*2688; col = n; }
      else if (n >= 24 && n < 45) { Wsrc = Wk + hh*2688; col = n - 24; }
      else if (n >= 48 && n < 69) { Wsrc = Wv + hh*2688; col = n - 48; }
      if (Wsrc){ lo = Wsrc[(2*k2)*21 + col]; hi = Wsrc[(2*k2 + 1)*21 + col]; }
      u[SCRO + n*68 + k2] = pkbf(lo, hi);
    }
    __syncthreads();

    // QKV: (128x80) = hs @ wqkv; warp: 16 rows x 40 cols (5 frags)
    {
      float qacc[5][4];
      #pragma unroll
      for (int f = 0; f < 5; f++)
        #pragma unroll
        for (int j = 0; j < 4; j++) qacc[f][j] = 0.f;

      #pragma unroll
      for (int ks = 0; ks < 8; ks++){
        int k8 = ks*8;
        uint32_t a0 = u[HSO + (mrow+qr)*68   + k8 + qc];
        uint32_t a1 = u[HSO + (mrow+qr+8)*68 + k8 + qc];
        uint32_t a2 = u[HSO + (mrow+qr)*68   + k8 + qc + 4];
        uint32_t a3 = u[HSO + (mrow+qr+8)*68 + k8 + qc + 4];
        #pragma unroll
        for (int f = 0; f < 5; f++){
          int n = nhalf*40 + f*8 + qr;
          mma16(qacc[f], a0,a1,a2,a3,
                u[SCRO + n*68 + k8 + qc], u[SCRO + n*68 + k8 + qc + 4]);
        }
      }
      // scatter: q (x SCALE) -> QS, k -> KS, v -> vsm_f (fp32, e-major)
      float* vf = (float*)&u[P32O];
      #pragma unroll
      for (int f = 0; f < 5; f++){
        int cc = nhalf*40 + f*8 + 2*qc;
        #pragma unroll
        for (int half = 0; half < 2; half++){
          int rr = mrow + qr + 8*half;
          float c0 = qacc[f][2*half], c1 = qacc[f][2*half + 1];
          if (cc < 24)       u[QSO + rr*20 + (cc>>1)] = pkbf(c0*SCALE, c1*SCALE);
          else if (cc < 48)  u[KSO + rr*20 + ((cc-24)>>1)] = pkbf(c0, c1);
          else if (cc < 72){
            vf[(cc-48)*132 + rr] = c0;
            vf[(cc-47)*132 + rr] = c1;
          }
        }
      }
    }
    __syncthreads();

    // pack v^T pairs along t; then S = q @ k^T (K=32, pads zero)
    {
      const float* vf = (const float*)&u[P32O];
      for (int idx = tid; idx < 1536; idx += THREADS){
        int e = idx >> 6, t2 = idx & 63;
        u[VTO + e*68 + t2] = pkbf(vf[e*132 + 2*t2], vf[e*132 + 2*t2 + 1]);
      }
      float sacc[8][4];
      #pragma unroll
      for (int f = 0; f < 8; f++)
        #pragma unroll
        for (int j = 0; j < 4; j++) sacc[f][j] = 0.f;

      #pragma unroll
      for (int ks = 0; ks < 2; ks++){
        int k8 = ks*8;
        uint32_t a0 = u[QSO + (mrow+qr)*20   + k8 + qc];
        uint32_t a1 = u[QSO + (mrow+qr+8)*20 + k8 + qc];
        uint32_t a2 = u[QSO + (mrow+qr)*20   + k8 + qc + 4];
        uint32_t a3 = u[QSO + (mrow+qr+8)*20 + k8 + qc + 4];
        #pragma unroll
        for (int f = 0; f < 8; f++){
          int n = nhalf*64 + f*8 + qr;
          mma16(sacc[f], a0,a1,a2,a3,
                u[KSO + n*20 + k8 + qc], u[KSO + n*20 + k8 + qc + 4]);
        }
      }
      float* Sf = (float*)&u[SCRO];
      int rr = mrow + qr;
      #pragma unroll
      for (int f = 0; f < 8; f++){
        int cc = nhalf*64 + f*8 + 2*qc;
        *(float2*)&Sf[ rr   *132 + cc] = make_float2(sacc[f][0], sacc[f][1]);
        *(float2*)&Sf[(rr+8)*132 + cc] = make_float2(sacc[f][2], sacc[f][3]);
      }
    }
    __syncthreads();

    // masked softmax (warp per row); write bf16x2 P
    {
      const float* Sf = (const float*)&u[SCRO];
      for (int r = w; r < TT; r += 16){
        float2 sa = *(const float2*)&Sf[r*132 + 2*lane];
        float2 sb = *(const float2*)&Sf[r*132 + 64 + 2*lane];
        int c0 = 2*lane;
        float v0 = (c0     <= r) ? sa.x : -1e30f;
        float v1 = (c0 + 1 <= r) ? sa.y : -1e30f;
        float v2 = (c0 + 64<= r) ? sb.x : -1e30f;
        float v3 = (c0 + 65<= r) ? sb.y : -1e30f;
        float m = wredmax(fmaxf(fmaxf(v0, v1), fmaxf(v2, v3)));
        float p0 = __expf(v0 - m), p1 = __expf(v1 - m);
        float p2 = __expf(v2 - m), p3 = __expf(v3 - m);
        float inv = 1.f / wredsum(p0 + p1 + p2 + p3);
        u[P32O + r*68 + lane]      = pkbf(p0*inv, p1*inv);
        u[P32O + r*68 + 32 + lane] = pkbf(p2*inv, p3*inv);
      }
    }
    __syncthreads();

    // O(128x24) = P @ v (K=128); stage wosT; O -> QS (overlays q)
    {
      const int nfc = nhalf ? 1 : 2;
      float oacc[2][4];
      #pragma unroll
      for (int f = 0; f < 2; f++)
        #pragma unroll
        for (int j = 0; j < 4; j++) oacc[f][j] = 0.f;

      #pragma unroll
      for (int ks = 0; ks < 8; ks++){
        int k8 = ks*8;
        uint32_t a0 = u[P32O + (mrow+qr)*68   + k8 + qc];
        uint32_t a1 = u[P32O + (mrow+qr+8)*68 + k8 + qc];
        uint32_t a2 = u[P32O + (mrow+qr)*68   + k8 + qc + 4];
        uint32_t a3 = u[P32O + (mrow+qr+8)*68 + k8 + qc + 4];
        #pragma unroll
        for (int f = 0; f < 2; f++){
          if (f < nfc){
            int n = (nhalf*2 + f)*8 + qr;
            mma16(oacc[f], a0,a1,a2,a3,
                  u[VTO + n*68 + k8 + qc], u[VTO + n*68 + k8 + qc + 4]);
          }
        }
      }
      // stage wosT[n][k2] (e pairs; e>=21 zero)
      for (int idx = tid; idx < 2048; idx += THREADS){
        int n = idx >> 4, k2 = idx & 15;
        int e0 = 2*k2;
        float lo = (e0     < 21) ? Wo[(hh*21 + e0    )*DM + n] : 0.f;
        float hi = (e0 + 1 < 21) ? Wo[(hh*21 + e0 + 1)*DM + n] : 0.f;
        u[SCRO + n*20 + k2] = pkbf(lo, hi);
      }
      #pragma unroll
      for (int f = 0; f < 2; f++){
        if (f < nfc){
          int cc = (nhalf*2 + f)*8 + 2*qc;
          u[QSO + (mrow+qr)*20   + (cc>>1)] = pkbf(oacc[f][0], oacc[f][1]);
          u[QSO + (mrow+qr+8)*20 + (cc>>1)] = pkbf(oacc[f][2], oacc[f][3]);
        }
      }
    }
    __syncthreads();

    // fold: xs += O @ Wo^T (K=32, pads zero)
    {
      float facc[8][4];
      #pragma unroll
      for (int f = 0; f < 8; f++)
        #pragma unroll
        for (int j = 0; j < 4; j++) facc[f][j] = 0.f;

      #pragma unroll
      for (int ks = 0; ks < 2; ks++){
        int k8 = ks*8;
        uint32_t a0 = u[QSO + (mrow+qr)*20   + k8 + qc];
        uint32_t a1 = u[QSO + (mrow+qr+8)*20 + k8 + qc];
        uint32_t a2 = u[QSO + (mrow+qr)*20   + k8 + qc + 4];
        uint32_t a3 = u[QSO + (mrow+qr+8)*20 + k8 + qc + 4];
        #pragma unroll
        for (int f = 0; f < 8; f++){
          int n = nhalf*64 + f*8 + qr;
          mma16(facc[f], a0,a1,a2,a3,
                u[SCRO + n*20 + k8 + qc], u[SCRO + n*20 + k8 + qc + 4]);
        }
      }
      int rr = mrow + qr;
      #pragma unroll
      for (int f = 0; f < 8; f++){
        int cc = nhalf*64 + f*8 + 2*qc;
        xs[ rr   *DM + cc]     += facc[f][0];
        xs[ rr   *DM + cc + 1] += facc[f][1];
        xs[(rr+8)*DM + cc]     += facc[f][2];
        xs[(rr+8)*DM + cc + 1] += facc[f][3];
      }
    }
    __syncthreads();
  }

  // ---------------- add bo, LN2 -> HS; xs := x2 ----------------
  {
    float2 ga = *(const float2*)&g2[2*lane];
    float2 gb = *(const float2*)&g2[64 + 2*lane];
    float2 ea = *(const float2*)&be2[2*lane];
    float2 eb = *(const float2*)&be2[64 + 2*lane];
    float2 ba = *(const float2*)&bo[2*lane];
    float2 bb = *(const float2*)&bo[64 + 2*lane];
    for (int r = w; r < TT; r += 16){
      float2 xa = *(const float2*)&xs[r*DM + 2*lane];
      float2 xc = *(const float2*)&xs[r*DM + 64 + 2*lane];
      xa.x += ba.x; xa.y += ba.y; xc.x += bb.x; xc.y += bb.y;
      *(float2*)&xs[r*DM + 2*lane]      = xa;
      *(float2*)&xs[r*DM + 64 + 2*lane] = xc;
      float s  = xa.x + xa.y + xc.x + xc.y;
      float s2 = xa.x*xa.x + xa.y*xa.y + xc.x*xc.x + xc.y*xc.y;
      s = wredsum(s); s2 = wredsum(s2);
      float mu = s * (1.f/DM);
      float rs = rsqrtf(s2 * (1.f/DM) - mu*mu + EPSF);
      u[HSO + r*68 + lane]      = pkbf((xa.x - mu)*rs*ga.x + ea.x,
                                       (xa.y - mu)*rs*ga.y + ea.y);
      u[HSO + r*68 + 32 + lane] = pkbf((xc.x - mu)*rs*gb.x + eb.x,
                                       (xc.y - mu)*rs*gb.y + eb.y);
    }
  }
  __syncthreads();

  // ---------------- FFN: 16 chunks of 32 ----------------
  {
    float dacc[8][4];
    #pragma unroll
    for (int f = 0; f < 8; f++)
      #pragma unroll
      for (int j = 0; j < 4; j++) dacc[f][j] = 0.f;

    for (int cb = 0; cb < 16; cb++){
      // stage w1t[n 0..31][k2 0..63] and w2t[n 0..127][k2 0..15]
      for (int idx = tid; idx < 2048; idx += THREADS){
        int n = idx >> 6, k2 = idx & 63;
        u[SCRO + n*68 + k2] = pkbf(W1[(2*k2)*DF + cb*32 + n],
                                   W1[(2*k2+1)*DF + cb*32 + n]);
      }
      for (int idx = tid; idx < 2048; idx += THREADS){
        int n = idx >> 4, k2 = idx & 15;
        u[SCRO + 2176 + n*20 + k2] = pkbf(W2[(cb*32 + 2*k2)*DM + n],
                                          W2[(cb*32 + 2*k2+1)*DM + n]);
      }
      __syncthreads();

      // U(128x32) = relu(hs @ w1chunk + b1) -> Ubuf bf16x2
      {
        float uacc[2][4];
        #pragma unroll
        for (int f = 0; f < 2; f++)
          #pragma unroll
          for (int j = 0; j < 4; j++) uacc[f][j] = 0.f;

        #pragma unroll
        for (int ks = 0; ks < 8; ks++){
          int k8 = ks*8;
          uint32_t a0 = u[HSO + (mrow+qr)*68   + k8 + qc];
          uint32_t a1 = u[HSO + (mrow+qr+8)*68 + k8 + qc];
          uint32_t a2 = u[HSO + (mrow+qr)*68   + k8 + qc + 4];
          uint32_t a3 = u[HSO + (mrow+qr+8)*68 + k8 + qc + 4];
          #pragma unroll
          for (int f = 0; f < 2; f++){
            int n = nhalf*16 + f*8 + qr;
            mma16(uacc[f], a0,a1,a2,a3,
                  u[SCRO + n*68 + k8 + qc], u[SCRO + n*68 + k8 + qc + 4]);
          }
        }
        #pragma unroll
        for (int f = 0; f < 2; f++){
          int cc = nhalf*16 + f*8 + 2*qc;
          float2 bb = *(const float2*)&b1[cb*32 + cc];
          u[P32O + (mrow+qr)*20   + (cc>>1)] =
              pkbf(fmaxf(uacc[f][0] + bb.x, 0.f), fmaxf(uacc[f][1] + bb.y, 0.f));
          u[P32O + (mrow+qr+8)*20 + (cc>>1)] =
              pkbf(fmaxf(uacc[f][2] + bb.x, 0.f), fmaxf(uacc[f][3] + bb.y, 0.f));
        }
      }
      __syncthreads();

      // D2 += U @ w2chunk (K=32)
      #pragma unroll
      for (int ks = 0; ks < 2; ks++){
        int k8 = ks*8;
        uint32_t a0 = u[P32O + (mrow+qr)*20   + k8 + qc];
        uint32_t a1 = u[P32O + (mrow+qr+8)*20 + k8 + qc];
        uint32_t a2 = u[P32O + (mrow+qr)*20   + k8 + qc + 4];
        uint32_t a3 = u[P32O + (mrow+qr+8)*20 + k8 + qc + 4];
        #pragma unroll
        for (int f = 0; f < 8; f++){
          int n = nhalf*64 + f*8 + qr;
          mma16(dacc[f], a0,a1,a2,a3,
                u[SCRO + 2176 + n*20 + k8 + qc],
                u[SCRO + 2176 + n*20 + k8 + qc + 4]);
        }
      }
      __syncthreads();
    }

    // epilogue: out = x2 + D2 + b2
    int rr = mrow + qr;
    #pragma unroll
    for (int f = 0; f < 8; f++){
      int cc = nhalf*64 + f*8 + 2*qc;
      float2 bb = *(const float2*)&b2[cc];
      float2 o0 = make_float2(xs[ rr   *DM + cc]     + dacc[f][0] + bb.x,
                              xs[ rr   *DM + cc + 1] + dacc[f][1] + bb.y);
      float2 o1 = make_float2(xs[(rr+8)*DM + cc]     + dacc[f][2] + bb.x,
                              xs[(rr+8)*DM + cc + 1] + dacc[f][3] + bb.y);
      *(float2*)&ob[ rr   *DM + cc] = o0;
      *(float2*)&ob[(rr+8)*DM + cc] = o1;
    }
  }
}

extern "C" void kernel_launch(void* const* d_in, const int* in_sizes, int n_in,
                              void* d_out, int out_size)
{
  (void)in_sizes; (void)n_in; (void)out_size;
  cudaFuncSetAttribute(decoder_block_kernel,
                       cudaFuncAttributeMaxDynamicSharedMemorySize,
                       SMEM_U32 * 4);
  decoder_block_kernel<<<NB, THREADS, SMEM_U32 * 4>>>(
      (const float*)d_in[0],  (const float*)d_in[1],  (const float*)d_in[2],
      (const float*)d_in[3],  (const float*)d_in[4],  (const float*)d_in[5],
      (const float*)d_in[6],  (const float*)d_in[7],  (const float*)d_in[8],
      (const float*)d_in[9],  (const float*)d_in[10], (const float*)d_in[11],
      (const float*)d_in[12], (const float*)d_in[13],
      (float*)d_out);
}

// round 10
// speedup vs baseline: 2.1086x; 1.0876x over previous
#include <cuda_runtime.h>
#include <cstdint>

// Fused transformer decoder block, one CTA per batch element, 512 threads.
// ALL GEMMs on mma.sync m16n8k16 bf16 (fp32 accum); fragments via ldmatrix.
// Softmax fully in registers (no S round-trip). LN/residual fp32.
// B=512, T=128, D=128, H=6, Dh=21, D_FF=512.

#define NB 512
#define TT 128
#define DM 128
#define NH 6
#define DF 512
#define EPSF 1e-5f
#define SCALE 0.21821789023599236f   // 1/sqrt(21)
#define THREADS 512

__device__ __forceinline__ float wredsum(float v){
  #pragma unroll
  for (int o = 16; o > 0; o >>= 1) v += __shfl_xor_sync(0xffffffffu, v, o);
  return v;
}
__device__ __forceinline__ uint32_t pkbf(float lo, float hi){
  uint32_t r; asm("cvt.rn.bf16x2.f32 %0, %1, %2;" : "=r"(r) : "f"(hi), "f"(lo));
  return r;
}
__device__ __forceinline__ void mma16(float* d, uint32_t a0, uint32_t a1,
                                      uint32_t a2, uint32_t a3,
                                      uint32_t b0, uint32_t b1){
  asm volatile("mma.sync.aligned.m16n8k16.row.col.f32.bf16.bf16.f32 "
    "{%0,%1,%2,%3},{%4,%5,%6,%7},{%8,%9},{%0,%1,%2,%3};"
    : "+f"(d[0]), "+f"(d[1]), "+f"(d[2]), "+f"(d[3])
    : "r"(a0), "r"(a1), "r"(a2), "r"(a3), "r"(b0), "r"(b1));
}
__device__ __forceinline__ void ldsm4(uint32_t addr, uint32_t& a0, uint32_t& a1,
                                      uint32_t& a2, uint32_t& a3){
  asm volatile("ldmatrix.sync.aligned.m8n8.x4.shared.b16 {%0,%1,%2,%3},[%4];"
    : "=r"(a0),"=r"(a1),"=r"(a2),"=r"(a3) : "r"(addr));
}
__device__ __forceinline__ void ldsm2(uint32_t addr, uint32_t& b0, uint32_t& b1){
  asm volatile("ldmatrix.sync.aligned.m8n8.x2.shared.b16 {%0,%1},[%2];"
    : "=r"(b0),"=r"(b1) : "r"(addr));
}
__device__ __forceinline__ uint32_t smem_u32_of(const void* p){
  uint32_t a;
  asm("{ .reg .u64 t; cvta.to.shared.u64 t, %1; cvt.u32.u64 %0, t; }" : "=r"(a) : "l"(p));
  return a;
}

// smem layout (u32 units):
//  XS   0      16384  residual fp32 (stride 128)
//  HS   16384  8704   ln output bf16x2 [128][68]
//  SCR  25088  16896  wqkvT[80][68] / wosT[128][20] / FFN w1t[32][68]+w2t[128][20]@2176
//  STAT 31232  512    softmax stats (inside SCR, above wqkvT)
//  P32  41984  8704   P bf16x2 [128][68] / vsm_f fp32[24][132] / Ubuf[128][20]
//  QS   50688  2560   q / O bf16x2 [128][20] (u32 cols 12..15 zero)
//  KS   53248  2560   k bf16x2 [128][20] (u32 cols 12..15 zero)
//  VT   55808  1632   v^T bf16x2 [24][68]
#define XSO   0
#define HSO   16384
#define SCRO  25088
#define STATO 31232
#define P32O  41984
#define QSO   50688
#define KSO   53248
#define VTO   55808
#define SMEM_U32 57440   // 229760 bytes

extern "C" __global__ void __launch_bounds__(THREADS, 1)
decoder_block_kernel(const float* __restrict__ gx,
                     const float* __restrict__ Wq,
                     const float* __restrict__ Wk,
                     const float* __restrict__ Wv,
                     const float* __restrict__ Wo,
                     const float* __restrict__ bo,
                     const float* __restrict__ W1,
                     const float* __restrict__ b1,
                     const float* __restrict__ W2,
                     const float* __restrict__ b2,
                     const float* __restrict__ g1,
                     const float* __restrict__ be1,
                     const float* __restrict__ g2,
                     const float* __restrict__ be2,
                     float* __restrict__ gout)
{
  extern __shared__ float sm[];
  uint32_t* u  = (uint32_t*)sm;
  float*    xs = sm;

  const int tid   = threadIdx.x;
  const int lane  = tid & 31;
  const int w     = tid >> 5;
  const int b     = blockIdx.x;
  const int qr    = lane >> 2;
  const int qc    = lane & 3;
  const int mrow  = (w & 7) * 16;
  const int nhalf = w >> 3;

  // ldmatrix per-lane geometry
  const int aRow  = (lane & 7) + 8*((lane >> 3) & 1);
  const int aCoff = 4*(lane >> 4);
  const int bRow  = lane & 7;
  const int bCoff = 4*((lane >> 3) & 1);

  const uint32_t sb = smem_u32_of(sm);

  const float* xb = gx   + (size_t)b * (TT * DM);
  float*       ob = gout + (size_t)b * (TT * DM);

  // ---------------- load x; zero q/k K-pads ----------------
  {
    const float4* src = (const float4*)xb;
    float4* dst = (float4*)xs;
    #pragma unroll
    for (int i = 0; i < 8; i++) dst[tid + THREADS * i] = src[tid + THREADS * i];
    for (int idx = tid; idx < 512; idx += THREADS){
      int r = idx >> 2, j = idx & 3;
      u[QSO + r*20 + 12 + j] = 0u;
      u[KSO + r*20 + 12 + j] = 0u;
    }
  }
  __syncthreads();

  // ---------------- LN1 -> HS (bf16x2) ----------------
  {
    float2 ga = *(const float2*)&g1[2*lane];
    float2 gb = *(const float2*)&g1[64 + 2*lane];
    float2 ea = *(const float2*)&be1[2*lane];
    float2 eb = *(const float2*)&be1[64 + 2*lane];
    for (int r = w; r < TT; r += 16){
      float2 xa = *(const float2*)&xs[r*DM + 2*lane];
      float2 xc = *(const float2*)&xs[r*DM + 64 + 2*lane];
      float s  = xa.x + xa.y + xc.x + xc.y;
      float s2 = xa.x*xa.x + xa.y*xa.y + xc.x*xc.x + xc.y*xc.y;
      s = wredsum(s); s2 = wredsum(s2);
      float mu = s * (1.f/DM);
      float rs = rsqrtf(s2 * (1.f/DM) - mu*mu + EPSF);
      u[HSO + r*68 + lane]      = pkbf((xa.x - mu)*rs*ga.x + ea.x,
                                       (xa.y - mu)*rs*ga.y + ea.y);
      u[HSO + r*68 + 32 + lane] = pkbf((xc.x - mu)*rs*gb.x + eb.x,
                                       (xc.y - mu)*rs*gb.y + eb.y);
    }
  }
  __syncthreads();

  float* st = (float*)&u[STATO];   // [0..127] max h0, [128..255] max h1,
                                   // [256..383] sum h0, [384..511] sum h1

  // ---------------- attention, head by head ----------------
  for (int hh = 0; hh < NH; hh++){
    // stage wqkvT[n][k2]: n 0..20 Wq, 24..44 Wk, 48..68 Wv, else 0
    for (int idx = tid; idx < 5120; idx += THREADS){
      int k2 = idx & 63, n = idx >> 6;
      float lo = 0.f, hi = 0.f;
      const float* Wsrc = 0; int col = 0;
      if (n < 21)                 { Wsrc = Wq + hh*2688; col = n; }
      else if (n >= 24 && n < 45) { Wsrc = Wk + hh*2688; col = n - 24; }
      else if (n >= 48 && n < 69) { Wsrc = Wv + hh*2688; col = n - 48; }
      if (Wsrc){ lo = Wsrc[(2*k2)*21 + col]; hi = Wsrc[(2*k2 + 1)*21 + col]; }
      u[SCRO + n*68 + k2] = pkbf(lo, hi);
    }
    __syncthreads();

    // QKV (128x80) = hs @ wqkv; warp: 16 rows x 40 cols
    {
      float qacc[5][4];
      #pragma unroll
      for (int f = 0; f < 5; f++)
        #pragma unroll
        for (int j = 0; j < 4; j++) qacc[f][j] = 0.f;

      uint32_t aB = sb + 4u*(HSO + (uint32_t)(mrow + aRow)*68 + aCoff);
      uint32_t bB = sb + 4u*(SCRO + (uint32_t)(nhalf*40 + bRow)*68 + bCoff);
      #pragma unroll
      for (int ks = 0; ks < 8; ks++){
        uint32_t a0,a1,a2,a3;
        ldsm4(aB + ks*32, a0,a1,a2,a3);
        #pragma unroll
        for (int f = 0; f < 5; f++){
          uint32_t b0,b1;
          ldsm2(bB + (uint32_t)f*(8*68*4) + ks*32, b0,b1);
          mma16(qacc[f], a0,a1,a2,a3, b0,b1);
        }
      }
      float* vf = (float*)&u[P32O];
      #pragma unroll
      for (int f = 0; f < 5; f++){
        int cc = nhalf*40 + f*8 + 2*qc;
        #pragma unroll
        for (int half = 0; half < 2; half++){
          int rr = mrow + qr + 8*half;
          float c0 = qacc[f][2*half], c1 = qacc[f][2*half + 1];
          if (cc < 24)       u[QSO + rr*20 + (cc>>1)] = pkbf(c0*SCALE, c1*SCALE);
          else if (cc < 48)  u[KSO + rr*20 + ((cc-24)>>1)] = pkbf(c0, c1);
          else if (cc < 72){
            vf[(cc-48)*132 + rr] = c0;
            vf[(cc-47)*132 + rr] = c1;
          }
        }
      }
    }
    __syncthreads();

    // pack v^T, S-GEMM, in-register softmax
    float sacc[8][4];
    {
      const float* vf = (const float*)&u[P32O];
      for (int idx = tid; idx < 1536; idx += THREADS){
        int e = idx >> 6, t2 = idx & 63;
        u[VTO + e*68 + t2] = pkbf(vf[e*132 + 2*t2], vf[e*132 + 2*t2 + 1]);
      }
      #pragma unroll
      for (int f = 0; f < 8; f++)
        #pragma unroll
        for (int j = 0; j < 4; j++) sacc[f][j] = 0.f;

      uint32_t aB = sb + 4u*(QSO + (uint32_t)(mrow + aRow)*20 + aCoff);
      uint32_t bB = sb + 4u*(KSO + (uint32_t)(nhalf*64 + bRow)*20 + bCoff);
      #pragma unroll
      for (int ks = 0; ks < 2; ks++){
        uint32_t a0,a1,a2,a3;
        ldsm4(aB + ks*32, a0,a1,a2,a3);
        #pragma unroll
        for (int f = 0; f < 8; f++){
          uint32_t b0,b1;
          ldsm2(bB + (uint32_t)f*(8*20*4) + ks*32, b0,b1);
          mma16(sacc[f], a0,a1,a2,a3, b0,b1);
        }
      }
    }
    // mask + row max (in registers)
    {
      int r0 = mrow + qr, r1 = r0 + 8;
      float mx0 = -1e30f, mx1 = -1e30f;
      #pragma unroll
      for (int f = 0; f < 8; f++){
        int c0 = nhalf*64 + f*8 + 2*qc;
        if (c0     > r0) sacc[f][0] = -1e30f;
        if (c0 + 1 > r0) sacc[f][1] = -1e30f;
        if (c0     > r1) sacc[f][2] = -1e30f;
        if (c0 + 1 > r1) sacc[f][3] = -1e30f;
        mx0 = fmaxf(mx0, fmaxf(sacc[f][0], sacc[f][1]));
        mx1 = fmaxf(mx1, fmaxf(sacc[f][2], sacc[f][3]));
      }
      mx0 = fmaxf(mx0, __shfl_xor_sync(0xffffffffu, mx0, 1));
      mx0 = fmaxf(mx0, __shfl_xor_sync(0xffffffffu, mx0, 2));
      mx1 = fmaxf(mx1, __shfl_xor_sync(0xffffffffu, mx1, 1));
      mx1 = fmaxf(mx1, __shfl_xor_sync(0xffffffffu, mx1, 2));
      if (qc == 0){ st[nhalf*128 + r0] = mx0; st[nhalf*128 + r1] = mx1; }
      __syncthreads();
      float M0 = fmaxf(st[r0], st[128 + r0]);
      float M1 = fmaxf(st[r1], st[128 + r1]);
      float s0 = 0.f, s1 = 0.f;
      #pragma unroll
      for (int f = 0; f < 8; f++){
        sacc[f][0] = __expf(sacc[f][0] - M0);
        sacc[f][1] = __expf(sacc[f][1] - M0);
        sacc[f][2] = __expf(sacc[f][2] - M1);
        sacc[f][3] = __expf(sacc[f][3] - M1);
        s0 += sacc[f][0] + sacc[f][1];
        s1 += sacc[f][2] + sacc[f][3];
      }
      s0 += __shfl_xor_sync(0xffffffffu, s0, 1);
      s0 += __shfl_xor_sync(0xffffffffu, s0, 2);
      s1 += __shfl_xor_sync(0xffffffffu, s1, 1);
      s1 += __shfl_xor_sync(0xffffffffu, s1, 2);
      if (qc == 0){ st[256 + nhalf*128 + r0] = s0; st[256 + nhalf*128 + r1] = s1; }
      __syncthreads();
      float inv0 = 1.f / (st[256 + r0] + st[384 + r0]);
      float inv1 = 1.f / (st[256 + r1] + st[384 + r1]);
      #pragma unroll
      for (int f = 0; f < 8; f++){
        int uc = nhalf*32 + f*4 + qc;
        u[P32O + r0*68 + uc] = pkbf(sacc[f][0]*inv0, sacc[f][1]*inv0);
        u[P32O + r1*68 + uc] = pkbf(sacc[f][2]*inv1, sacc[f][3]*inv1);
      }
    }
    __syncthreads();

    // O(128x24) = P @ v (K=128); stage wosT; O -> QS
    {
      const int nfc = nhalf ? 1 : 2;
      float oacc[2][4];
      #pragma unroll
      for (int f = 0; f < 2; f++)
        #pragma unroll
        for (int j = 0; j < 4; j++) oacc[f][j] = 0.f;

      uint32_t aB = sb + 4u*(P32O + (uint32_t)(mrow + aRow)*68 + aCoff);
      uint32_t bB = sb + 4u*(VTO + (uint32_t)(nhalf*16 + bRow)*68 + bCoff);
      #pragma unroll
      for (int ks = 0; ks < 8; ks++){
        uint32_t a0,a1,a2,a3;
        ldsm4(aB + ks*32, a0,a1,a2,a3);
        #pragma unroll
        for (int f = 0; f < 2; f++){
          if (f < nfc){
            uint32_t b0,b1;
            ldsm2(bB + (uint32_t)f*(8*68*4) + ks*32, b0,b1);
            mma16(oacc[f], a0,a1,a2,a3, b0,b1);
          }
        }
      }
      for (int idx = tid; idx < 2048; idx += THREADS){
        int n = idx >> 4, k2 = idx & 15;
        int e0 = 2*k2;
        float lo = (e0     < 21) ? Wo[(hh*21 + e0    )*DM + n] : 0.f;
        float hi = (e0 + 1 < 21) ? Wo[(hh*21 + e0 + 1)*DM + n] : 0.f;
        u[SCRO + n*20 + k2] = pkbf(lo, hi);
      }
      #pragma unroll
      for (int f = 0; f < 2; f++){
        if (f < nfc){
          int cc = (nhalf*2 + f)*8 + 2*qc;
          u[QSO + (mrow+qr)*20   + (cc>>1)] = pkbf(oacc[f][0], oacc[f][1]);
          u[QSO + (mrow+qr+8)*20 + (cc>>1)] = pkbf(oacc[f][2], oacc[f][3]);
        }
      }
    }
    __syncthreads();

    // fold: xs += O @ Wo^T (K=32)
    {
      float facc[8][4];
      #pragma unroll
      for (int f = 0; f < 8; f++)
        #pragma unroll
        for (int j = 0; j < 4; j++) facc[f][j] = 0.f;

      uint32_t aB = sb + 4u*(QSO + (uint32_t)(mrow + aRow)*20 + aCoff);
      uint32_t bB = sb + 4u*(SCRO + (uint32_t)(nhalf*64 + bRow)*20 + bCoff);
      #pragma unroll
      for (int ks = 0; ks < 2; ks++){
        uint32_t a0,a1,a2,a3;
        ldsm4(aB + ks*32, a0,a1,a2,a3);
        #pragma unroll
        for (int f = 0; f < 8; f++){
          uint32_t b0,b1;
          ldsm2(bB + (uint32_t)f*(8*20*4) + ks*32, b0,b1);
          mma16(facc[f], a0,a1,a2,a3, b0,b1);
        }
      }
      int rr = mrow + qr;
      #pragma unroll
      for (int f = 0; f < 8; f++){
        int cc = nhalf*64 + f*8 + 2*qc;
        xs[ rr   *DM + cc]     += facc[f][0];
        xs[ rr   *DM + cc + 1] += facc[f][1];
        xs[(rr+8)*DM + cc]     += facc[f][2];
        xs[(rr+8)*DM + cc + 1] += facc[f][3];
      }
    }
    __syncthreads();
  }

  // ---------------- add bo, LN2 -> HS; xs := x2 ----------------
  {
    float2 ga = *(const float2*)&g2[2*lane];
    float2 gb = *(const float2*)&g2[64 + 2*lane];
    float2 ea = *(const float2*)&be2[2*lane];
    float2 eb = *(const float2*)&be2[64 + 2*lane];
    float2 ba = *(const float2*)&bo[2*lane];
    float2 bb = *(const float2*)&bo[64 + 2*lane];
    for (int r = w; r < TT; r += 16){
      float2 xa = *(const float2*)&xs[r*DM + 2*lane];
      float2 xc = *(const float2*)&xs[r*DM + 64 + 2*lane];
      xa.x += ba.x; xa.y += ba.y; xc.x += bb.x; xc.y += bb.y;
      *(float2*)&xs[r*DM + 2*lane]      = xa;
      *(float2*)&xs[r*DM + 64 + 2*lane] = xc;
      float s  = xa.x + xa.y + xc.x + xc.y;
      float s2 = xa.x*xa.x + xa.y*xa.y + xc.x*xc.x + xc.y*xc.y;
      s = wredsum(s); s2 = wredsum(s2);
      float mu = s * (1.f/DM);
      float rs = rsqrtf(s2 * (1.f/DM) - mu*mu + EPSF);
      u[HSO + r*68 + lane]      = pkbf((xa.x - mu)*rs*ga.x + ea.x,
                                       (xa.y - mu)*rs*ga.y + ea.y);
      u[HSO + r*68 + 32 + lane] = pkbf((xc.x - mu)*rs*gb.x + eb.x,
                                       (xc.y - mu)*rs*gb.y + eb.y);
    }
  }
  __syncthreads();

  // ---------------- FFN: 16 chunks of 32 ----------------
  {
    float dacc[8][4];
    #pragma unroll
    for (int f = 0; f < 8; f++)
      #pragma unroll
      for (int j = 0; j < 4; j++) dacc[f][j] = 0.f;

    for (int cb = 0; cb < 16; cb++){
      for (int idx = tid; idx < 2048; idx += THREADS){
        int n = idx >> 6, k2 = idx & 63;
        u[SCRO + n*68 + k2] = pkbf(W1[(2*k2)*DF + cb*32 + n],
                                   W1[(2*k2+1)*DF + cb*32 + n]);
      }
      for (int idx = tid; idx < 2048; idx += THREADS){
        int n = idx >> 4, k2 = idx & 15;
        u[SCRO + 2176 + n*20 + k2] = pkbf(W2[(cb*32 + 2*k2)*DM + n],
                                          W2[(cb*32 + 2*k2+1)*DM + n]);
      }
      __syncthreads();

      // U(128x32) = relu(hs @ w1chunk + b1) -> Ubuf (P32 region, stride 20)
      {
        float uacc[2][4];
        #pragma unroll
        for (int f = 0; f < 2; f++)
          #pragma unroll
          for (int j = 0; j < 4; j++) uacc[f][j] = 0.f;

        uint32_t aB = sb + 4u*(HSO + (uint32_t)(mrow + aRow)*68 + aCoff);
        uint32_t bB = sb + 4u*(SCRO + (uint32_t)(nhalf*16 + bRow)*68 + bCoff);
        #pragma unroll
        for (int ks = 0; ks < 8; ks++){
          uint32_t a0,a1,a2,a3;
          ldsm4(aB + ks*32, a0,a1,a2,a3);
          #pragma unroll
          for (int f = 0; f < 2; f++){
            uint32_t b0,b1;
            ldsm2(bB + (uint32_t)f*(8*68*4) + ks*32, b0,b1);
            mma16(uacc[f], a0,a1,a2,a3, b0,b1);
          }
        }
        #pragma unroll
        for (int f = 0; f < 2; f++){
          int cc = nhalf*16 + f*8 + 2*qc;
          float2 bb = *(const float2*)&b1[cb*32 + cc];
          u[P32O + (mrow+qr)*20   + (cc>>1)] =
              pkbf(fmaxf(uacc[f][0] + bb.x, 0.f), fmaxf(uacc[f][1] + bb.y, 0.f));
          u[P32O + (mrow+qr+8)*20 + (cc>>1)] =
              pkbf(fmaxf(uacc[f][2] + bb.x, 0.f), fmaxf(uacc[f][3] + bb.y, 0.f));
        }
      }
      __syncthreads();

      // D2 += U @ w2chunk (K=32)
      {
        uint32_t aB = sb + 4u*(P32O + (uint32_t)(mrow + aRow)*20 + aCoff);
        uint32_t bB = sb + 4u*(SCRO + 2176 + (uint32_t)(nhalf*64 + bRow)*20 + bCoff);
        #pragma unroll
        for (int ks = 0; ks < 2; ks++){
          uint32_t a0,a1,a2,a3;
          ldsm4(aB + ks*32, a0,a1,a2,a3);
          #pragma unroll
          for (int f = 0; f < 8; f++){
            uint32_t b0,b1;
            ldsm2(bB + (uint32_t)f*(8*20*4) + ks*32, b0,b1);
            mma16(dacc[f], a0,a1,a2,a3, b0,b1);
          }
        }
      }
      __syncthreads();
    }

    // epilogue: out = x2 + D2 + b2
    int rr = mrow + qr;
    #pragma unroll
    for (int f = 0; f < 8; f++){
      int cc = nhalf*64 + f*8 + 2*qc;
      float2 bb = *(const float2*)&b2[cc];
      float2 o0 = make_float2(xs[ rr   *DM + cc]     + dacc[f][0] + bb.x,
                              xs[ rr   *DM + cc + 1] + dacc[f][1] + bb.y);
      float2 o1 = make_float2(xs[(rr+8)*DM + cc]     + dacc[f][2] + bb.x,
                              xs[(rr+8)*DM + cc + 1] + dacc[f][3] + bb.y);
      *(float2*)&ob[ rr   *DM + cc] = o0;
      *(float2*)&ob[(rr+8)*DM + cc] = o1;
    }
  }
}

extern "C" void kernel_launch(void* const* d_in, const int* in_sizes, int n_in,
                              void* d_out, int out_size)
{
  (void)in_sizes; (void)n_in; (void)out_size;
  cudaFuncSetAttribute(decoder_block_kernel,
                       cudaFuncAttributeMaxDynamicSharedMemorySize,
                       SMEM_U32 * 4);
  decoder_block_kernel<<<NB, THREADS, SMEM_U32 * 4>>>(
      (const float*)d_in[0],  (const float*)d_in[1],  (const float*)d_in[2],
      (const float*)d_in[3],  (const float*)d_in[4],  (const float*)d_in[5],
      (const float*)d_in[6],  (const float*)d_in[7],  (const float*)d_in[8],
      (const float*)d_in[9],  (const float*)d_in[10], (const float*)d_in[11],
      (const float*)d_in[12], (const float*)d_in[13],
      (float*)d_out);
}

// round 11
// speedup vs baseline: 2.1604x; 1.0245x over previous
#include <cuda_runtime.h>
#include <cstdint>

// Fused transformer decoder block, one CTA per batch element, 512 threads.
// All GEMMs mma.sync m16n8k16 bf16 (fp32 accum), ldmatrix fragments.
// Residual stream + attention-out + FFN accumulator live in registers
// (fragment layout). Single K=144 fold GEMM for all heads. Pairwise
// named barriers where possible. B=512, T=128, D=128, H=6, Dh=21, DF=512.

#define NB 512
#define TT 128
#define DM 128
#define NH 6
#define DF 512
#define EPSF 1e-5f
#define SCALE 0.21821789023599236f   // 1/sqrt(21)
#define THREADS 512

__device__ __forceinline__ uint32_t pkbf(float lo, float hi){
  uint32_t r; asm("cvt.rn.bf16x2.f32 %0, %1, %2;" : "=r"(r) : "f"(hi), "f"(lo));
  return r;
}
__device__ __forceinline__ void mma16(float* d, uint32_t a0, uint32_t a1,
                                      uint32_t a2, uint32_t a3,
                                      uint32_t b0, uint32_t b1){
  asm volatile("mma.sync.aligned.m16n8k16.row.col.f32.bf16.bf16.f32 "
    "{%0,%1,%2,%3},{%4,%5,%6,%7},{%8,%9},{%0,%1,%2,%3};"
    : "+f"(d[0]), "+f"(d[1]), "+f"(d[2]), "+f"(d[3])
    : "r"(a0), "r"(a1), "r"(a2), "r"(a3), "r"(b0), "r"(b1));
}
__device__ __forceinline__ void ldsm4(uint32_t addr, uint32_t& a0, uint32_t& a1,
                                      uint32_t& a2, uint32_t& a3){
  asm volatile("ldmatrix.sync.aligned.m8n8.x4.shared.b16 {%0,%1,%2,%3},[%4];"
    : "=r"(a0),"=r"(a1),"=r"(a2),"=r"(a3) : "r"(addr));
}
__device__ __forceinline__ void ldsm2(uint32_t addr, uint32_t& b0, uint32_t& b1){
  asm volatile("ldmatrix.sync.aligned.m8n8.x2.shared.b16 {%0,%1},[%2];"
    : "=r"(b0),"=r"(b1) : "r"(addr));
}
__device__ __forceinline__ uint32_t smem_u32_of(const void* p){
  uint32_t a;
  asm("{ .reg .u64 t; cvta.to.shared.u64 t, %1; cvt.u32.u64 %0, t; }" : "=r"(a) : "l"(p));
  return a;
}
#define PAIRBAR(id) asm volatile("bar.sync %0, 64;" :: "r"(id) : "memory")

// smem layout (u32 units):
//  HS    0      8704   ln output bf16x2 [128][68]
//  STAT  8704   512    softmax / LN2 stats
//  SCR   9216   17408  wqkvT db 2x[80][68] / WoT_all[128][76] / w1t[128][68]+w2t[128][68]
//  OALL  26624  9728   O_all bf16x2 [128][76]
//  P     36352  8704   P bf16x2 [128][68]; overlays: vf fp32 [21][132], Ubuf [128][68]
//  QS    45056  2560   q bf16x2 [128][20] (u32 cols 12..15 zero)
//  KS    47616  2560   k bf16x2 [128][20] (u32 cols 12..15 zero)
//  VT    50176  1632   v^T bf16x2 [24][68] (rows 21..23 zero)
#define HSO   0
#define STATO 8704
#define SCRO  9216
#define OALLO 26624
#define PO    36352
#define QSO   45056
#define KSO   47616
#define VTO   50176
#define SMEM_U32 51808   // 207232 bytes

extern "C" __global__ void __launch_bounds__(THREADS, 1)
decoder_block_kernel(const float* __restrict__ gx,
                     const float* __restrict__ Wq,
                     const float* __restrict__ Wk,
                     const float* __restrict__ Wv,
                     const float* __restrict__ Wo,
                     const float* __restrict__ bo,
                     const float* __restrict__ W1,
                     const float* __restrict__ b1,
                     const float* __restrict__ W2,
                     const float* __restrict__ b2,
                     const float* __restrict__ g1,
                     const float* __restrict__ be1,
                     const float* __restrict__ g2,
                     const float* __restrict__ be2,
                     float* __restrict__ gout)
{
  extern __shared__ float sm[];
  uint32_t* u = (uint32_t*)sm;

  const int tid   = threadIdx.x;
  const int lane  = tid & 31;
  const int w     = tid >> 5;
  const int b     = blockIdx.x;
  const int qr    = lane >> 2;
  const int qc    = lane & 3;
  const int mrow  = (w & 7) * 16;
  const int nhalf = w >> 3;
  const int pairid = 1 + (w & 7);

  const int aRow  = (lane & 7) + 8*((lane >> 3) & 1);
  const int aCoff = 4*(lane >> 4);
  const int bRow  = lane & 7;
  const int bCoff = 4*((lane >> 3) & 1);

  const uint32_t sb = smem_u32_of(sm);
  float* st = (float*)&u[STATO];

  const float* xb = gx   + (size_t)b * (TT * DM);
  float*       ob = gout + (size_t)b * (TT * DM);

  // ---------------- init: pads, wqkvT[0] stage, LN1 ----------------
  {
    for (int idx = tid; idx < 512; idx += THREADS){
      int r = idx >> 2, j = idx & 3;
      u[QSO + r*20 + 12 + j] = 0u;
      u[KSO + r*20 + 12 + j] = 0u;
    }
    for (int idx = tid; idx < 204; idx += THREADS)
      u[VTO + 21*68 + idx] = 0u;

    // stage wqkvT buffer 0 (head 0)
    for (int idx = tid; idx < 5120; idx += THREADS){
      int k2 = idx & 63, n = idx >> 6;
      float lo = 0.f, hi = 0.f;
      const float* Wsrc = 0; int col = 0;
      if (n < 21)                 { Wsrc = Wq; col = n; }
      else if (n >= 24 && n < 45) { Wsrc = Wk; col = n - 24; }
      else if (n >= 48 && n < 69) { Wsrc = Wv; col = n - 48; }
      if (Wsrc){ lo = Wsrc[(2*k2)*21 + col]; hi = Wsrc[(2*k2+1)*21 + col]; }
      u[SCRO + n*68 + k2] = pkbf(lo, hi);
    }

    // LN1 from global x -> HS
    float2 ga = *(const float2*)&g1[2*lane];
    float2 gb = *(const float2*)&g1[64 + 2*lane];
    float2 ea = *(const float2*)&be1[2*lane];
    float2 eb = *(const float2*)&be1[64 + 2*lane];
    for (int r = w; r < TT; r += 16){
      float2 xa = *(const float2*)&xb[r*DM + 2*lane];
      float2 xc = *(const float2*)&xb[r*DM + 64 + 2*lane];
      float s  = xa.x + xa.y + xc.x + xc.y;
      float s2 = xa.x*xa.x + xa.y*xa.y + xc.x*xc.x + xc.y*xc.y;
      #pragma unroll
      for (int o = 16; o > 0; o >>= 1){
        s  += __shfl_xor_sync(0xffffffffu, s, o);
        s2 += __shfl_xor_sync(0xffffffffu, s2, o);
      }
      float mu = s * (1.f/DM);
      float rs = rsqrtf(s2 * (1.f/DM) - mu*mu + EPSF);
      u[HSO + r*68 + lane]      = pkbf((xa.x - mu)*rs*ga.x + ea.x,
                                       (xa.y - mu)*rs*ga.y + ea.y);
      u[HSO + r*68 + 32 + lane] = pkbf((xc.x - mu)*rs*gb.x + eb.x,
                                       (xc.y - mu)*rs*gb.y + eb.y);
    }
  }
  __syncthreads();

  // ---------------- attention: 6 heads ----------------
  for (int hh = 0; hh < NH; hh++){
    const uint32_t wbuf = SCRO + (uint32_t)(hh & 1) * 5440u;

    // P1: QKV GEMM + scatter; stage next head's weights into other buffer
    {
      float qacc[5][4];
      #pragma unroll
      for (int f = 0; f < 5; f++)
        #pragma unroll
        for (int j = 0; j < 4; j++) qacc[f][j] = 0.f;

      uint32_t aB = sb + 4u*(HSO + (uint32_t)(mrow + aRow)*68 + aCoff);
      uint32_t bB = sb + 4u*(wbuf + (uint32_t)(nhalf*40 + bRow)*68 + bCoff);
      #pragma unroll
      for (int ks = 0; ks < 8; ks++){
        uint32_t a0,a1,a2,a3;
        ldsm4(aB + ks*32, a0,a1,a2,a3);
        #pragma unroll
        for (int f = 0; f < 5; f++){
          uint32_t b0,b1;
          ldsm2(bB + (uint32_t)f*(8*68*4) + ks*32, b0,b1);
          mma16(qacc[f], a0,a1,a2,a3, b0,b1);
        }
      }
      float* vf = (float*)&u[PO];
      #pragma unroll
      for (int f = 0; f < 5; f++){
        int cc = nhalf*40 + f*8 + 2*qc;
        #pragma unroll
        for (int half = 0; half < 2; half++){
          int rr = mrow + qr + 8*half;
          float c0 = qacc[f][2*half], c1 = qacc[f][2*half + 1];
          if (cc < 24)       u[QSO + rr*20 + (cc>>1)] = pkbf(c0*SCALE, c1*SCALE);
          else if (cc < 48)  u[KSO + rr*20 + ((cc-24)>>1)] = pkbf(c0, c1);
          else if (cc < 72){
            vf[(cc-48)*132 + rr] = c0;
            vf[(cc-47)*132 + rr] = c1;
          }
        }
      }
      if (hh < 5){
        const uint32_t nbuf = SCRO + (uint32_t)((hh + 1) & 1) * 5440u;
        const float* Wq2 = Wq + (hh+1)*2688;
        const float* Wk2 = Wk + (hh+1)*2688;
        const float* Wv2 = Wv + (hh+1)*2688;
        for (int idx = tid; idx < 5120; idx += THREADS){
          int k2 = idx & 63, n = idx >> 6;
          float lo = 0.f, hi = 0.f;
          const float* Wsrc = 0; int col = 0;
          if (n < 21)                 { Wsrc = Wq2; col = n; }
          else if (n >= 24 && n < 45) { Wsrc = Wk2; col = n - 24; }
          else if (n >= 48 && n < 69) { Wsrc = Wv2; col = n - 48; }
          if (Wsrc){ lo = Wsrc[(2*k2)*21 + col]; hi = Wsrc[(2*k2+1)*21 + col]; }
          u[nbuf + n*68 + k2] = pkbf(lo, hi);
        }
      }
    }
    __syncthreads();

    // P2a: VT pack + S GEMM + mask + local max/exp/sum + stats
    float sacc[8][4];
    float mx0, mx1;
    {
      const float* vf = (const float*)&u[PO];
      for (int idx = tid; idx < 1344; idx += THREADS){
        int e = idx >> 6, t2 = idx & 63;
        u[VTO + e*68 + t2] = pkbf(vf[e*132 + 2*t2], vf[e*132 + 2*t2 + 1]);
      }
      #pragma unroll
      for (int f = 0; f < 8; f++)
        #pragma unroll
        for (int j = 0; j < 4; j++) sacc[f][j] = 0.f;

      uint32_t aB = sb + 4u*(QSO + (uint32_t)(mrow + aRow)*20 + aCoff);
      uint32_t bB = sb + 4u*(KSO + (uint32_t)(nhalf*64 + bRow)*20 + bCoff);
      #pragma unroll
      for (int ks = 0; ks < 2; ks++){
        uint32_t a0,a1,a2,a3;
        ldsm4(aB + ks*32, a0,a1,a2,a3);
        #pragma unroll
        for (int f = 0; f < 8; f++){
          uint32_t b0,b1;
          ldsm2(bB + (uint32_t)f*(8*20*4) + ks*32, b0,b1);
          mma16(sacc[f], a0,a1,a2,a3, b0,b1);
        }
      }
      int r0 = mrow + qr, r1 = r0 + 8;
      mx0 = -1e30f; mx1 = -1e30f;
      #pragma unroll
      for (int f = 0; f < 8; f++){
        int c0 = nhalf*64 + f*8 + 2*qc;
        if (c0     > r0) sacc[f][0] = -1e30f;
        if (c0 + 1 > r0) sacc[f][1] = -1e30f;
        if (c0     > r1) sacc[f][2] = -1e30f;
        if (c0 + 1 > r1) sacc[f][3] = -1e30f;
        mx0 = fmaxf(mx0, fmaxf(sacc[f][0], sacc[f][1]));
        mx1 = fmaxf(mx1, fmaxf(sacc[f][2], sacc[f][3]));
      }
      mx0 = fmaxf(mx0, __shfl_xor_sync(0xffffffffu, mx0, 1));
      mx0 = fmaxf(mx0, __shfl_xor_sync(0xffffffffu, mx0, 2));
      mx1 = fmaxf(mx1, __shfl_xor_sync(0xffffffffu, mx1, 1));
      mx1 = fmaxf(mx1, __shfl_xor_sync(0xffffffffu, mx1, 2));
      float s0 = 0.f, s1 = 0.f;
      #pragma unroll
      for (int f = 0; f < 8; f++){
        sacc[f][0] = __expf(sacc[f][0] - mx0);
        sacc[f][1] = __expf(sacc[f][1] - mx0);
        sacc[f][2] = __expf(sacc[f][2] - mx1);
        sacc[f][3] = __expf(sacc[f][3] - mx1);
        s0 += sacc[f][0] + sacc[f][1];
        s1 += sacc[f][2] + sacc[f][3];
      }
      s0 += __shfl_xor_sync(0xffffffffu, s0, 1);
      s0 += __shfl_xor_sync(0xffffffffu, s0, 2);
      s1 += __shfl_xor_sync(0xffffffffu, s1, 1);
      s1 += __shfl_xor_sync(0xffffffffu, s1, 2);
      if (qc == 0){
        st[nhalf*128 + r0] = mx0;       st[nhalf*128 + r1] = mx1;
        st[256 + nhalf*128 + r0] = s0;  st[256 + nhalf*128 + r1] = s1;
      }
    }
    __syncthreads();

    // P2b: combine stats, write normalized P (bf16x2)
    {
      int r0 = mrow + qr, r1 = r0 + 8;
      float M0 = fmaxf(st[r0], st[128 + r0]);
      float M1 = fmaxf(st[r1], st[128 + r1]);
      float d0 = st[256 + r0]*__expf(st[r0] - M0) + st[384 + r0]*__expf(st[128 + r0] - M0);
      float d1 = st[256 + r1]*__expf(st[r1] - M1) + st[384 + r1]*__expf(st[128 + r1] - M1);
      float sc0 = __expf(mx0 - M0) / d0;
      float sc1 = __expf(mx1 - M1) / d1;
      #pragma unroll
      for (int f = 0; f < 8; f++){
        int uc = nhalf*32 + f*4 + qc;
        u[PO + r0*68 + uc] = pkbf(sacc[f][0]*sc0, sacc[f][1]*sc0);
        u[PO + r1*68 + uc] = pkbf(sacc[f][2]*sc1, sacc[f][3]*sc1);
      }
    }
    PAIRBAR(pairid);

    // P3: O GEMM -> O_all slab
    {
      const int nfc = nhalf ? 1 : 2;
      float oacc[2][4];
      #pragma unroll
      for (int f = 0; f < 2; f++)
        #pragma unroll
        for (int j = 0; j < 4; j++) oacc[f][j] = 0.f;

      uint32_t aB = sb + 4u*(PO + (uint32_t)(mrow + aRow)*68 + aCoff);
      uint32_t bB = sb + 4u*(VTO + (uint32_t)(nhalf*16 + bRow)*68 + bCoff);
      #pragma unroll
      for (int ks = 0; ks < 8; ks++){
        uint32_t a0,a1,a2,a3;
        ldsm4(aB + ks*32, a0,a1,a2,a3);
        #pragma unroll
        for (int f = 0; f < 2; f++){
          if (f < nfc){
            uint32_t b0,b1;
            ldsm2(bB + (uint32_t)f*(8*68*4) + ks*32, b0,b1);
            mma16(oacc[f], a0,a1,a2,a3, b0,b1);
          }
        }
      }
      #pragma unroll
      for (int f = 0; f < 2; f++){
        if (f < nfc){
          int uc = hh*12 + (nhalf*2 + f)*4 + qc;
          u[OALLO + (mrow+qr)*76   + uc] = pkbf(oacc[f][0], oacc[f][1]);
          u[OALLO + (mrow+qr+8)*76 + uc] = pkbf(oacc[f][2], oacc[f][3]);
        }
      }
    }
    __syncthreads();
  }

  // ---------------- stage WoT_all [128][76] ----------------
  for (int idx = tid; idx < 9216; idx += THREADS){
    int n = idx / 72, k2 = idx - n*72;
    int head = k2 / 12, within = k2 - head*12;
    int e0 = 2*within;
    float lo = (e0     < 21) ? Wo[(head*21 + e0    )*DM + n] : 0.f;
    float hi = (e0 + 1 < 21) ? Wo[(head*21 + e0 + 1)*DM + n] : 0.f;
    u[SCRO + n*76 + k2] = pkbf(lo, hi);
  }
  __syncthreads();

  // ---------------- fold (K=144) -> x2 regs; LN2 partial stats ----------------
  float x2r[8][4];
  {
    #pragma unroll
    for (int f = 0; f < 8; f++)
      #pragma unroll
      for (int j = 0; j < 4; j++) x2r[f][j] = 0.f;

    uint32_t aB = sb + 4u*(OALLO + (uint32_t)(mrow + aRow)*76 + aCoff);
    uint32_t bB = sb + 4u*(SCRO + (uint32_t)(nhalf*64 + bRow)*76 + bCoff);
    #pragma unroll
    for (int ks = 0; ks < 9; ks++){
      uint32_t a0,a1,a2,a3;
      ldsm4(aB + ks*32, a0,a1,a2,a3);
      #pragma unroll
      for (int f = 0; f < 8; f++){
        uint32_t b0,b1;
        ldsm2(bB + (uint32_t)f*(8*76*4) + ks*32, b0,b1);
        mma16(x2r[f], a0,a1,a2,a3, b0,b1);
      }
    }
    // x2 = x + attn + bo  (fragment pattern), LN2 partial stats
    int r0 = mrow + qr, r1 = r0 + 8;
    float s0 = 0.f, q0 = 0.f, s1 = 0.f, q1 = 0.f;
    #pragma unroll
    for (int f = 0; f < 8; f++){
      int cc = nhalf*64 + f*8 + 2*qc;
      float2 bv = *(const float2*)&bo[cc];
      float2 xa = *(const float2*)&xb[r0*DM + cc];
      float2 xc = *(const float2*)&xb[r1*DM + cc];
      x2r[f][0] += xa.x + bv.x;  x2r[f][1] += xa.y + bv.y;
      x2r[f][2] += xc.x + bv.x;  x2r[f][3] += xc.y + bv.y;
      s0 += x2r[f][0] + x2r[f][1];
      q0 += x2r[f][0]*x2r[f][0] + x2r[f][1]*x2r[f][1];
      s1 += x2r[f][2] + x2r[f][3];
      q1 += x2r[f][2]*x2r[f][2] + x2r[f][3]*x2r[f][3];
    }
    s0 += __shfl_xor_sync(0xffffffffu, s0, 1); s0 += __shfl_xor_sync(0xffffffffu, s0, 2);
    q0 += __shfl_xor_sync(0xffffffffu, q0, 1); q0 += __shfl_xor_sync(0xffffffffu, q0, 2);
    s1 += __shfl_xor_sync(0xffffffffu, s1, 1); s1 += __shfl_xor_sync(0xffffffffu, s1, 2);
    q1 += __shfl_xor_sync(0xffffffffu, q1, 1); q1 += __shfl_xor_sync(0xffffffffu, q1, 2);
    if (qc == 0){
      st[nhalf*128 + r0] = s0;        st[nhalf*128 + r1] = s1;
      st[256 + nhalf*128 + r0] = q0;  st[256 + nhalf*128 + r1] = q1;
    }
  }
  __syncthreads();

  // ---------------- LN2 finalize -> HS ; stage FFN chunk 0 ----------------
  {
    int r0 = mrow + qr, r1 = r0 + 8;
    float S0 = st[r0] + st[128 + r0], Q0 = st[256 + r0] + st[384 + r0];
    float S1 = st[r1] + st[128 + r1], Q1 = st[256 + r1] + st[384 + r1];
    float mu0 = S0 * (1.f/DM), rs0 = rsqrtf(Q0*(1.f/DM) - mu0*mu0 + EPSF);
    float mu1 = S1 * (1.f/DM), rs1 = rsqrtf(Q1*(1.f/DM) - mu1*mu1 + EPSF);
    #pragma unroll
    for (int f = 0; f < 8; f++){
      int cc = nhalf*64 + f*8 + 2*qc;
      float2 gv = *(const float2*)&g2[cc];
      float2 ev = *(const float2*)&be2[cc];
      u[HSO + r0*68 + (cc>>1)] = pkbf((x2r[f][0]-mu0)*rs0*gv.x + ev.x,
                                      (x2r[f][1]-mu0)*rs0*gv.y + ev.y);
      u[HSO + r1*68 + (cc>>1)] = pkbf((x2r[f][2]-mu1)*rs1*gv.x + ev.x,
                                      (x2r[f][3]-mu1)*rs1*gv.y + ev.y);
    }
    // stage w1t/w2t for chunk 0
    for (int idx = tid; idx < 8192; idx += THREADS){
      int n = idx >> 6, k2 = idx & 63;
      u[SCRO + n*68 + k2] = pkbf(W1[(2*k2)*DF + n], W1[(2*k2+1)*DF + n]);
    }
    for (int idx = tid; idx < 8192; idx += THREADS){
      int n = idx >> 6, k2 = idx & 63;
      u[SCRO + 8704 + n*68 + k2] = pkbf(W2[(2*k2)*DM + n], W2[(2*k2+1)*DM + n]);
    }
  }
  __syncthreads();

  // ---------------- FFN: 4 chunks of 128 ----------------
  float dacc[8][4];
  #pragma unroll
  for (int f = 0; f < 8; f++)
    #pragma unroll
    for (int j = 0; j < 4; j++) dacc[f][j] = 0.f;

  for (int cb = 0; cb < 4; cb++){
    // U(128x128) = relu(hs @ w1chunk + b1) -> Ubuf (P region)
    {
      float uacc[8][4];
      #pragma unroll
      for (int f = 0; f < 8; f++)
        #pragma unroll
        for (int j = 0; j < 4; j++) uacc[f][j] = 0.f;

      uint32_t aB = sb + 4u*(HSO + (uint32_t)(mrow + aRow)*68 + aCoff);
      uint32_t bB = sb + 4u*(SCRO + (uint32_t)(nhalf*64 + bRow)*68 + bCoff);
      #pragma unroll
      for (int ks = 0; ks < 8; ks++){
        uint32_t a0,a1,a2,a3;
        ldsm4(aB + ks*32, a0,a1,a2,a3);
        #pragma unroll
        for (int f = 0; f < 8; f++){
          uint32_t b0,b1;
          ldsm2(bB + (uint32_t)f*(8*68*4) + ks*32, b0,b1);
          mma16(uacc[f], a0,a1,a2,a3, b0,b1);
        }
      }
      int r0 = mrow + qr, r1 = r0 + 8;
      #pragma unroll
      for (int f = 0; f < 8; f++){
        int cc = nhalf*64 + f*8 + 2*qc;
        float2 bv = *(const float2*)&b1[cb*128 + cc];
        u[PO + r0*68 + (cc>>1)] = pkbf(fmaxf(uacc[f][0] + bv.x, 0.f),
                                       fmaxf(uacc[f][1] + bv.y, 0.f));
        u[PO + r1*68 + (cc>>1)] = pkbf(fmaxf(uacc[f][2] + bv.x, 0.f),
                                       fmaxf(uacc[f][3] + bv.y, 0.f));
      }
    }
    PAIRBAR(pairid);

    // D2 += U @ w2chunk (K=128)
    {
      uint32_t aB = sb + 4u*(PO + (uint32_t)(mrow + aRow)*68 + aCoff);
      uint32_t bB = sb + 4u*(SCRO + 8704 + (uint32_t)(nhalf*64 + bRow)*68 + bCoff);
      #pragma unroll
      for (int ks = 0; ks < 8; ks++){
        uint32_t a0,a1,a2,a3;
        ldsm4(aB + ks*32, a0,a1,a2,a3);
        #pragma unroll
        for (int f = 0; f < 8; f++){
          uint32_t b0,b1;
          ldsm2(bB + (uint32_t)f*(8*68*4) + ks*32, b0,b1);
          mma16(dacc[f], a0,a1,a2,a3, b0,b1);
        }
      }
    }
    __syncthreads();

    // stage next chunk's weights
    if (cb < 3){
      for (int idx = tid; idx < 8192; idx += THREADS){
        int n = idx >> 6, k2 = idx & 63;
        u[SCRO + n*68 + k2] = pkbf(W1[(2*k2)*DF + (cb+1)*128 + n],
                                   W1[(2*k2+1)*DF + (cb+1)*128 + n]);
      }
      for (int idx = tid; idx < 8192; idx += THREADS){
        int n = idx >> 6, k2 = idx & 63;
        u[SCRO + 8704 + n*68 + k2] = pkbf(W2[((cb+1)*128 + 2*k2)*DM + n],
                                          W2[((cb+1)*128 + 2*k2+1)*DM + n]);
      }
      __syncthreads();
    }
  }

  // ---------------- epilogue: out = x2 + D2 + b2 ----------------
  {
    int r0 = mrow + qr, r1 = r0 + 8;
    #pragma unroll
    for (int f = 0; f < 8; f++){
      int cc = nhalf*64 + f*8 + 2*qc;
      float2 bv = *(const float2*)&b2[cc];
      float2 o0 = make_float2(x2r[f][0] + dacc[f][0] + bv.x,
                              x2r[f][1] + dacc[f][1] + bv.y);
      float2 o1 = make_float2(x2r[f][2] + dacc[f][2] + bv.x,
                              x2r[f][3] + dacc[f][3] + bv.y);
      *(float2*)&ob[r0*DM + cc] = o0;
      *(float2*)&ob[r1*DM + cc] = o1;
    }
  }
}

extern "C" void kernel_launch(void* const* d_in, const int* in_sizes, int n_in,
                              void* d_out, int out_size)
{
  (void)in_sizes; (void)n_in; (void)out_size;
  cudaFuncSetAttribute(decoder_block_kernel,
                       cudaFuncAttributeMaxDynamicSharedMemorySize,
                       SMEM_U32 * 4);
  decoder_block_kernel<<<NB, THREADS, SMEM_U32 * 4>>>(
      (const float*)d_in[0],  (const float*)d_in[1],  (const float*)d_in[2],
      (const float*)d_in[3],  (const float*)d_in[4],  (const float*)d_in[5],
      (const float*)d_in[6],  (const float*)d_in[7],  (const float*)d_in[8],
      (const float*)d_in[9],  (const float*)d_in[10], (const float*)d_in[11],
      (const float*)d_in[12], (const float*)d_in[13],
      (float*)d_out);
}

// round 12
// speedup vs baseline: 3.5217x; 1.6302x over previous
#include <cuda_runtime.h>
#include <cstdint>

// Fused transformer decoder block, one CTA per batch element, 512 threads.
// All GEMMs mma.sync m16n8k16 bf16 (fp32 accum), ldmatrix fragments
// (B operands via paired x4). All weight staging coalesced (transpose on
// the STS side). Residual/attn-out/FFN accumulators in registers.
// B=512, T=128, D=128, H=6, Dh=21, DF=512.

#define NB 512
#define TT 128
#define DM 128
#define NH 6
#define DF 512
#define EPSF 1e-5f
#define SCALE 0.21821789023599236f   // 1/sqrt(21)
#define THREADS 512

__device__ __forceinline__ uint32_t pkbf(float lo, float hi){
  uint32_t r; asm("cvt.rn.bf16x2.f32 %0, %1, %2;" : "=r"(r) : "f"(hi), "f"(lo));
  return r;
}
__device__ __forceinline__ void mma16(float* d, uint32_t a0, uint32_t a1,
                                      uint32_t a2, uint32_t a3,
                                      uint32_t b0, uint32_t b1){
  asm volatile("mma.sync.aligned.m16n8k16.row.col.f32.bf16.bf16.f32 "
    "{%0,%1,%2,%3},{%4,%5,%6,%7},{%8,%9},{%0,%1,%2,%3};"
    : "+f"(d[0]), "+f"(d[1]), "+f"(d[2]), "+f"(d[3])
    : "r"(a0), "r"(a1), "r"(a2), "r"(a3), "r"(b0), "r"(b1));
}
__device__ __forceinline__ void ldsm4(uint32_t addr, uint32_t& a0, uint32_t& a1,
                                      uint32_t& a2, uint32_t& a3){
  asm volatile("ldmatrix.sync.aligned.m8n8.x4.shared.b16 {%0,%1,%2,%3},[%4];"
    : "=r"(a0),"=r"(a1),"=r"(a2),"=r"(a3) : "r"(addr));
}
__device__ __forceinline__ void ldsm2(uint32_t addr, uint32_t& b0, uint32_t& b1){
  asm volatile("ldmatrix.sync.aligned.m8n8.x2.shared.b16 {%0,%1},[%2];"
    : "=r"(b0),"=r"(b1) : "r"(addr));
}
__device__ __forceinline__ uint32_t smem_u32_of(const void* p){
  uint32_t a;
  asm("{ .reg .u64 t; cvta.to.shared.u64 t, %1; cvt.u32.u64 %0, t; }" : "=r"(a) : "l"(p));
  return a;
}
#define PAIRBAR(id) asm volatile("bar.sync %0, 64;" :: "r"(id) : "memory")

// smem layout (u32 units):
//  HS    0      8704   ln output bf16x2 [128][68]
//  STAT  8704   512    softmax / LN2 stats
//  SCR   9216   17408  wqkvT db 2x[80][68] / WoT_all[128][76] / w1t+w2t [128][68] each
//  OALL  26624  9728   O_all bf16x2 [128][76]
//  P     36352  8704   P bf16x2 [128][68]; overlays: vf fp32 [21][132], Ubuf [128][68]
//  QS    45056  2560   q bf16x2 [128][20] (u32 cols 12..15 zero)
//  KS    47616  2560   k bf16x2 [128][20] (u32 cols 12..15 zero)
//  VT    50176  1632   v^T bf16x2 [24][68] (rows 21..23 zero)
#define HSO   0
#define STATO 8704
#define SCRO  9216
#define OALLO 26624
#define PO    36352
#define QSO   45056
#define KSO   47616
#define VTO   50176
#define SMEM_U32 51808   // 207232 bytes

extern "C" __global__ void __launch_bounds__(THREADS, 1)
decoder_block_kernel(const float* __restrict__ gx,
                     const float* __restrict__ Wq,
                     const float* __restrict__ Wk,
                     const float* __restrict__ Wv,
                     const float* __restrict__ Wo,
                     const float* __restrict__ bo,
                     const float* __restrict__ W1,
                     const float* __restrict__ b1,
                     const float* __restrict__ W2,
                     const float* __restrict__ b2,
                     const float* __restrict__ g1,
                     const float* __restrict__ be1,
                     const float* __restrict__ g2,
                     const float* __restrict__ be2,
                     float* __restrict__ gout)
{
  extern __shared__ float sm[];
  uint32_t* u = (uint32_t*)sm;

  const int tid   = threadIdx.x;
  const int lane  = tid & 31;
  const int w     = tid >> 5;
  const int b     = blockIdx.x;
  const int qr    = lane >> 2;
  const int qc    = lane & 3;
  const int mrow  = (w & 7) * 16;
  const int nhalf = w >> 3;
  const int pairid = 1 + (w & 7);

  // A-fragment ldmatrix lane geometry
  const int aRow  = (lane & 7) + 8*((lane >> 3) & 1);
  const int aCoff = 4*(lane >> 4);
  // single B-fragment (x2) lane geometry
  const int bRow  = lane & 7;
  const int bCoff = 4*((lane >> 3) & 1);
  // paired B-fragments (x4) lane geometry: m = lane>>3 -> (m0,m1)=frag even
  // koff 0/4, (m2,m3)=frag odd (+8 rows) koff 0/4
  const int bpR   = (lane & 7) + ((lane >> 4) << 3);
  const int bpK   = ((lane >> 3) & 1) * 4;

  const uint32_t sb = smem_u32_of(sm);
  float* st = (float*)&u[STATO];

  const float* xb = gx   + (size_t)b * (TT * DM);
  float*       ob = gout + (size_t)b * (TT * DM);

  // ---------------- init: pads, wqkvT[0] stage (coalesced), LN1 ----------------
  {
    for (int idx = tid; idx < 512; idx += THREADS){
      int r = idx >> 2, j = idx & 3;
      u[QSO + r*20 + 12 + j] = 0u;
      u[KSO + r*20 + 12 + j] = 0u;
    }
    for (int idx = tid; idx < 204; idx += THREADS)
      u[VTO + 21*68 + idx] = 0u;

    // stage wqkvT buffer 0 (head 0): n fastest -> coalesced LDG
    for (int idx = tid; idx < 8192; idx += THREADS){
      int nn = idx & 127, k2 = idx >> 7;
      if (nn < 80){
        float lo = 0.f, hi = 0.f;
        const float* Wsrc = 0; int col = 0;
        if (nn < 21)                  { Wsrc = Wq; col = nn; }
        else if (nn >= 24 && nn < 45) { Wsrc = Wk; col = nn - 24; }
        else if (nn >= 48 && nn < 69) { Wsrc = Wv; col = nn - 48; }
        if (Wsrc){ lo = Wsrc[(2*k2)*21 + col]; hi = Wsrc[(2*k2+1)*21 + col]; }
        u[SCRO + nn*68 + k2] = pkbf(lo, hi);
      }
    }

    // LN1 from global x -> HS
    float2 ga = *(const float2*)&g1[2*lane];
    float2 gb = *(const float2*)&g1[64 + 2*lane];
    float2 ea = *(const float2*)&be1[2*lane];
    float2 eb = *(const float2*)&be1[64 + 2*lane];
    for (int r = w; r < TT; r += 16){
      float2 xa = *(const float2*)&xb[r*DM + 2*lane];
      float2 xc = *(const float2*)&xb[r*DM + 64 + 2*lane];
      float s  = xa.x + xa.y + xc.x + xc.y;
      float s2 = xa.x*xa.x + xa.y*xa.y + xc.x*xc.x + xc.y*xc.y;
      #pragma unroll
      for (int o = 16; o > 0; o >>= 1){
        s  += __shfl_xor_sync(0xffffffffu, s, o);
        s2 += __shfl_xor_sync(0xffffffffu, s2, o);
      }
      float mu = s * (1.f/DM);
      float rs = rsqrtf(s2 * (1.f/DM) - mu*mu + EPSF);
      u[HSO + r*68 + lane]      = pkbf((xa.x - mu)*rs*ga.x + ea.x,
                                       (xa.y - mu)*rs*ga.y + ea.y);
      u[HSO + r*68 + 32 + lane] = pkbf((xc.x - mu)*rs*gb.x + eb.x,
                                       (xc.y - mu)*rs*gb.y + eb.y);
    }
  }
  __syncthreads();

  // ---------------- attention: 6 heads ----------------
  for (int hh = 0; hh < NH; hh++){
    const uint32_t wbuf = SCRO + (uint32_t)(hh & 1) * 5440u;

    // P1: QKV GEMM + scatter; stage next head's weights (coalesced)
    {
      float qacc[5][4];
      #pragma unroll
      for (int f = 0; f < 5; f++)
        #pragma unroll
        for (int j = 0; j < 4; j++) qacc[f][j] = 0.f;

      uint32_t aB  = sb + 4u*(HSO + (uint32_t)(mrow + aRow)*68 + aCoff);
      uint32_t bP0 = sb + 4u*(wbuf + (uint32_t)(nhalf*40 + bpR)*68 + bpK);
      uint32_t bP1 = bP0 + 16u*68u*4u;
      uint32_t b4  = sb + 4u*(wbuf + (uint32_t)(nhalf*40 + 32 + bRow)*68 + bCoff);
      #pragma unroll
      for (int ks = 0; ks < 8; ks++){
        uint32_t a0,a1,a2,a3, b0,b1,b2,b3;
        ldsm4(aB + ks*32, a0,a1,a2,a3);
        ldsm4(bP0 + ks*32, b0,b1,b2,b3);
        mma16(qacc[0], a0,a1,a2,a3, b0,b1);
        mma16(qacc[1], a0,a1,a2,a3, b2,b3);
        ldsm4(bP1 + ks*32, b0,b1,b2,b3);
        mma16(qacc[2], a0,a1,a2,a3, b0,b1);
        mma16(qacc[3], a0,a1,a2,a3, b2,b3);
        ldsm2(b4 + ks*32, b0,b1);
        mma16(qacc[4], a0,a1,a2,a3, b0,b1);
      }
      float* vf = (float*)&u[PO];
      #pragma unroll
      for (int f = 0; f < 5; f++){
        int cc = nhalf*40 + f*8 + 2*qc;
        #pragma unroll
        for (int half = 0; half < 2; half++){
          int rr = mrow + qr + 8*half;
          float c0 = qacc[f][2*half], c1 = qacc[f][2*half + 1];
          if (cc < 24)       u[QSO + rr*20 + (cc>>1)] = pkbf(c0*SCALE, c1*SCALE);
          else if (cc < 48)  u[KSO + rr*20 + ((cc-24)>>1)] = pkbf(c0, c1);
          else if (cc < 72){
            vf[(cc-48)*132 + rr] = c0;
            vf[(cc-47)*132 + rr] = c1;
          }
        }
      }
      if (hh < 5){
        const uint32_t nbuf = SCRO + (uint32_t)((hh + 1) & 1) * 5440u;
        const float* Wq2 = Wq + (hh+1)*2688;
        const float* Wk2 = Wk + (hh+1)*2688;
        const float* Wv2 = Wv + (hh+1)*2688;
        for (int idx = tid; idx < 8192; idx += THREADS){
          int nn = idx & 127, k2 = idx >> 7;
          if (nn < 80){
            float lo = 0.f, hi = 0.f;
            const float* Wsrc = 0; int col = 0;
            if (nn < 21)                  { Wsrc = Wq2; col = nn; }
            else if (nn >= 24 && nn < 45) { Wsrc = Wk2; col = nn - 24; }
            else if (nn >= 48 && nn < 69) { Wsrc = Wv2; col = nn - 48; }
            if (Wsrc){ lo = Wsrc[(2*k2)*21 + col]; hi = Wsrc[(2*k2+1)*21 + col]; }
            u[nbuf + nn*68 + k2] = pkbf(lo, hi);
          }
        }
      }
    }
    __syncthreads();

    // P2a: VT pack + S GEMM + mask + local max/exp/sum + stats
    float sacc[8][4];
    float mx0, mx1;
    {
      const float* vf = (const float*)&u[PO];
      for (int idx = tid; idx < 1344; idx += THREADS){
        int e = idx >> 6, t2 = idx & 63;
        u[VTO + e*68 + t2] = pkbf(vf[e*132 + 2*t2], vf[e*132 + 2*t2 + 1]);
      }
      #pragma unroll
      for (int f = 0; f < 8; f++)
        #pragma unroll
        for (int j = 0; j < 4; j++) sacc[f][j] = 0.f;

      uint32_t aB = sb + 4u*(QSO + (uint32_t)(mrow + aRow)*20 + aCoff);
      #pragma unroll
      for (int ks = 0; ks < 2; ks++){
        uint32_t a0,a1,a2,a3;
        ldsm4(aB + ks*32, a0,a1,a2,a3);
        #pragma unroll
        for (int p = 0; p < 4; p++){
          uint32_t b0,b1,b2,b3;
          uint32_t bP = sb + 4u*(KSO + (uint32_t)(nhalf*64 + p*16 + bpR)*20 + bpK);
          ldsm4(bP + ks*32, b0,b1,b2,b3);
          mma16(sacc[2*p],   a0,a1,a2,a3, b0,b1);
          mma16(sacc[2*p+1], a0,a1,a2,a3, b2,b3);
        }
      }
      int r0 = mrow + qr, r1 = r0 + 8;
      mx0 = -1e30f; mx1 = -1e30f;
      #pragma unroll
      for (int f = 0; f < 8; f++){
        int c0 = nhalf*64 + f*8 + 2*qc;
        if (c0     > r0) sacc[f][0] = -1e30f;
        if (c0 + 1 > r0) sacc[f][1] = -1e30f;
        if (c0     > r1) sacc[f][2] = -1e30f;
        if (c0 + 1 > r1) sacc[f][3] = -1e30f;
        mx0 = fmaxf(mx0, fmaxf(sacc[f][0], sacc[f][1]));
        mx1 = fmaxf(mx1, fmaxf(sacc[f][2], sacc[f][3]));
      }
      mx0 = fmaxf(mx0, __shfl_xor_sync(0xffffffffu, mx0, 1));
      mx0 = fmaxf(mx0, __shfl_xor_sync(0xffffffffu, mx0, 2));
      mx1 = fmaxf(mx1, __shfl_xor_sync(0xffffffffu, mx1, 1));
      mx1 = fmaxf(mx1, __shfl_xor_sync(0xffffffffu, mx1, 2));
      float s0 = 0.f, s1 = 0.f;
      #pragma unroll
      for (int f = 0; f < 8; f++){
        sacc[f][0] = __expf(sacc[f][0] - mx0);
        sacc[f][1] = __expf(sacc[f][1] - mx0);
        sacc[f][2] = __expf(sacc[f][2] - mx1);
        sacc[f][3] = __expf(sacc[f][3] - mx1);
        s0 += sacc[f][0] + sacc[f][1];
        s1 += sacc[f][2] + sacc[f][3];
      }
      s0 += __shfl_xor_sync(0xffffffffu, s0, 1);
      s0 += __shfl_xor_sync(0xffffffffu, s0, 2);
      s1 += __shfl_xor_sync(0xffffffffu, s1, 1);
      s1 += __shfl_xor_sync(0xffffffffu, s1, 2);
      if (qc == 0){
        st[nhalf*128 + r0] = mx0;       st[nhalf*128 + r1] = mx1;
        st[256 + nhalf*128 + r0] = s0;  st[256 + nhalf*128 + r1] = s1;
      }
    }
    __syncthreads();

    // P2b: combine stats, write normalized P (bf16x2)
    {
      int r0 = mrow + qr, r1 = r0 + 8;
      float M0 = fmaxf(st[r0], st[128 + r0]);
      float M1 = fmaxf(st[r1], st[128 + r1]);
      float d0 = st[256 + r0]*__expf(st[r0] - M0) + st[384 + r0]*__expf(st[128 + r0] - M0);
      float d1 = st[256 + r1]*__expf(st[r1] - M1) + st[384 + r1]*__expf(st[128 + r1] - M1);
      float sc0 = __expf(mx0 - M0) / d0;
      float sc1 = __expf(mx1 - M1) / d1;
      #pragma unroll
      for (int f = 0; f < 8; f++){
        int uc = nhalf*32 + f*4 + qc;
        u[PO + r0*68 + uc] = pkbf(sacc[f][0]*sc0, sacc[f][1]*sc0);
        u[PO + r1*68 + uc] = pkbf(sacc[f][2]*sc1, sacc[f][3]*sc1);
      }
    }
    PAIRBAR(pairid);

    // P3: O GEMM -> O_all slab
    {
      float oacc[2][4];
      #pragma unroll
      for (int f = 0; f < 2; f++)
        #pragma unroll
        for (int j = 0; j < 4; j++) oacc[f][j] = 0.f;

      uint32_t aB = sb + 4u*(PO + (uint32_t)(mrow + aRow)*68 + aCoff);
      if (nhalf == 0){
        uint32_t bP = sb + 4u*(VTO + (uint32_t)bpR*68 + bpK);
        #pragma unroll
        for (int ks = 0; ks < 8; ks++){
          uint32_t a0,a1,a2,a3, b0,b1,b2,b3;
          ldsm4(aB + ks*32, a0,a1,a2,a3);
          ldsm4(bP + ks*32, b0,b1,b2,b3);
          mma16(oacc[0], a0,a1,a2,a3, b0,b1);
          mma16(oacc[1], a0,a1,a2,a3, b2,b3);
        }
      } else {
        uint32_t bB = sb + 4u*(VTO + (uint32_t)(16 + bRow)*68 + bCoff);
        #pragma unroll
        for (int ks = 0; ks < 8; ks++){
          uint32_t a0,a1,a2,a3, b0,b1;
          ldsm4(aB + ks*32, a0,a1,a2,a3);
          ldsm2(bB + ks*32, b0,b1);
          mma16(oacc[0], a0,a1,a2,a3, b0,b1);
        }
      }
      const int nfc = nhalf ? 1 : 2;
      #pragma unroll
      for (int f = 0; f < 2; f++){
        if (f < nfc){
          int uc = hh*12 + (nhalf*2 + f)*4 + qc;
          u[OALLO + (mrow+qr)*76   + uc] = pkbf(oacc[f][0], oacc[f][1]);
          u[OALLO + (mrow+qr+8)*76 + uc] = pkbf(oacc[f][2], oacc[f][3]);
        }
      }
    }
    __syncthreads();
  }

  // ---------------- stage WoT_all [128][76] (coalesced) ----------------
  for (int idx = tid; idx < 9216; idx += THREADS){
    int n = idx & 127, k2 = idx >> 7;     // k2 0..71
    int head = k2 / 12, within = k2 - head*12;
    int e0 = 2*within;
    float lo = (e0     < 21) ? Wo[(head*21 + e0    )*DM + n] : 0.f;
    float hi = (e0 + 1 < 21) ? Wo[(head*21 + e0 + 1)*DM + n] : 0.f;
    u[SCRO + n*76 + k2] = pkbf(lo, hi);
  }
  __syncthreads();

  // ---------------- fold (K=144) -> x2 regs; LN2 partial stats ----------------
  float x2r[8][4];
  {
    #pragma unroll
    for (int f = 0; f < 8; f++)
      #pragma unroll
      for (int j = 0; j < 4; j++) x2r[f][j] = 0.f;

    uint32_t aB = sb + 4u*(OALLO + (uint32_t)(mrow + aRow)*76 + aCoff);
    #pragma unroll
    for (int ks = 0; ks < 9; ks++){
      uint32_t a0,a1,a2,a3;
      ldsm4(aB + ks*32, a0,a1,a2,a3);
      #pragma unroll
      for (int p = 0; p < 4; p++){
        uint32_t b0,b1,b2,b3;
        uint32_t bP = sb + 4u*(SCRO + (uint32_t)(nhalf*64 + p*16 + bpR)*76 + bpK);
        ldsm4(bP + ks*32, b0,b1,b2,b3);
        mma16(x2r[2*p],   a0,a1,a2,a3, b0,b1);
        mma16(x2r[2*p+1], a0,a1,a2,a3, b2,b3);
      }
    }
    int r0 = mrow + qr, r1 = r0 + 8;
    float s0 = 0.f, q0 = 0.f, s1 = 0.f, q1 = 0.f;
    #pragma unroll
    for (int f = 0; f < 8; f++){
      int cc = nhalf*64 + f*8 + 2*qc;
      float2 bv = *(const float2*)&bo[cc];
      float2 xa = *(const float2*)&xb[r0*DM + cc];
      float2 xc = *(const float2*)&xb[r1*DM + cc];
      x2r[f][0] += xa.x + bv.x;  x2r[f][1] += xa.y + bv.y;
      x2r[f][2] += xc.x + bv.x;  x2r[f][3] += xc.y + bv.y;
      s0 += x2r[f][0] + x2r[f][1];
      q0 += x2r[f][0]*x2r[f][0] + x2r[f][1]*x2r[f][1];
      s1 += x2r[f][2] + x2r[f][3];
      q1 += x2r[f][2]*x2r[f][2] + x2r[f][3]*x2r[f][3];
    }
    s0 += __shfl_xor_sync(0xffffffffu, s0, 1); s0 += __shfl_xor_sync(0xffffffffu, s0, 2);
    q0 += __shfl_xor_sync(0xffffffffu, q0, 1); q0 += __shfl_xor_sync(0xffffffffu, q0, 2);
    s1 += __shfl_xor_sync(0xffffffffu, s1, 1); s1 += __shfl_xor_sync(0xffffffffu, s1, 2);
    q1 += __shfl_xor_sync(0xffffffffu, q1, 1); q1 += __shfl_xor_sync(0xffffffffu, q1, 2);
    if (qc == 0){
      st[nhalf*128 + r0] = s0;        st[nhalf*128 + r1] = s1;
      st[256 + nhalf*128 + r0] = q0;  st[256 + nhalf*128 + r1] = q1;
    }
  }
  __syncthreads();

  // ---------------- LN2 finalize -> HS ; stage FFN chunk 0 ----------------
  {
    int r0 = mrow + qr, r1 = r0 + 8;
    float S0 = st[r0] + st[128 + r0], Q0 = st[256 + r0] + st[384 + r0];
    float S1 = st[r1] + st[128 + r1], Q1 = st[256 + r1] + st[384 + r1];
    float mu0 = S0 * (1.f/DM), rs0 = rsqrtf(Q0*(1.f/DM) - mu0*mu0 + EPSF);
    float mu1 = S1 * (1.f/DM), rs1 = rsqrtf(Q1*(1.f/DM) - mu1*mu1 + EPSF);
    #pragma unroll
    for (int f = 0; f < 8; f++){
      int cc = nhalf*64 + f*8 + 2*qc;
      float2 gv = *(const float2*)&g2[cc];
      float2 ev = *(const float2*)&be2[cc];
      u[HSO + r0*68 + (cc>>1)] = pkbf((x2r[f][0]-mu0)*rs0*gv.x + ev.x,
                                      (x2r[f][1]-mu0)*rs0*gv.y + ev.y);
      u[HSO + r1*68 + (cc>>1)] = pkbf((x2r[f][2]-mu1)*rs1*gv.x + ev.x,
                                      (x2r[f][3]-mu1)*rs1*gv.y + ev.y);
    }
    // stage w1t/w2t for chunk 0 (coalesced: n fastest)
    for (int idx = tid; idx < 8192; idx += THREADS){
      int n = idx & 127, k2 = idx >> 7;
      u[SCRO + n*68 + k2] = pkbf(W1[(2*k2)*DF + n], W1[(2*k2+1)*DF + n]);
    }
    for (int idx = tid; idx < 8192; idx += THREADS){
      int n = idx & 127, k2 = idx >> 7;
      u[SCRO + 8704 + n*68 + k2] = pkbf(W2[(2*k2)*DM + n], W2[(2*k2+1)*DM + n]);
    }
  }
  __syncthreads();

  // ---------------- FFN: 4 chunks of 128 ----------------
  float dacc[8][4];
  #pragma unroll
  for (int f = 0; f < 8; f++)
    #pragma unroll
    for (int j = 0; j < 4; j++) dacc[f][j] = 0.f;

  for (int cb = 0; cb < 4; cb++){
    // U(128x128) = relu(hs @ w1chunk + b1) -> Ubuf (P region)
    {
      float uacc[8][4];
      #pragma unroll
      for (int f = 0; f < 8; f++)
        #pragma unroll
        for (int j = 0; j < 4; j++) uacc[f][j] = 0.f;

      uint32_t aB = sb + 4u*(HSO + (uint32_t)(mrow + aRow)*68 + aCoff);
      #pragma unroll
      for (int ks = 0; ks < 8; ks++){
        uint32_t a0,a1,a2,a3;
        ldsm4(aB + ks*32, a0,a1,a2,a3);
        #pragma unroll
        for (int p = 0; p < 4; p++){
          uint32_t b0,b1,b2,b3;
          uint32_t bP = sb + 4u*(SCRO + (uint32_t)(nhalf*64 + p*16 + bpR)*68 + bpK);
          ldsm4(bP + ks*32, b0,b1,b2,b3);
          mma16(uacc[2*p],   a0,a1,a2,a3, b0,b1);
          mma16(uacc[2*p+1], a0,a1,a2,a3, b2,b3);
        }
      }
      int r0 = mrow + qr, r1 = r0 + 8;
      #pragma unroll
      for (int f = 0; f < 8; f++){
        int cc = nhalf*64 + f*8 + 2*qc;
        float2 bv = *(const float2*)&b1[cb*128 + cc];
        u[PO + r0*68 + (cc>>1)] = pkbf(fmaxf(uacc[f][0] + bv.x, 0.f),
                                       fmaxf(uacc[f][1] + bv.y, 0.f));
        u[PO + r1*68 + (cc>>1)] = pkbf(fmaxf(uacc[f][2] + bv.x, 0.f),
                                       fmaxf(uacc[f][3] + bv.y, 0.f));
      }
    }
    PAIRBAR(pairid);

    // D2 += U @ w2chunk (K=128)
    {
      uint32_t aB = sb + 4u*(PO + (uint32_t)(mrow + aRow)*68 + aCoff);
      #pragma unroll
      for (int ks = 0; ks < 8; ks++){
        uint32_t a0,a1,a2,a3;
        ldsm4(aB + ks*32, a0,a1,a2,a3);
        #pragma unroll
        for (int p = 0; p < 4; p++){
          uint32_t b0,b1,b2,b3;
          uint32_t bP = sb + 4u*(SCRO + 8704 + (uint32_t)(nhalf*64 + p*16 + bpR)*68 + bpK);
          ldsm4(bP + ks*32, b0,b1,b2,b3);
          mma16(dacc[2*p],   a0,a1,a2,a3, b0,b1);
          mma16(dacc[2*p+1], a0,a1,a2,a3, b2,b3);
        }
      }
    }
    __syncthreads();

    // stage next chunk's weights (coalesced)
    if (cb < 3){
      for (int idx = tid; idx < 8192; idx += THREADS){
        int n = idx & 127, k2 = idx >> 7;
        u[SCRO + n*68 + k2] = pkbf(W1[(2*k2)*DF + (cb+1)*128 + n],
                                   W1[(2*k2+1)*DF + (cb+1)*128 + n]);
      }
      for (int idx = tid; idx < 8192; idx += THREADS){
        int n = idx & 127, k2 = idx >> 7;
        u[SCRO + 8704 + n*68 + k2] = pkbf(W2[((cb+1)*128 + 2*k2)*DM + n],
                                          W2[((cb+1)*128 + 2*k2+1)*DM + n]);
      }
      __syncthreads();
    }
  }

  // ---------------- epilogue: out = x2 + D2 + b2 ----------------
  {
    int r0 = mrow + qr, r1 = r0 + 8;
    #pragma unroll
    for (int f = 0; f < 8; f++){
      int cc = nhalf*64 + f*8 + 2*qc;
      float2 bv = *(const float2*)&b2[cc];
      float2 o0 = make_float2(x2r[f][0] + dacc[f][0] + bv.x,
                              x2r[f][1] + dacc[f][1] + bv.y);
      float2 o1 = make_float2(x2r[f][2] + dacc[f][2] + bv.x,
                              x2r[f][3] + dacc[f][3] + bv.y);
      *(float2*)&ob[r0*DM + cc] = o0;
      *(float2*)&ob[r1*DM + cc] = o1;
    }
  }
}

extern "C" void kernel_launch(void* const* d_in, const int* in_sizes, int n_in,
                              void* d_out, int out_size)
{
  (void)in_sizes; (void)n_in; (void)out_size;
  cudaFuncSetAttribute(decoder_block_kernel,
                       cudaFuncAttributeMaxDynamicSharedMemorySize,
                       SMEM_U32 * 4);
  decoder_block_kernel<<<NB, THREADS, SMEM_U32 * 4>>>(
      (const float*)d_in[0],  (const float*)d_in[1],  (const float*)d_in[2],
      (const float*)d_in[3],  (const float*)d_in[4],  (const float*)d_in[5],
      (const float*)d_in[6],  (const float*)d_in[7],  (const float*)d_in[8],
      (const float*)d_in[9],  (const float*)d_in[10], (const float*)d_in[11],
      (const float*)d_in[12], (const float*)d_in[13],
      (float*)d_out);
}

// round 13
// speedup vs baseline: 4.0168x; 1.1406x over previous
#include <cuda_runtime.h>
#include <cstdint>

// Fused transformer decoder block, one CTA per batch element, 512 threads.
// Attention: 2 heads in flight (8 warps each, full-N per warp); S/P/O via
// register repack (no P smem). All GEMMs mma.sync m16n8k16 bf16 + ldmatrix.
// Residual/attn/FFN accumulators in registers. Coalesced weight staging.
// B=512, T=128, D=128, H=6, Dh=21, DF=512.

#define NB 512
#define TT 128
#define DM 128
#define NH 6
#define DF 512
#define EPSF 1e-5f
#define SCALE 0.21821789023599236f   // 1/sqrt(21)
#define THREADS 512

__device__ __forceinline__ uint32_t pkbf(float lo, float hi){
  uint32_t r; asm("cvt.rn.bf16x2.f32 %0, %1, %2;" : "=r"(r) : "f"(hi), "f"(lo));
  return r;
}
__device__ __forceinline__ void mma16(float* d, uint32_t a0, uint32_t a1,
                                      uint32_t a2, uint32_t a3,
                                      uint32_t b0, uint32_t b1){
  asm volatile("mma.sync.aligned.m16n8k16.row.col.f32.bf16.bf16.f32 "
    "{%0,%1,%2,%3},{%4,%5,%6,%7},{%8,%9},{%0,%1,%2,%3};"
    : "+f"(d[0]), "+f"(d[1]), "+f"(d[2]), "+f"(d[3])
    : "r"(a0), "r"(a1), "r"(a2), "r"(a3), "r"(b0), "r"(b1));
}
__device__ __forceinline__ void ldsm4(uint32_t addr, uint32_t& a0, uint32_t& a1,
                                      uint32_t& a2, uint32_t& a3){
  asm volatile("ldmatrix.sync.aligned.m8n8.x4.shared.b16 {%0,%1,%2,%3},[%4];"
    : "=r"(a0),"=r"(a1),"=r"(a2),"=r"(a3) : "r"(addr));
}
__device__ __forceinline__ void ldsm2(uint32_t addr, uint32_t& b0, uint32_t& b1){
  asm volatile("ldmatrix.sync.aligned.m8n8.x2.shared.b16 {%0,%1},[%2];"
    : "=r"(b0),"=r"(b1) : "r"(addr));
}
__device__ __forceinline__ uint32_t smem_u32_of(const void* p){
  uint32_t a;
  asm("{ .reg .u64 t; cvta.to.shared.u64 t, %1; cvt.u32.u64 %0, t; }" : "=r"(a) : "l"(p));
  return a;
}
#define GROUPBAR(g) asm volatile("bar.sync %0, 256;" :: "r"(1 + (g)) : "memory")
#define PAIRBAR(id) asm volatile("bar.sync %0, 64;"  :: "r"(id) : "memory")

// smem layout (u32 units):
//  HS    0      8704   ln output bf16x2 [128][68]
//  WQ    8704   19584  wqkvT pair db: 2 x [144][68] (72 rows per head)
//                       FFN: w1t[128][68]@WQ + w2t[128][68]@WQ+8704; WoT[128][76]
//  OALL  28288  9728   O_all bf16x2 [128][76]
//  KS0   38016  2560   k head A [128][20]
//  KS1   40576  2560   k head B
//  VT0   43136  1632   v^T head A [24][68]
//  VT1   44768  1632   v^T head B
//  STAT  46400  512    LN2 stats
//  PO    46912  8704   FFN U buffer [128][68]
#define HSO   0
#define WQO   8704
#define OALLO 28288
#define KS0O  38016
#define KS1O  40576
#define VT0O  43136
#define VT1O  44768
#define STATO 46400
#define POO   46912
#define SMEM_U32 55616   // 222464 bytes

extern "C" __global__ void __launch_bounds__(THREADS, 1)
decoder_block_kernel(const float* __restrict__ gx,
                     const float* __restrict__ Wq,
                     const float* __restrict__ Wk,
                     const float* __restrict__ Wv,
                     const float* __restrict__ Wo,
                     const float* __restrict__ bo,
                     const float* __restrict__ W1,
                     const float* __restrict__ b1,
                     const float* __restrict__ W2,
                     const float* __restrict__ b2,
                     const float* __restrict__ g1,
                     const float* __restrict__ be1,
                     const float* __restrict__ g2,
                     const float* __restrict__ be2,
                     float* __restrict__ gout)
{
  extern __shared__ float sm[];
  uint32_t* u = (uint32_t*)sm;

  const int tid   = threadIdx.x;
  const int lane  = tid & 31;
  const int w     = tid >> 5;
  const int b     = blockIdx.x;
  const int qr    = lane >> 2;
  const int qc    = lane & 3;
  const int gid   = w >> 3;            // head group 0/1
  const int wl    = w & 7;
  const int mrow  = wl * 16;
  const int nhalf = gid;               // FFN reuses gid as N-half

  const int aRow  = (lane & 7) + 8*((lane >> 3) & 1);
  const int aCoff = 4*(lane >> 4);
  const int bRow  = lane & 7;
  const int bCoff = 4*((lane >> 3) & 1);
  const int bpR   = (lane & 7) + ((lane >> 4) << 3);
  const int bpK   = ((lane >> 3) & 1) * 4;

  const uint32_t sb = smem_u32_of(sm);
  float* st = (float*)&u[STATO];

  const uint32_t ksb = gid ? KS1O : KS0O;
  const uint32_t vtb = gid ? VT1O : VT0O;

  const float* xb = gx   + (size_t)b * (TT * DM);
  float*       ob = gout + (size_t)b * (TT * DM);

  // ---------------- init: KS pads, stage pair-0 weights, LN1 ----------------
  {
    for (int idx = tid; idx < 2048; idx += THREADS){
      int r = idx >> 3, j = idx & 7;
      uint32_t base = (j < 4) ? KS0O : KS1O;
      u[base + r*20 + 12 + (j & 3)] = 0u;
    }
    // stage wqkvT pair 0 (heads 0,1): [144][68], 72 rows per head
    for (int idx = tid; idx < 9216; idx += THREADS){
      int k2 = idx / 144, nn = idx - k2*144;
      int hh = (nn >= 72) ? 1 : 0;
      int n0 = nn - hh*72;
      const float* Wsrc = 0; int col = 0;
      if (n0 < 21)                  { Wsrc = Wq + hh*2688; col = n0; }
      else if (n0 >= 24 && n0 < 45) { Wsrc = Wk + hh*2688; col = n0 - 24; }
      else if (n0 >= 48 && n0 < 69) { Wsrc = Wv + hh*2688; col = n0 - 48; }
      float lo = 0.f, hi = 0.f;
      if (Wsrc){ lo = Wsrc[(2*k2)*21 + col]; hi = Wsrc[(2*k2+1)*21 + col]; }
      u[WQO + nn*68 + k2] = pkbf(lo, hi);
    }
    // LN1 from global x -> HS
    float2 ga = *(const float2*)&g1[2*lane];
    float2 gb = *(const float2*)&g1[64 + 2*lane];
    float2 ea = *(const float2*)&be1[2*lane];
    float2 eb = *(const float2*)&be1[64 + 2*lane];
    for (int r = w; r < TT; r += 16){
      float2 xa = *(const float2*)&xb[r*DM + 2*lane];
      float2 xc = *(const float2*)&xb[r*DM + 64 + 2*lane];
      float s  = xa.x + xa.y + xc.x + xc.y;
      float s2 = xa.x*xa.x + xa.y*xa.y + xc.x*xc.x + xc.y*xc.y;
      #pragma unroll
      for (int o = 16; o > 0; o >>= 1){
        s  += __shfl_xor_sync(0xffffffffu, s, o);
        s2 += __shfl_xor_sync(0xffffffffu, s2, o);
      }
      float mu = s * (1.f/DM);
      float rs = rsqrtf(s2 * (1.f/DM) - mu*mu + EPSF);
      u[HSO + r*68 + lane]      = pkbf((xa.x - mu)*rs*ga.x + ea.x,
                                       (xa.y - mu)*rs*ga.y + ea.y);
      u[HSO + r*68 + 32 + lane] = pkbf((xc.x - mu)*rs*gb.x + eb.x,
                                       (xc.y - mu)*rs*gb.y + eb.y);
    }
  }
  __syncthreads();

  // ---------------- attention: 3 head pairs, 2 heads concurrent ----------------
  for (int pr = 0; pr < 3; pr++){
    const int hh = pr*2 + gid;
    const uint32_t wbuf = WQO + (uint32_t)(pr & 1) * 9792u;
    const uint32_t wrow = (uint32_t)gid * 72u;

    // -- QKV GEMM: 16 rows x 72 cols (9 frags) --
    float qacc[9][4];
    #pragma unroll
    for (int f = 0; f < 9; f++)
      #pragma unroll
      for (int j = 0; j < 4; j++) qacc[f][j] = 0.f;
    {
      uint32_t aB = sb + 4u*(HSO + (uint32_t)(mrow + aRow)*68 + aCoff);
      uint32_t bP[4], b8;
      #pragma unroll
      for (int p = 0; p < 4; p++)
        bP[p] = sb + 4u*(wbuf + (wrow + p*16 + bpR)*68 + bpK);
      b8 = sb + 4u*(wbuf + (wrow + 64 + bRow)*68 + bCoff);
      #pragma unroll
      for (int ks = 0; ks < 8; ks++){
        uint32_t a0,a1,a2,a3, b0,b1,b2,b3;
        ldsm4(aB + ks*32, a0,a1,a2,a3);
        #pragma unroll
        for (int p = 0; p < 4; p++){
          ldsm4(bP[p] + ks*32, b0,b1,b2,b3);
          mma16(qacc[2*p],   a0,a1,a2,a3, b0,b1);
          mma16(qacc[2*p+1], a0,a1,a2,a3, b2,b3);
        }
        ldsm2(b8 + ks*32, b0,b1);
        mma16(qacc[8], a0,a1,a2,a3, b0,b1);
      }
    }

    // -- scatter/repack: q->regs (scaled), k->KS, v->VT (shuffle pack) --
    uint32_t aq[2][4];
    aq[0][0] = pkbf(qacc[0][0]*SCALE, qacc[0][1]*SCALE);
    aq[0][1] = pkbf(qacc[0][2]*SCALE, qacc[0][3]*SCALE);
    aq[0][2] = pkbf(qacc[1][0]*SCALE, qacc[1][1]*SCALE);
    aq[0][3] = pkbf(qacc[1][2]*SCALE, qacc[1][3]*SCALE);
    aq[1][0] = pkbf(qacc[2][0]*SCALE, qacc[2][1]*SCALE);
    aq[1][1] = pkbf(qacc[2][2]*SCALE, qacc[2][3]*SCALE);
    aq[1][2] = 0u; aq[1][3] = 0u;
    #pragma unroll
    for (int f = 0; f < 3; f++){
      int e2 = (f*8 + 2*qc) >> 1;
      u[ksb + (mrow+qr)*20 + e2]   = pkbf(qacc[3+f][0], qacc[3+f][1]);
      u[ksb + (mrow+qr+8)*20 + e2] = pkbf(qacc[3+f][2], qacc[3+f][3]);
    }
    #pragma unroll
    for (int f = 0; f < 3; f++){
      int e0 = f*8 + 2*qc;
      #pragma unroll
      for (int h = 0; h < 2; h++){
        float v0 = qacc[6+f][2*h], v1 = qacc[6+f][2*h+1];
        float p0 = __shfl_xor_sync(0xffffffffu, v0, 4);
        float p1 = __shfl_xor_sync(0xffffffffu, v1, 4);
        if (!(qr & 1)){
          int t2 = (mrow + qr + 8*h) >> 1;
          u[vtb + e0*68 + t2]       = pkbf(v0, p0);
          u[vtb + (e0+1)*68 + t2]   = pkbf(v1, p1);
        }
      }
    }

    // -- stage next pair's weights (other buffer); overlaps S/O compute --
    if (pr < 2){
      const uint32_t nbuf = WQO + (uint32_t)((pr + 1) & 1) * 9792u;
      for (int idx = tid; idx < 9216; idx += THREADS){
        int k2 = idx / 144, nn = idx - k2*144;
        int h2 = (pr+1)*2 + ((nn >= 72) ? 1 : 0);
        int n0 = (nn >= 72) ? nn - 72 : nn;
        const float* Wsrc = 0; int col = 0;
        if (n0 < 21)                  { Wsrc = Wq + h2*2688; col = n0; }
        else if (n0 >= 24 && n0 < 45) { Wsrc = Wk + h2*2688; col = n0 - 24; }
        else if (n0 >= 48 && n0 < 69) { Wsrc = Wv + h2*2688; col = n0 - 48; }
        float lo = 0.f, hi = 0.f;
        if (Wsrc){ lo = Wsrc[(2*k2)*21 + col]; hi = Wsrc[(2*k2+1)*21 + col]; }
        u[nbuf + nn*68 + k2] = pkbf(lo, hi);
      }
    }
    GROUPBAR(gid);

    // -- S GEMM: 16 rows x 128 cols, K=32 --
    float sacc[16][4];
    #pragma unroll
    for (int f = 0; f < 16; f++)
      #pragma unroll
      for (int j = 0; j < 4; j++) sacc[f][j] = 0.f;
    #pragma unroll
    for (int kg = 0; kg < 2; kg++){
      #pragma unroll
      for (int p = 0; p < 8; p++){
        uint32_t b0,b1,b2,b3;
        uint32_t bP = sb + 4u*(ksb + (uint32_t)(p*16 + bpR)*20 + kg*8 + bpK);
        ldsm4(bP, b0,b1,b2,b3);
        mma16(sacc[2*p],   aq[kg][0],aq[kg][1],aq[kg][2],aq[kg][3], b0,b1);
        mma16(sacc[2*p+1], aq[kg][0],aq[kg][1],aq[kg][2],aq[kg][3], b2,b3);
      }
    }

    // -- warp-local masked softmax + P repack to A-frags --
    uint32_t pa[8][4];
    {
      int r0 = mrow + qr, r1 = r0 + 8;
      float mx0 = -1e30f, mx1 = -1e30f;
      #pragma unroll
      for (int f = 0; f < 16; f++){
        int c0 = f*8 + 2*qc;
        if (c0     > r0) sacc[f][0] = -1e30f;
        if (c0 + 1 > r0) sacc[f][1] = -1e30f;
        if (c0     > r1) sacc[f][2] = -1e30f;
        if (c0 + 1 > r1) sacc[f][3] = -1e30f;
        mx0 = fmaxf(mx0, fmaxf(sacc[f][0], sacc[f][1]));
        mx1 = fmaxf(mx1, fmaxf(sacc[f][2], sacc[f][3]));
      }
      mx0 = fmaxf(mx0, __shfl_xor_sync(0xffffffffu, mx0, 1));
      mx0 = fmaxf(mx0, __shfl_xor_sync(0xffffffffu, mx0, 2));
      mx1 = fmaxf(mx1, __shfl_xor_sync(0xffffffffu, mx1, 1));
      mx1 = fmaxf(mx1, __shfl_xor_sync(0xffffffffu, mx1, 2));
      float s0 = 0.f, s1 = 0.f;
      #pragma unroll
      for (int f = 0; f < 16; f++){
        sacc[f][0] = __expf(sacc[f][0] - mx0);
        sacc[f][1] = __expf(sacc[f][1] - mx0);
        sacc[f][2] = __expf(sacc[f][2] - mx1);
        sacc[f][3] = __expf(sacc[f][3] - mx1);
        s0 += sacc[f][0] + sacc[f][1];
        s1 += sacc[f][2] + sacc[f][3];
      }
      s0 += __shfl_xor_sync(0xffffffffu, s0, 1);
      s0 += __shfl_xor_sync(0xffffffffu, s0, 2);
      s1 += __shfl_xor_sync(0xffffffffu, s1, 1);
      s1 += __shfl_xor_sync(0xffffffffu, s1, 2);
      float inv0 = 1.f / s0, inv1 = 1.f / s1;
      #pragma unroll
      for (int g = 0; g < 8; g++){
        pa[g][0] = pkbf(sacc[2*g][0]*inv0,   sacc[2*g][1]*inv0);
        pa[g][1] = pkbf(sacc[2*g][2]*inv1,   sacc[2*g][3]*inv1);
        pa[g][2] = pkbf(sacc[2*g+1][0]*inv0, sacc[2*g+1][1]*inv0);
        pa[g][3] = pkbf(sacc[2*g+1][2]*inv1, sacc[2*g+1][3]*inv1);
      }
    }

    // -- O GEMM: 16 rows x 24 cols, K=128, B from VT --
    {
      float oacc[3][4];
      #pragma unroll
      for (int f = 0; f < 3; f++)
        #pragma unroll
        for (int j = 0; j < 4; j++) oacc[f][j] = 0.f;
      #pragma unroll
      for (int kg = 0; kg < 8; kg++){
        uint32_t b0,b1,b2,b3;
        uint32_t bP = sb + 4u*(vtb + (uint32_t)bpR*68 + kg*8 + bpK);
        ldsm4(bP, b0,b1,b2,b3);
        mma16(oacc[0], pa[kg][0],pa[kg][1],pa[kg][2],pa[kg][3], b0,b1);
        mma16(oacc[1], pa[kg][0],pa[kg][1],pa[kg][2],pa[kg][3], b2,b3);
        uint32_t bQ = sb + 4u*(vtb + (uint32_t)(16 + bRow)*68 + kg*8 + bCoff);
        ldsm2(bQ, b0,b1);
        mma16(oacc[2], pa[kg][0],pa[kg][1],pa[kg][2],pa[kg][3], b0,b1);
      }
      #pragma unroll
      for (int f = 0; f < 3; f++){
        int uc = hh*12 + f*4 + qc;
        u[OALLO + (mrow+qr)*76 + uc]   = pkbf(oacc[f][0], oacc[f][1]);
        u[OALLO + (mrow+qr+8)*76 + uc] = pkbf(oacc[f][2], oacc[f][3]);
      }
    }
    __syncthreads();   // KS/VT reusable; next-pair weights visible to both groups
  }

  // ---------------- stage WoT_all [128][76] (coalesced) ----------------
  for (int idx = tid; idx < 9216; idx += THREADS){
    int n = idx & 127, k2 = idx >> 7;     // k2 0..71
    int head = k2 / 12, within = k2 - head*12;
    int e0 = 2*within;
    float lo = (e0     < 21) ? Wo[(head*21 + e0    )*DM + n] : 0.f;
    float hi = (e0 + 1 < 21) ? Wo[(head*21 + e0 + 1)*DM + n] : 0.f;
    u[WQO + n*76 + k2] = pkbf(lo, hi);
  }
  __syncthreads();

  // ---------------- fold (K=144) -> x2 regs; LN2 partial stats ----------------
  float x2r[8][4];
  {
    #pragma unroll
    for (int f = 0; f < 8; f++)
      #pragma unroll
      for (int j = 0; j < 4; j++) x2r[f][j] = 0.f;

    uint32_t aB = sb + 4u*(OALLO + (uint32_t)(mrow + aRow)*76 + aCoff);
    #pragma unroll
    for (int ks = 0; ks < 9; ks++){
      uint32_t a0,a1,a2,a3;
      ldsm4(aB + ks*32, a0,a1,a2,a3);
      #pragma unroll
      for (int p = 0; p < 4; p++){
        uint32_t b0,b1,b2,b3;
        uint32_t bP = sb + 4u*(WQO + (uint32_t)(nhalf*64 + p*16 + bpR)*76 + bpK);
        ldsm4(bP + ks*32, b0,b1,b2,b3);
        mma16(x2r[2*p],   a0,a1,a2,a3, b0,b1);
        mma16(x2r[2*p+1], a0,a1,a2,a3, b2,b3);
      }
    }
    int r0 = mrow + qr, r1 = r0 + 8;
    float s0 = 0.f, q0 = 0.f, s1 = 0.f, q1 = 0.f;
    #pragma unroll
    for (int f = 0; f < 8; f++){
      int cc = nhalf*64 + f*8 + 2*qc;
      float2 bv = *(const float2*)&bo[cc];
      float2 xa = *(const float2*)&xb[r0*DM + cc];
      float2 xc = *(const float2*)&xb[r1*DM + cc];
      x2r[f][0] += xa.x + bv.x;  x2r[f][1] += xa.y + bv.y;
      x2r[f][2] += xc.x + bv.x;  x2r[f][3] += xc.y + bv.y;
      s0 += x2r[f][0] + x2r[f][1];
      q0 += x2r[f][0]*x2r[f][0] + x2r[f][1]*x2r[f][1];
      s1 += x2r[f][2] + x2r[f][3];
      q1 += x2r[f][2]*x2r[f][2] + x2r[f][3]*x2r[f][3];
    }
    s0 += __shfl_xor_sync(0xffffffffu, s0, 1); s0 += __shfl_xor_sync(0xffffffffu, s0, 2);
    q0 += __shfl_xor_sync(0xffffffffu, q0, 1); q0 += __shfl_xor_sync(0xffffffffu, q0, 2);
    s1 += __shfl_xor_sync(0xffffffffu, s1, 1); s1 += __shfl_xor_sync(0xffffffffu, s1, 2);
    q1 += __shfl_xor_sync(0xffffffffu, q1, 1); q1 += __shfl_xor_sync(0xffffffffu, q1, 2);
    if (qc == 0){
      st[nhalf*128 + r0] = s0;        st[nhalf*128 + r1] = s1;
      st[256 + nhalf*128 + r0] = q0;  st[256 + nhalf*128 + r1] = q1;
    }
  }
  __syncthreads();

  // ---------------- LN2 finalize -> HS ; stage FFN chunk 0 ----------------
  {
    int r0 = mrow + qr, r1 = r0 + 8;
    float S0 = st[r0] + st[128 + r0], Q0 = st[256 + r0] + st[384 + r0];
    float S1 = st[r1] + st[128 + r1], Q1 = st[256 + r1] + st[384 + r1];
    float mu0 = S0 * (1.f/DM), rs0 = rsqrtf(Q0*(1.f/DM) - mu0*mu0 + EPSF);
    float mu1 = S1 * (1.f/DM), rs1 = rsqrtf(Q1*(1.f/DM) - mu1*mu1 + EPSF);
    #pragma unroll
    for (int f = 0; f < 8; f++){
      int cc = nhalf*64 + f*8 + 2*qc;
      float2 gv = *(const float2*)&g2[cc];
      float2 ev = *(const float2*)&be2[cc];
      u[HSO + r0*68 + (cc>>1)] = pkbf((x2r[f][0]-mu0)*rs0*gv.x + ev.x,
                                      (x2r[f][1]-mu0)*rs0*gv.y + ev.y);
      u[HSO + r1*68 + (cc>>1)] = pkbf((x2r[f][2]-mu1)*rs1*gv.x + ev.x,
                                      (x2r[f][3]-mu1)*rs1*gv.y + ev.y);
    }
    for (int idx = tid; idx < 8192; idx += THREADS){
      int n = idx & 127, k2 = idx >> 7;
      u[WQO + n*68 + k2] = pkbf(W1[(2*k2)*DF + n], W1[(2*k2+1)*DF + n]);
    }
    for (int idx = tid; idx < 8192; idx += THREADS){
      int n = idx & 127, k2 = idx >> 7;
      u[WQO + 8704 + n*68 + k2] = pkbf(W2[(2*k2)*DM + n], W2[(2*k2+1)*DM + n]);
    }
  }
  __syncthreads();

  // ---------------- FFN: 4 chunks of 128 ----------------
  float dacc[8][4];
  #pragma unroll
  for (int f = 0; f < 8; f++)
    #pragma unroll
    for (int j = 0; j < 4; j++) dacc[f][j] = 0.f;

  const int pairid = 9 + wl;   // ids 9..15 + ... (64-thread bars, ids distinct from group bars)

  for (int cb = 0; cb < 4; cb++){
    {
      float uacc[8][4];
      #pragma unroll
      for (int f = 0; f < 8; f++)
        #pragma unroll
        for (int j = 0; j < 4; j++) uacc[f][j] = 0.f;

      uint32_t aB = sb + 4u*(HSO + (uint32_t)(mrow + aRow)*68 + aCoff);
      #pragma unroll
      for (int ks = 0; ks < 8; ks++){
        uint32_t a0,a1,a2,a3;
        ldsm4(aB + ks*32, a0,a1,a2,a3);
        #pragma unroll
        for (int p = 0; p < 4; p++){
          uint32_t b0,b1,b2,b3;
          uint32_t bP = sb + 4u*(WQO + (uint32_t)(nhalf*64 + p*16 + bpR)*68 + bpK);
          ldsm4(bP + ks*32, b0,b1,b2,b3);
          mma16(uacc[2*p],   a0,a1,a2,a3, b0,b1);
          mma16(uacc[2*p+1], a0,a1,a2,a3, b2,b3);
        }
      }
      int r0 = mrow + qr, r1 = r0 + 8;
      #pragma unroll
      for (int f = 0; f < 8; f++){
        int cc = nhalf*64 + f*8 + 2*qc;
        float2 bv = *(const float2*)&b1[cb*128 + cc];
        u[POO + r0*68 + (cc>>1)] = pkbf(fmaxf(uacc[f][0] + bv.x, 0.f),
                                        fmaxf(uacc[f][1] + bv.y, 0.f));
        u[POO + r1*68 + (cc>>1)] = pkbf(fmaxf(uacc[f][2] + bv.x, 0.f),
                                        fmaxf(uacc[f][3] + bv.y, 0.f));
      }
    }
    PAIRBAR(pairid - 8 + (wl & 7));   // 64-thread pair bar: warps wl and wl+8
    {
      uint32_t aB = sb + 4u*(POO + (uint32_t)(mrow + aRow)*68 + aCoff);
      #pragma unroll
      for (int ks = 0; ks < 8; ks++){
        uint32_t a0,a1,a2,a3;
        ldsm4(aB + ks*32, a0,a1,a2,a3);
        #pragma unroll
        for (int p = 0; p < 4; p++){
          uint32_t b0,b1,b2,b3;
          uint32_t bP = sb + 4u*(WQO + 8704 + (uint32_t)(nhalf*64 + p*16 + bpR)*68 + bpK);
          ldsm4(bP + ks*32, b0,b1,b2,b3);
          mma16(dacc[2*p],   a0,a1,a2,a3, b0,b1);
          mma16(dacc[2*p+1], a0,a1,a2,a3, b2,b3);
        }
      }
    }
    __syncthreads();

    if (cb < 3){
      for (int idx = tid; idx < 8192; idx += THREADS){
        int n = idx & 127, k2 = idx >> 7;
        u[WQO + n*68 + k2] = pkbf(W1[(2*k2)*DF + (cb+1)*128 + n],
                                  W1[(2*k2+1)*DF + (cb+1)*128 + n]);
      }
      for (int idx = tid; idx < 8192; idx += THREADS){
        int n = idx & 127, k2 = idx >> 7;
        u[WQO + 8704 + n*68 + k2] = pkbf(W2[((cb+1)*128 + 2*k2)*DM + n],
                                         W2[((cb+1)*128 + 2*k2+1)*DM + n]);
      }
      __syncthreads();
    }
  }

  // ---------------- epilogue: out = x2 + D2 + b2 ----------------
  {
    int r0 = mrow + qr, r1 = r0 + 8;
    #pragma unroll
    for (int f = 0; f < 8; f++){
      int cc = nhalf*64 + f*8 + 2*qc;
      float2 bv = *(const float2*)&b2[cc];
      float2 o0 = make_float2(x2r[f][0] + dacc[f][0] + bv.x,
                              x2r[f][1] + dacc[f][1] + bv.y);
      float2 o1 = make_float2(x2r[f][2] + dacc[f][2] + bv.x,
                              x2r[f][3] + dacc[f][3] + bv.y);
      *(float2*)&ob[r0*DM + cc] = o0;
      *(float2*)&ob[r1*DM + cc] = o1;
    }
  }
}

extern "C" void kernel_launch(void* const* d_in, const int* in_sizes, int n_in,
                              void* d_out, int out_size)
{
  (void)in_sizes; (void)n_in; (void)out_size;
  cudaFuncSetAttribute(decoder_block_kernel,
                       cudaFuncAttributeMaxDynamicSharedMemorySize,
                       SMEM_U32 * 4);
  decoder_block_kernel<<<NB, THREADS, SMEM_U32 * 4>>>(
      (const float*)d_in[0],  (const float*)d_in[1],  (const float*)d_in[2],
      (const float*)d_in[3],  (const float*)d_in[4],  (const float*)d_in[5],
      (const float*)d_in[6],  (const float*)d_in[7],  (const float*)d_in[8],
      (const float*)d_in[9],  (const float*)d_in[10], (const float*)d_in[11],
      (const float*)d_in[12], (const float*)d_in[13],
      (float*)d_out);
}

// round 14
// speedup vs baseline: 7.0229x; 1.7484x over previous
#include <cuda_runtime.h>
#include <cstdint>

// Fused transformer decoder block. Two kernels:
//  1) prep: pack all weights to bf16x2 in ldsm-ready layouts in global scratch.
//  2) main: one CTA per batch element, 512 threads; all GEMMs mma.sync
//     m16n8k16 bf16 + ldmatrix; ALL weight staging via cp.async (pipelined).
// B=512, T=128, D=128, H=6, Dh=21, DF=512.

#define NB 512
#define TT 128
#define DM 128
#define NH 6
#define DF 512
#define EPSF 1e-5f
#define SCALE 0.21821789023599236f   // 1/sqrt(21)
#define THREADS 512

// global scratch offsets (u32)
#define GQKV 0                 // 3 pairs x [144][68]
#define GWOT 29376             // [128][76]
#define GW1  39104             // 4 chunks x [128][68]
#define GW2  73920             // 4 chunks x [128][68]
#define GTOT 108736
__device__ __align__(16) uint32_t g_wscratch[GTOT];

__device__ __forceinline__ uint32_t pkbf(float lo, float hi){
  uint32_t r; asm("cvt.rn.bf16x2.f32 %0, %1, %2;" : "=r"(r) : "f"(hi), "f"(lo));
  return r;
}
__device__ __forceinline__ void mma16(float* d, uint32_t a0, uint32_t a1,
                                      uint32_t a2, uint32_t a3,
                                      uint32_t b0, uint32_t b1){
  asm volatile("mma.sync.aligned.m16n8k16.row.col.f32.bf16.bf16.f32 "
    "{%0,%1,%2,%3},{%4,%5,%6,%7},{%8,%9},{%0,%1,%2,%3};"
    : "+f"(d[0]), "+f"(d[1]), "+f"(d[2]), "+f"(d[3])
    : "r"(a0), "r"(a1), "r"(a2), "r"(a3), "r"(b0), "r"(b1));
}
__device__ __forceinline__ void ldsm4(uint32_t addr, uint32_t& a0, uint32_t& a1,
                                      uint32_t& a2, uint32_t& a3){
  asm volatile("ldmatrix.sync.aligned.m8n8.x4.shared.b16 {%0,%1,%2,%3},[%4];"
    : "=r"(a0),"=r"(a1),"=r"(a2),"=r"(a3) : "r"(addr));
}
__device__ __forceinline__ void ldsm2(uint32_t addr, uint32_t& b0, uint32_t& b1){
  asm volatile("ldmatrix.sync.aligned.m8n8.x2.shared.b16 {%0,%1},[%2];"
    : "=r"(b0),"=r"(b1) : "r"(addr));
}
__device__ __forceinline__ uint32_t smem_u32_of(const void* p){
  uint32_t a;
  asm("{ .reg .u64 t; cvta.to.shared.u64 t, %1; cvt.u32.u64 %0, t; }" : "=r"(a) : "l"(p));
  return a;
}
__device__ __forceinline__ void cpa16(uint32_t sdst, const uint32_t* gsrc){
  asm volatile("cp.async.cg.shared.global [%0],[%1],16;" :: "r"(sdst), "l"(gsrc));
}
__device__ __forceinline__ void cpcopy(uint32_t sdst, const uint32_t* gsrc,
                                       int nchunks, int tid){
  for (int i = tid; i < nchunks; i += THREADS)
    cpa16(sdst + 16u*(uint32_t)i, gsrc + 4*i);
}
#define CPA_COMMIT()  asm volatile("cp.async.commit_group;" ::: "memory")
#define CPA_WAIT0()   asm volatile("cp.async.wait_group 0;" ::: "memory")
#define CPA_WAIT1()   asm volatile("cp.async.wait_group 1;" ::: "memory")
#define GROUPBAR(g) asm volatile("bar.sync %0, 256;" :: "r"(1 + (g)) : "memory")

// ================= prep kernel =================
extern "C" __global__ void prep_weights(const float* __restrict__ Wq,
                                        const float* __restrict__ Wk,
                                        const float* __restrict__ Wv,
                                        const float* __restrict__ Wo,
                                        const float* __restrict__ W1,
                                        const float* __restrict__ W2)
{
  int tid = blockIdx.x*blockDim.x + threadIdx.x;
  int NT  = gridDim.x*blockDim.x;
  // qkv pairs: 3 x [144][68]
  for (int idx = tid; idx < 3*144*68; idx += NT){
    int p = idx / (144*68), rem = idx - p*(144*68);
    int nn = rem / 68, k2 = rem - nn*68;
    uint32_t val = 0u;
    if (k2 < 64){
      int hh = p*2 + (nn >= 72 ? 1 : 0);
      int n0 = (nn >= 72) ? nn - 72 : nn;
      const float* Wsrc = 0; int col = 0;
      if (n0 < 21)                  { Wsrc = Wq + hh*2688; col = n0; }
      else if (n0 >= 24 && n0 < 45) { Wsrc = Wk + hh*2688; col = n0 - 24; }
      else if (n0 >= 48 && n0 < 69) { Wsrc = Wv + hh*2688; col = n0 - 48; }
      if (Wsrc) val = pkbf(Wsrc[(2*k2)*21 + col], Wsrc[(2*k2+1)*21 + col]);
    }
    g_wscratch[GQKV + p*9792 + nn*68 + k2] = val;
  }
  // WoT: [128][76]
  for (int idx = tid; idx < 128*76; idx += NT){
    int n = idx / 76, k2 = idx - n*76;
    uint32_t val = 0u;
    if (k2 < 72){
      int head = k2 / 12, within = k2 - head*12;
      int e0 = 2*within;
      float lo = (e0     < 21) ? Wo[(head*21 + e0    )*DM + n] : 0.f;
      float hi = (e0 + 1 < 21) ? Wo[(head*21 + e0 + 1)*DM + n] : 0.f;
      val = pkbf(lo, hi);
    }
    g_wscratch[GWOT + idx] = val;
  }
  // W1 chunks: 4 x [128][68]
  for (int idx = tid; idx < 4*128*68; idx += NT){
    int c = idx / (128*68), rem = idx - c*(128*68);
    int n = rem / 68, k2 = rem - n*68;
    uint32_t val = 0u;
    if (k2 < 64)
      val = pkbf(W1[(2*k2)*DF + c*128 + n], W1[(2*k2+1)*DF + c*128 + n]);
    g_wscratch[GW1 + c*8704 + n*68 + k2] = val;
  }
  // W2 chunks: 4 x [128][68]
  for (int idx = tid; idx < 4*128*68; idx += NT){
    int c = idx / (128*68), rem = idx - c*(128*68);
    int n = rem / 68, k2 = rem - n*68;
    uint32_t val = 0u;
    if (k2 < 64)
      val = pkbf(W2[(c*128 + 2*k2)*DM + n], W2[(c*128 + 2*k2+1)*DM + n]);
    g_wscratch[GW2 + c*8704 + n*68 + k2] = val;
  }
}

// ================= main kernel =================
// smem layout (u32):
//  HS 0(8704) | STAT 8704(512) | BUF0 9216(9792) | BUF1 19008(9792) |
//  OALL 28800(9728) | KS0 38528 KS1 41088 | VT0 43648 VT1 45280 | U 46912(8704)
//  FFN overlays: w1A@9216 w1B@19008 w2A@28800 w2B@37504; WoT@19008 (fold)
#define HSO   0
#define STATO 8704
#define BUF0O 9216
#define BUF1O 19008
#define OALLO 28800
#define KS0O  38528
#define KS1O  41088
#define VT0O  43648
#define VT1O  45280
#define UO    46912
#define WOTO  19008
#define SMEM_U32 55616   // 222464 bytes

extern "C" __global__ void __launch_bounds__(THREADS, 1)
decoder_block_kernel(const float* __restrict__ gx,
                     const float* __restrict__ bo,
                     const float* __restrict__ b1,
                     const float* __restrict__ b2,
                     const float* __restrict__ g1,
                     const float* __restrict__ be1,
                     const float* __restrict__ g2,
                     const float* __restrict__ be2,
                     float* __restrict__ gout)
{
  extern __shared__ float sm[];
  uint32_t* u = (uint32_t*)sm;

  const int tid   = threadIdx.x;
  const int lane  = tid & 31;
  const int w     = tid >> 5;
  const int b     = blockIdx.x;
  const int qr    = lane >> 2;
  const int qc    = lane & 3;
  const int gid   = w >> 3;
  const int wl    = w & 7;
  const int mrow  = wl * 16;
  const int nhalf = gid;

  const int aRow  = (lane & 7) + 8*((lane >> 3) & 1);
  const int aCoff = 4*(lane >> 4);
  const int bRow  = lane & 7;
  const int bCoff = 4*((lane >> 3) & 1);
  const int bpR   = (lane & 7) + ((lane >> 4) << 3);
  const int bpK   = ((lane >> 3) & 1) * 4;

  const uint32_t sb = smem_u32_of(sm);
  float* st = (float*)&u[STATO];

  const uint32_t ksb = gid ? KS1O : KS0O;
  const uint32_t vtb = gid ? VT1O : VT0O;

  const float* xb = gx   + (size_t)b * (TT * DM);
  float*       ob = gout + (size_t)b * (TT * DM);

  // ---------------- init: issue pair-0 copy, KS pads, LN1 ----------------
  {
    cpcopy(sb + 4u*BUF0O, g_wscratch + GQKV, 2448, tid);
    CPA_COMMIT();

    for (int idx = tid; idx < 2048; idx += THREADS){
      int r = idx >> 3, j = idx & 7;
      uint32_t base = (j < 4) ? KS0O : KS1O;
      u[base + r*20 + 12 + (j & 3)] = 0u;
    }
    float2 ga = *(const float2*)&g1[2*lane];
    float2 gb = *(const float2*)&g1[64 + 2*lane];
    float2 ea = *(const float2*)&be1[2*lane];
    float2 eb = *(const float2*)&be1[64 + 2*lane];
    for (int r = w; r < TT; r += 16){
      float2 xa = *(const float2*)&xb[r*DM + 2*lane];
      float2 xc = *(const float2*)&xb[r*DM + 64 + 2*lane];
      float s  = xa.x + xa.y + xc.x + xc.y;
      float s2 = xa.x*xa.x + xa.y*xa.y + xc.x*xc.x + xc.y*xc.y;
      #pragma unroll
      for (int o = 16; o > 0; o >>= 1){
        s  += __shfl_xor_sync(0xffffffffu, s, o);
        s2 += __shfl_xor_sync(0xffffffffu, s2, o);
      }
      float mu = s * (1.f/DM);
      float rs = rsqrtf(s2 * (1.f/DM) - mu*mu + EPSF);
      u[HSO + r*68 + lane]      = pkbf((xa.x - mu)*rs*ga.x + ea.x,
                                       (xa.y - mu)*rs*ga.y + ea.y);
      u[HSO + r*68 + 32 + lane] = pkbf((xc.x - mu)*rs*gb.x + eb.x,
                                       (xc.y - mu)*rs*gb.y + eb.y);
    }
    CPA_WAIT0();
  }
  __syncthreads();

  // ---------------- attention: 3 head pairs ----------------
  for (int pr = 0; pr < 3; pr++){
    const int hh = pr*2 + gid;
    const uint32_t wbuf = (pr & 1) ? BUF1O : BUF0O;
    const uint32_t wrow = (uint32_t)gid * 72u;

    // prefetch next pair (or WoT) — overlaps this whole phase
    if (pr < 2)
      cpcopy(sb + 4u*((pr & 1) ? BUF0O : BUF1O),
             g_wscratch + GQKV + (pr+1)*9792, 2448, tid);
    else
      cpcopy(sb + 4u*WOTO, g_wscratch + GWOT, 2432, tid);
    CPA_COMMIT();

    // -- QKV GEMM: 16 rows x 72 cols --
    float qacc[9][4];
    #pragma unroll
    for (int f = 0; f < 9; f++)
      #pragma unroll
      for (int j = 0; j < 4; j++) qacc[f][j] = 0.f;
    {
      uint32_t aB = sb + 4u*(HSO + (uint32_t)(mrow + aRow)*68 + aCoff);
      uint32_t bP[4], b8;
      #pragma unroll
      for (int p = 0; p < 4; p++)
        bP[p] = sb + 4u*(wbuf + (wrow + p*16 + bpR)*68 + bpK);
      b8 = sb + 4u*(wbuf + (wrow + 64 + bRow)*68 + bCoff);
      #pragma unroll
      for (int ks = 0; ks < 8; ks++){
        uint32_t a0,a1,a2,a3, b0,b1,b2,b3;
        ldsm4(aB + ks*32, a0,a1,a2,a3);
        #pragma unroll
        for (int p = 0; p < 4; p++){
          ldsm4(bP[p] + ks*32, b0,b1,b2,b3);
          mma16(qacc[2*p],   a0,a1,a2,a3, b0,b1);
          mma16(qacc[2*p+1], a0,a1,a2,a3, b2,b3);
        }
        ldsm2(b8 + ks*32, b0,b1);
        mma16(qacc[8], a0,a1,a2,a3, b0,b1);
      }
    }

    // -- repack: q->regs, k->KS, v->VT --
    uint32_t aq[2][4];
    aq[0][0] = pkbf(qacc[0][0]*SCALE, qacc[0][1]*SCALE);
    aq[0][1] = pkbf(qacc[0][2]*SCALE, qacc[0][3]*SCALE);
    aq[0][2] = pkbf(qacc[1][0]*SCALE, qacc[1][1]*SCALE);
    aq[0][3] = pkbf(qacc[1][2]*SCALE, qacc[1][3]*SCALE);
    aq[1][0] = pkbf(qacc[2][0]*SCALE, qacc[2][1]*SCALE);
    aq[1][1] = pkbf(qacc[2][2]*SCALE, qacc[2][3]*SCALE);
    aq[1][2] = 0u; aq[1][3] = 0u;
    #pragma unroll
    for (int f = 0; f < 3; f++){
      int e2 = (f*8 + 2*qc) >> 1;
      u[ksb + (mrow+qr)*20 + e2]   = pkbf(qacc[3+f][0], qacc[3+f][1]);
      u[ksb + (mrow+qr+8)*20 + e2] = pkbf(qacc[3+f][2], qacc[3+f][3]);
    }
    #pragma unroll
    for (int f = 0; f < 3; f++){
      int e0 = f*8 + 2*qc;
      #pragma unroll
      for (int h = 0; h < 2; h++){
        float v0 = qacc[6+f][2*h], v1 = qacc[6+f][2*h+1];
        float p0 = __shfl_xor_sync(0xffffffffu, v0, 4);
        float p1 = __shfl_xor_sync(0xffffffffu, v1, 4);
        if (!(qr & 1)){
          int t2 = (mrow + qr + 8*h) >> 1;
          u[vtb + e0*68 + t2]     = pkbf(v0, p0);
          u[vtb + (e0+1)*68 + t2] = pkbf(v1, p1);
        }
      }
    }
    GROUPBAR(gid);

    // -- S GEMM --
    float sacc[16][4];
    #pragma unroll
    for (int f = 0; f < 16; f++)
      #pragma unroll
      for (int j = 0; j < 4; j++) sacc[f][j] = 0.f;
    #pragma unroll
    for (int kg = 0; kg < 2; kg++){
      #pragma unroll
      for (int p = 0; p < 8; p++){
        uint32_t b0,b1,b2,b3;
        uint32_t bP = sb + 4u*(ksb + (uint32_t)(p*16 + bpR)*20 + kg*8 + bpK);
        ldsm4(bP, b0,b1,b2,b3);
        mma16(sacc[2*p],   aq[kg][0],aq[kg][1],aq[kg][2],aq[kg][3], b0,b1);
        mma16(sacc[2*p+1], aq[kg][0],aq[kg][1],aq[kg][2],aq[kg][3], b2,b3);
      }
    }

    // -- warp-local masked softmax + repack P --
    uint32_t pa[8][4];
    {
      int r0 = mrow + qr, r1 = r0 + 8;
      float mx0 = -1e30f, mx1 = -1e30f;
      #pragma unroll
      for (int f = 0; f < 16; f++){
        int c0 = f*8 + 2*qc;
        if (c0     > r0) sacc[f][0] = -1e30f;
        if (c0 + 1 > r0) sacc[f][1] = -1e30f;
        if (c0     > r1) sacc[f][2] = -1e30f;
        if (c0 + 1 > r1) sacc[f][3] = -1e30f;
        mx0 = fmaxf(mx0, fmaxf(sacc[f][0], sacc[f][1]));
        mx1 = fmaxf(mx1, fmaxf(sacc[f][2], sacc[f][3]));
      }
      mx0 = fmaxf(mx0, __shfl_xor_sync(0xffffffffu, mx0, 1));
      mx0 = fmaxf(mx0, __shfl_xor_sync(0xffffffffu, mx0, 2));
      mx1 = fmaxf(mx1, __shfl_xor_sync(0xffffffffu, mx1, 1));
      mx1 = fmaxf(mx1, __shfl_xor_sync(0xffffffffu, mx1, 2));
      float s0 = 0.f, s1 = 0.f;
      #pragma unroll
      for (int f = 0; f < 16; f++){
        sacc[f][0] = __expf(sacc[f][0] - mx0);
        sacc[f][1] = __expf(sacc[f][1] - mx0);
        sacc[f][2] = __expf(sacc[f][2] - mx1);
        sacc[f][3] = __expf(sacc[f][3] - mx1);
        s0 += sacc[f][0] + sacc[f][1];
        s1 += sacc[f][2] + sacc[f][3];
      }
      s0 += __shfl_xor_sync(0xffffffffu, s0, 1);
      s0 += __shfl_xor_sync(0xffffffffu, s0, 2);
      s1 += __shfl_xor_sync(0xffffffffu, s1, 1);
      s1 += __shfl_xor_sync(0xffffffffu, s1, 2);
      float inv0 = 1.f / s0, inv1 = 1.f / s1;
      #pragma unroll
      for (int g = 0; g < 8; g++){
        pa[g][0] = pkbf(sacc[2*g][0]*inv0,   sacc[2*g][1]*inv0);
        pa[g][1] = pkbf(sacc[2*g][2]*inv1,   sacc[2*g][3]*inv1);
        pa[g][2] = pkbf(sacc[2*g+1][0]*inv0, sacc[2*g+1][1]*inv0);
        pa[g][3] = pkbf(sacc[2*g+1][2]*inv1, sacc[2*g+1][3]*inv1);
      }
    }

    // -- O GEMM -> O_all --
    {
      float oacc[3][4];
      #pragma unroll
      for (int f = 0; f < 3; f++)
        #pragma unroll
        for (int j = 0; j < 4; j++) oacc[f][j] = 0.f;
      #pragma unroll
      for (int kg = 0; kg < 8; kg++){
        uint32_t b0,b1,b2,b3;
        uint32_t bP = sb + 4u*(vtb + (uint32_t)bpR*68 + kg*8 + bpK);
        ldsm4(bP, b0,b1,b2,b3);
        mma16(oacc[0], pa[kg][0],pa[kg][1],pa[kg][2],pa[kg][3], b0,b1);
        mma16(oacc[1], pa[kg][0],pa[kg][1],pa[kg][2],pa[kg][3], b2,b3);
        uint32_t bQ = sb + 4u*(vtb + (uint32_t)(16 + bRow)*68 + kg*8 + bCoff);
        ldsm2(bQ, b0,b1);
        mma16(oacc[2], pa[kg][0],pa[kg][1],pa[kg][2],pa[kg][3], b0,b1);
      }
      #pragma unroll
      for (int f = 0; f < 3; f++){
        int uc = hh*12 + f*4 + qc;
        u[OALLO + (mrow+qr)*76 + uc]   = pkbf(oacc[f][0], oacc[f][1]);
        u[OALLO + (mrow+qr+8)*76 + uc] = pkbf(oacc[f][2], oacc[f][3]);
      }
    }
    CPA_WAIT0();
    __syncthreads();
  }

  // ---------------- fold (K=144): issue w1c0 prefetch, GEMM, stats ----------------
  float x2r[8][4];
  {
    cpcopy(sb + 4u*BUF0O, g_wscratch + GW1, 2176, tid);   // w1 chunk 0 -> w1A
    CPA_COMMIT();

    #pragma unroll
    for (int f = 0; f < 8; f++)
      #pragma unroll
      for (int j = 0; j < 4; j++) x2r[f][j] = 0.f;

    uint32_t aB = sb + 4u*(OALLO + (uint32_t)(mrow + aRow)*76 + aCoff);
    #pragma unroll
    for (int ks = 0; ks < 9; ks++){
      uint32_t a0,a1,a2,a3;
      ldsm4(aB + ks*32, a0,a1,a2,a3);
      #pragma unroll
      for (int p = 0; p < 4; p++){
        uint32_t b0,b1,b2,b3;
        uint32_t bP = sb + 4u*(WOTO + (uint32_t)(nhalf*64 + p*16 + bpR)*76 + bpK);
        ldsm4(bP + ks*32, b0,b1,b2,b3);
        mma16(x2r[2*p],   a0,a1,a2,a3, b0,b1);
        mma16(x2r[2*p+1], a0,a1,a2,a3, b2,b3);
      }
    }
    int r0 = mrow + qr, r1 = r0 + 8;
    float s0 = 0.f, q0 = 0.f, s1 = 0.f, q1 = 0.f;
    #pragma unroll
    for (int f = 0; f < 8; f++){
      int cc = nhalf*64 + f*8 + 2*qc;
      float2 bv = *(const float2*)&bo[cc];
      float2 xa = *(const float2*)&xb[r0*DM + cc];
      float2 xc = *(const float2*)&xb[r1*DM + cc];
      x2r[f][0] += xa.x + bv.x;  x2r[f][1] += xa.y + bv.y;
      x2r[f][2] += xc.x + bv.x;  x2r[f][3] += xc.y + bv.y;
      s0 += x2r[f][0] + x2r[f][1];
      q0 += x2r[f][0]*x2r[f][0] + x2r[f][1]*x2r[f][1];
      s1 += x2r[f][2] + x2r[f][3];
      q1 += x2r[f][2]*x2r[f][2] + x2r[f][3]*x2r[f][3];
    }
    s0 += __shfl_xor_sync(0xffffffffu, s0, 1); s0 += __shfl_xor_sync(0xffffffffu, s0, 2);
    q0 += __shfl_xor_sync(0xffffffffu, q0, 1); q0 += __shfl_xor_sync(0xffffffffu, q0, 2);
    s1 += __shfl_xor_sync(0xffffffffu, s1, 1); s1 += __shfl_xor_sync(0xffffffffu, s1, 2);
    q1 += __shfl_xor_sync(0xffffffffu, q1, 1); q1 += __shfl_xor_sync(0xffffffffu, q1, 2);
    if (qc == 0){
      st[nhalf*128 + r0] = s0;        st[nhalf*128 + r1] = s1;
      st[256 + nhalf*128 + r0] = q0;  st[256 + nhalf*128 + r1] = q1;
    }
  }
  __syncthreads();   // stats visible; all warps done with WoT/OALL

  // issue group B: w2 chunk 0 -> w2A, w1 chunk 1 -> w1B (overlaps LN2 + U0)
  cpcopy(sb + 4u*OALLO, g_wscratch + GW2, 2176, tid);
  cpcopy(sb + 4u*BUF1O, g_wscratch + GW1 + 8704, 2176, tid);
  CPA_COMMIT();

  // ---------------- LN2 finalize -> HS ----------------
  {
    int r0 = mrow + qr, r1 = r0 + 8;
    float S0 = st[r0] + st[128 + r0], Q0 = st[256 + r0] + st[384 + r0];
    float S1 = st[r1] + st[128 + r1], Q1 = st[256 + r1] + st[384 + r1];
    float mu0 = S0 * (1.f/DM), rs0 = rsqrtf(Q0*(1.f/DM) - mu0*mu0 + EPSF);
    float mu1 = S1 * (1.f/DM), rs1 = rsqrtf(Q1*(1.f/DM) - mu1*mu1 + EPSF);
    #pragma unroll
    for (int f = 0; f < 8; f++){
      int cc = nhalf*64 + f*8 + 2*qc;
      float2 gv = *(const float2*)&g2[cc];
      float2 ev = *(const float2*)&be2[cc];
      u[HSO + r0*68 + (cc>>1)] = pkbf((x2r[f][0]-mu0)*rs0*gv.x + ev.x,
                                      (x2r[f][1]-mu0)*rs0*gv.y + ev.y);
      u[HSO + r1*68 + (cc>>1)] = pkbf((x2r[f][2]-mu1)*rs1*gv.x + ev.x,
                                      (x2r[f][3]-mu1)*rs1*gv.y + ev.y);
    }
  }
  CPA_WAIT1();        // w1 chunk 0 ready (group B still in flight)
  __syncthreads();

  // ---------------- FFN: 4 chunks, cp.async double-buffered ----------------
  float dacc[8][4];
  #pragma unroll
  for (int f = 0; f < 8; f++)
    #pragma unroll
    for (int j = 0; j < 4; j++) dacc[f][j] = 0.f;

  const uint32_t w1s[2] = { BUF0O, BUF1O };
  const uint32_t w2s[2] = { OALLO, 37504u };

  for (int cb = 0; cb < 4; cb++){
    // U GEMM cb
    {
      float uacc[8][4];
      #pragma unroll
      for (int f = 0; f < 8; f++)
        #pragma unroll
        for (int j = 0; j < 4; j++) uacc[f][j] = 0.f;

      uint32_t aB = sb + 4u*(HSO + (uint32_t)(mrow + aRow)*68 + aCoff);
      #pragma unroll
      for (int ks = 0; ks < 8; ks++){
        uint32_t a0,a1,a2,a3;
        ldsm4(aB + ks*32, a0,a1,a2,a3);
        #pragma unroll
        for (int p = 0; p < 4; p++){
          uint32_t b0,b1,b2,b3;
          uint32_t bP = sb + 4u*(w1s[cb & 1] + (uint32_t)(nhalf*64 + p*16 + bpR)*68 + bpK);
          ldsm4(bP + ks*32, b0,b1,b2,b3);
          mma16(uacc[2*p],   a0,a1,a2,a3, b0,b1);
          mma16(uacc[2*p+1], a0,a1,a2,a3, b2,b3);
        }
      }
      int r0 = mrow + qr, r1 = r0 + 8;
      #pragma unroll
      for (int f = 0; f < 8; f++){
        int cc = nhalf*64 + f*8 + 2*qc;
        float2 bv = *(const float2*)&b1[cb*128 + cc];
        u[UO + r0*68 + (cc>>1)] = pkbf(fmaxf(uacc[f][0] + bv.x, 0.f),
                                       fmaxf(uacc[f][1] + bv.y, 0.f));
        u[UO + r1*68 + (cc>>1)] = pkbf(fmaxf(uacc[f][2] + bv.x, 0.f),
                                       fmaxf(uacc[f][3] + bv.y, 0.f));
      }
    }
    __syncthreads();    // U visible; w1 slot (cb&1) free

    // issue next weights: w2 c(cb+1), w1 c(cb+2) (overlap D2 + next U)
    if (cb < 3){
      cpcopy(sb + 4u*w2s[(cb+1) & 1], g_wscratch + GW2 + (cb+1)*8704, 2176, tid);
      if (cb < 2)
        cpcopy(sb + 4u*w1s[cb & 1], g_wscratch + GW1 + (cb+2)*8704, 2176, tid);
      CPA_COMMIT();
      CPA_WAIT1();      // w2 c_cb ready (newest group stays in flight)
    } else {
      CPA_WAIT0();      // last w2 ready
    }
    __syncthreads();

    // D2 GEMM cb
    {
      uint32_t aB = sb + 4u*(UO + (uint32_t)(mrow + aRow)*68 + aCoff);
      #pragma unroll
      for (int ks = 0; ks < 8; ks++){
        uint32_t a0,a1,a2,a3;
        ldsm4(aB + ks*32, a0,a1,a2,a3);
        #pragma unroll
        for (int p = 0; p < 4; p++){
          uint32_t b0,b1,b2,b3;
          uint32_t bP = sb + 4u*(w2s[cb & 1] + (uint32_t)(nhalf*64 + p*16 + bpR)*68 + bpK);
          ldsm4(bP + ks*32, b0,b1,b2,b3);
          mma16(dacc[2*p],   a0,a1,a2,a3, b0,b1);
          mma16(dacc[2*p+1], a0,a1,a2,a3, b2,b3);
        }
      }
    }
    __syncthreads();    // U buffer reusable next iter
  }

  // ---------------- epilogue: out = x2 + D2 + b2 ----------------
  {
    int r0 = mrow + qr, r1 = r0 + 8;
    #pragma unroll
    for (int f = 0; f < 8; f++){
      int cc = nhalf*64 + f*8 + 2*qc;
      float2 bv = *(const float2*)&b2[cc];
      float2 o0 = make_float2(x2r[f][0] + dacc[f][0] + bv.x,
                              x2r[f][1] + dacc[f][1] + bv.y);
      float2 o1 = make_float2(x2r[f][2] + dacc[f][2] + bv.x,
                              x2r[f][3] + dacc[f][3] + bv.y);
      *(float2*)&ob[r0*DM + cc] = o0;
      *(float2*)&ob[r1*DM + cc] = o1;
    }
  }
}

extern "C" void kernel_launch(void* const* d_in, const int* in_sizes, int n_in,
                              void* d_out, int out_size)
{
  (void)in_sizes; (void)n_in; (void)out_size;
  prep_weights<<<128, 256>>>(
      (const float*)d_in[1], (const float*)d_in[2], (const float*)d_in[3],
      (const float*)d_in[4], (const float*)d_in[6], (const float*)d_in[8]);
  cudaFuncSetAttribute(decoder_block_kernel,
                       cudaFuncAttributeMaxDynamicSharedMemorySize,
                       SMEM_U32 * 4);
  decoder_block_kernel<<<NB, THREADS, SMEM_U32 * 4>>>(
      (const float*)d_in[0],  (const float*)d_in[5],  (const float*)d_in[7],
      (const float*)d_in[9],  (const float*)d_in[10], (const float*)d_in[11],
      (const float*)d_in[12], (const float*)d_in[13],
      (float*)d_out);
}

// round 15
// speedup vs baseline: 7.1297x; 1.0152x over previous
#include <cuda_runtime.h>
#include <cstdint>

// Fused transformer decoder block. prep kernel packs weights bf16x2; main
// kernel: 1 CTA/batch, 512 threads, mma.sync m16n8k16 bf16 + ldmatrix,
// cp.async pipelined GROUP-PRIVATE weight staging, scoped barriers
// (group bars in attention, pair bars in FFN). B=512,T=128,D=128,H=6,Dh=21.

#define NB 512
#define TT 128
#define DM 128
#define NH 6
#define DF 512
#define EPSF 1e-5f
#define SCALE 0.21821789023599236f
#define THREADS 512

// global scratch offsets (u32)
#define GQKV 0                 // 3 pairs x [144][68]
#define GWOT 29376             // [128][76]
#define GW1  39104             // 4 chunks x [128][68]
#define GW2  73920             // 4 chunks x [128][68]
#define GTOT 108736
__device__ __align__(16) uint32_t g_wscratch[GTOT];

__device__ __forceinline__ uint32_t pkbf(float lo, float hi){
  uint32_t r; asm("cvt.rn.bf16x2.f32 %0, %1, %2;" : "=r"(r) : "f"(hi), "f"(lo));
  return r;
}
__device__ __forceinline__ void mma16(float* d, uint32_t a0, uint32_t a1,
                                      uint32_t a2, uint32_t a3,
                                      uint32_t b0, uint32_t b1){
  asm volatile("mma.sync.aligned.m16n8k16.row.col.f32.bf16.bf16.f32 "
    "{%0,%1,%2,%3},{%4,%5,%6,%7},{%8,%9},{%0,%1,%2,%3};"
    : "+f"(d[0]), "+f"(d[1]), "+f"(d[2]), "+f"(d[3])
    : "r"(a0), "r"(a1), "r"(a2), "r"(a3), "r"(b0), "r"(b1));
}
__device__ __forceinline__ void ldsm4(uint32_t addr, uint32_t& a0, uint32_t& a1,
                                      uint32_t& a2, uint32_t& a3){
  asm volatile("ldmatrix.sync.aligned.m8n8.x4.shared.b16 {%0,%1,%2,%3},[%4];"
    : "=r"(a0),"=r"(a1),"=r"(a2),"=r"(a3) : "r"(addr));
}
__device__ __forceinline__ void ldsm2(uint32_t addr, uint32_t& b0, uint32_t& b1){
  asm volatile("ldmatrix.sync.aligned.m8n8.x2.shared.b16 {%0,%1},[%2];"
    : "=r"(b0),"=r"(b1) : "r"(addr));
}
__device__ __forceinline__ uint32_t smem_u32_of(const void* p){
  uint32_t a;
  asm("{ .reg .u64 t; cvta.to.shared.u64 t, %1; cvt.u32.u64 %0, t; }" : "=r"(a) : "l"(p));
  return a;
}
__device__ __forceinline__ void cpa16(uint32_t sdst, const uint32_t* gsrc){
  asm volatile("cp.async.cg.shared.global [%0],[%1],16;" :: "r"(sdst), "l"(gsrc));
}
// group-scoped copy: 256 threads of one group copy nchunks 16B chunks
__device__ __forceinline__ void cpcopyg(uint32_t sdst, const uint32_t* gsrc,
                                        int nchunks, int gtid){
  for (int i = gtid; i < nchunks; i += 256)
    cpa16(sdst + 16u*(uint32_t)i, gsrc + 4*i);
}
#define CPA_COMMIT()  asm volatile("cp.async.commit_group;" ::: "memory")
#define CPA_WAIT0()   asm volatile("cp.async.wait_group 0;" ::: "memory")
#define CPA_WAIT1()   asm volatile("cp.async.wait_group 1;" ::: "memory")
#define GROUPBAR(g)   asm volatile("bar.sync %0, 256;" :: "r"(1 + (g)) : "memory")
#define PAIRBAR(id)   asm volatile("bar.sync %0, 64;"  :: "r"(3 + (id)) : "memory")

// ================= prep kernel =================
extern "C" __global__ void prep_weights(const float* __restrict__ Wq,
                                        const float* __restrict__ Wk,
                                        const float* __restrict__ Wv,
                                        const float* __restrict__ Wo,
                                        const float* __restrict__ W1,
                                        const float* __restrict__ W2)
{
  int tid = blockIdx.x*blockDim.x + threadIdx.x;
  int NT  = gridDim.x*blockDim.x;
  for (int idx = tid; idx < 3*144*68; idx += NT){
    int p = idx / (144*68), rem = idx - p*(144*68);
    int nn = rem / 68, k2 = rem - nn*68;
    uint32_t val = 0u;
    if (k2 < 64){
      int hh = p*2 + (nn >= 72 ? 1 : 0);
      int n0 = (nn >= 72) ? nn - 72 : nn;
      const float* Wsrc = 0; int col = 0;
      if (n0 < 21)                  { Wsrc = Wq + hh*2688; col = n0; }
      else if (n0 >= 24 && n0 < 45) { Wsrc = Wk + hh*2688; col = n0 - 24; }
      else if (n0 >= 48 && n0 < 69) { Wsrc = Wv + hh*2688; col = n0 - 48; }
      if (Wsrc) val = pkbf(Wsrc[(2*k2)*21 + col], Wsrc[(2*k2+1)*21 + col]);
    }
    g_wscratch[GQKV + p*9792 + nn*68 + k2] = val;
  }
  for (int idx = tid; idx < 128*76; idx += NT){
    int n = idx / 76, k2 = idx - n*76;
    uint32_t val = 0u;
    if (k2 < 72){
      int head = k2 / 12, within = k2 - head*12;
      int e0 = 2*within;
      float lo = (e0     < 21) ? Wo[(head*21 + e0    )*DM + n] : 0.f;
      float hi = (e0 + 1 < 21) ? Wo[(head*21 + e0 + 1)*DM + n] : 0.f;
      val = pkbf(lo, hi);
    }
    g_wscratch[GWOT + idx] = val;
  }
  for (int idx = tid; idx < 4*128*68; idx += NT){
    int c = idx / (128*68), rem = idx - c*(128*68);
    int n = rem / 68, k2 = rem - n*68;
    uint32_t val = 0u;
    if (k2 < 64)
      val = pkbf(W1[(2*k2)*DF + c*128 + n], W1[(2*k2+1)*DF + c*128 + n]);
    g_wscratch[GW1 + c*8704 + n*68 + k2] = val;
  }
  for (int idx = tid; idx < 4*128*68; idx += NT){
    int c = idx / (128*68), rem = idx - c*(128*68);
    int n = rem / 68, k2 = rem - n*68;
    uint32_t val = 0u;
    if (k2 < 64)
      val = pkbf(W2[(c*128 + 2*k2)*DM + n], W2[(c*128 + 2*k2+1)*DM + n]);
    g_wscratch[GW2 + c*8704 + n*68 + k2] = val;
  }
}

// ================= main kernel =================
#define HSO   0
#define STATO 8704
#define BUF0O 9216
#define BUF1O 19008
#define OALLO 28800
#define KS0O  38528
#define KS1O  41088
#define VT0O  43648
#define VT1O  45280
#define UO    46912
#define WOTO  19008
#define SMEM_U32 55616   // 222464 bytes

extern "C" __global__ void __launch_bounds__(THREADS, 1)
decoder_block_kernel(const float* __restrict__ gx,
                     const float* __restrict__ bo,
                     const float* __restrict__ b1,
                     const float* __restrict__ b2,
                     const float* __restrict__ g1,
                     const float* __restrict__ be1,
                     const float* __restrict__ g2,
                     const float* __restrict__ be2,
                     float* __restrict__ gout)
{
  extern __shared__ float sm[];
  uint32_t* u = (uint32_t*)sm;

  const int tid   = threadIdx.x;
  const int lane  = tid & 31;
  const int w     = tid >> 5;
  const int b     = blockIdx.x;
  const int qr    = lane >> 2;
  const int qc    = lane & 3;
  const int gid   = w >> 3;
  const int wl    = w & 7;
  const int gtid  = tid & 255;
  const int mrow  = wl * 16;
  const int nhalf = gid;

  const int aRow  = (lane & 7) + 8*((lane >> 3) & 1);
  const int aCoff = 4*(lane >> 4);
  const int bRow  = lane & 7;
  const int bCoff = 4*((lane >> 3) & 1);
  const int bpR   = (lane & 7) + ((lane >> 4) << 3);
  const int bpK   = ((lane >> 3) & 1) * 4;

  const uint32_t sb = smem_u32_of(sm);
  float* st = (float*)&u[STATO];

  const uint32_t ksb = gid ? KS1O : KS0O;
  const uint32_t vtb = gid ? VT1O : VT0O;

  const float* xb = gx   + (size_t)b * (TT * DM);
  float*       ob = gout + (size_t)b * (TT * DM);

  // ---------------- init: pair-0 copy (group rows), KS pads, LN1 ----------------
  {
    cpcopyg(sb + 4u*(BUF0O + (uint32_t)gid*72u*68u),
            g_wscratch + GQKV + gid*72*68, 1224, gtid);
    CPA_COMMIT();

    for (int idx = tid; idx < 2048; idx += THREADS){
      int r = idx >> 3, j = idx & 7;
      uint32_t base = (j < 4) ? KS0O : KS1O;
      u[base + r*20 + 12 + (j & 3)] = 0u;
    }
    float2 ga = *(const float2*)&g1[2*lane];
    float2 gb = *(const float2*)&g1[64 + 2*lane];
    float2 ea = *(const float2*)&be1[2*lane];
    float2 eb = *(const float2*)&be1[64 + 2*lane];
    for (int r = w; r < TT; r += 16){
      float2 xa = *(const float2*)&xb[r*DM + 2*lane];
      float2 xc = *(const float2*)&xb[r*DM + 64 + 2*lane];
      float s  = xa.x + xa.y + xc.x + xc.y;
      float s2 = xa.x*xa.x + xa.y*xa.y + xc.x*xc.x + xc.y*xc.y;
      #pragma unroll
      for (int o = 16; o > 0; o >>= 1){
        s  += __shfl_xor_sync(0xffffffffu, s, o);
        s2 += __shfl_xor_sync(0xffffffffu, s2, o);
      }
      float mu = s * (1.f/DM);
      float rs = rsqrtf(s2 * (1.f/DM) - mu*mu + EPSF);
      u[HSO + r*68 + lane]      = pkbf((xa.x - mu)*rs*ga.x + ea.x,
                                       (xa.y - mu)*rs*ga.y + ea.y);
      u[HSO + r*68 + 32 + lane] = pkbf((xc.x - mu)*rs*gb.x + eb.x,
                                       (xc.y - mu)*rs*gb.y + eb.y);
    }
    CPA_WAIT0();
  }
  __syncthreads();   // HS (cross-group rows) + pads + staged weights

  // ---------------- attention: 3 head pairs, groups fully decoupled ----------------
  for (int pr = 0; pr < 3; pr++){
    const int hh = pr*2 + gid;
    const uint32_t wbuf = (pr & 1) ? BUF1O : BUF0O;
    const uint32_t wrow = (uint32_t)gid * 72u;

    // prefetch next pair's (or WoT's) GROUP rows — overlaps this phase
    if (pr < 2)
      cpcopyg(sb + 4u*(((pr & 1) ? BUF0O : BUF1O) + wrow*68u),
              g_wscratch + GQKV + (pr+1)*9792 + gid*72*68, 1224, gtid);
    else
      cpcopyg(sb + 4u*(WOTO + (uint32_t)gid*64u*76u),
              g_wscratch + GWOT + gid*64*76, 1216, gtid);
    CPA_COMMIT();

    // -- QKV GEMM: 16 rows x 72 cols --
    float qacc[9][4];
    #pragma unroll
    for (int f = 0; f < 9; f++)
      #pragma unroll
      for (int j = 0; j < 4; j++) qacc[f][j] = 0.f;
    {
      uint32_t aB = sb + 4u*(HSO + (uint32_t)(mrow + aRow)*68 + aCoff);
      uint32_t bP[4], b8;
      #pragma unroll
      for (int p = 0; p < 4; p++)
        bP[p] = sb + 4u*(wbuf + (wrow + p*16 + bpR)*68 + bpK);
      b8 = sb + 4u*(wbuf + (wrow + 64 + bRow)*68 + bCoff);
      #pragma unroll
      for (int ks = 0; ks < 8; ks++){
        uint32_t a0,a1,a2,a3, b0,b1,b2,b3;
        ldsm4(aB + ks*32, a0,a1,a2,a3);
        #pragma unroll
        for (int p = 0; p < 4; p++){
          ldsm4(bP[p] + ks*32, b0,b1,b2,b3);
          mma16(qacc[2*p],   a0,a1,a2,a3, b0,b1);
          mma16(qacc[2*p+1], a0,a1,a2,a3, b2,b3);
        }
        ldsm2(b8 + ks*32, b0,b1);
        mma16(qacc[8], a0,a1,a2,a3, b0,b1);
      }
    }

    // -- repack: q->regs, k->KS, v->VT (all group-private) --
    uint32_t aq[2][4];
    aq[0][0] = pkbf(qacc[0][0]*SCALE, qacc[0][1]*SCALE);
    aq[0][1] = pkbf(qacc[0][2]*SCALE, qacc[0][3]*SCALE);
    aq[0][2] = pkbf(qacc[1][0]*SCALE, qacc[1][1]*SCALE);
    aq[0][3] = pkbf(qacc[1][2]*SCALE, qacc[1][3]*SCALE);
    aq[1][0] = pkbf(qacc[2][0]*SCALE, qacc[2][1]*SCALE);
    aq[1][1] = pkbf(qacc[2][2]*SCALE, qacc[2][3]*SCALE);
    aq[1][2] = 0u; aq[1][3] = 0u;
    #pragma unroll
    for (int f = 0; f < 3; f++){
      int e2 = (f*8 + 2*qc) >> 1;
      u[ksb + (mrow+qr)*20 + e2]   = pkbf(qacc[3+f][0], qacc[3+f][1]);
      u[ksb + (mrow+qr+8)*20 + e2] = pkbf(qacc[3+f][2], qacc[3+f][3]);
    }
    #pragma unroll
    for (int f = 0; f < 3; f++){
      int e0 = f*8 + 2*qc;
      #pragma unroll
      for (int h = 0; h < 2; h++){
        float v0 = qacc[6+f][2*h], v1 = qacc[6+f][2*h+1];
        float p0 = __shfl_xor_sync(0xffffffffu, v0, 4);
        float p1 = __shfl_xor_sync(0xffffffffu, v1, 4);
        if (!(qr & 1)){
          int t2 = (mrow + qr + 8*h) >> 1;
          u[vtb + e0*68 + t2]     = pkbf(v0, p0);
          u[vtb + (e0+1)*68 + t2] = pkbf(v1, p1);
        }
      }
    }
    GROUPBAR(gid);   // KS/VT visible within group

    // -- S GEMM --
    float sacc[16][4];
    #pragma unroll
    for (int f = 0; f < 16; f++)
      #pragma unroll
      for (int j = 0; j < 4; j++) sacc[f][j] = 0.f;
    #pragma unroll
    for (int kg = 0; kg < 2; kg++){
      #pragma unroll
      for (int p = 0; p < 8; p++){
        uint32_t b0,b1,b2,b3;
        uint32_t bP = sb + 4u*(ksb + (uint32_t)(p*16 + bpR)*20 + kg*8 + bpK);
        ldsm4(bP, b0,b1,b2,b3);
        mma16(sacc[2*p],   aq[kg][0],aq[kg][1],aq[kg][2],aq[kg][3], b0,b1);
        mma16(sacc[2*p+1], aq[kg][0],aq[kg][1],aq[kg][2],aq[kg][3], b2,b3);
      }
    }

    // -- warp-local masked softmax + repack P --
    uint32_t pa[8][4];
    {
      int r0 = mrow + qr, r1 = r0 + 8;
      float mx0 = -1e30f, mx1 = -1e30f;
      #pragma unroll
      for (int f = 0; f < 16; f++){
        int c0 = f*8 + 2*qc;
        if (c0     > r0) sacc[f][0] = -1e30f;
        if (c0 + 1 > r0) sacc[f][1] = -1e30f;
        if (c0     > r1) sacc[f][2] = -1e30f;
        if (c0 + 1 > r1) sacc[f][3] = -1e30f;
        mx0 = fmaxf(mx0, fmaxf(sacc[f][0], sacc[f][1]));
        mx1 = fmaxf(mx1, fmaxf(sacc[f][2], sacc[f][3]));
      }
      mx0 = fmaxf(mx0, __shfl_xor_sync(0xffffffffu, mx0, 1));
      mx0 = fmaxf(mx0, __shfl_xor_sync(0xffffffffu, mx0, 2));
      mx1 = fmaxf(mx1, __shfl_xor_sync(0xffffffffu, mx1, 1));
      mx1 = fmaxf(mx1, __shfl_xor_sync(0xffffffffu, mx1, 2));
      float s0 = 0.f, s1 = 0.f;
      #pragma unroll
      for (int f = 0; f < 16; f++){
        sacc[f][0] = __expf(sacc[f][0] - mx0);
        sacc[f][1] = __expf(sacc[f][1] - mx0);
        sacc[f][2] = __expf(sacc[f][2] - mx1);
        sacc[f][3] = __expf(sacc[f][3] - mx1);
        s0 += sacc[f][0] + sacc[f][1];
        s1 += sacc[f][2] + sacc[f][3];
      }
      s0 += __shfl_xor_sync(0xffffffffu, s0, 1);
      s0 += __shfl_xor_sync(0xffffffffu, s0, 2);
      s1 += __shfl_xor_sync(0xffffffffu, s1, 1);
      s1 += __shfl_xor_sync(0xffffffffu, s1, 2);
      float inv0 = 1.f / s0, inv1 = 1.f / s1;
      #pragma unroll
      for (int g = 0; g < 8; g++){
        pa[g][0] = pkbf(sacc[2*g][0]*inv0,   sacc[2*g][1]*inv0);
        pa[g][1] = pkbf(sacc[2*g][2]*inv1,   sacc[2*g][3]*inv1);
        pa[g][2] = pkbf(sacc[2*g+1][0]*inv0, sacc[2*g+1][1]*inv0);
        pa[g][3] = pkbf(sacc[2*g+1][2]*inv1, sacc[2*g+1][3]*inv1);
      }
    }

    // -- O GEMM -> O_all (cols disjoint across groups) --
    {
      float oacc[3][4];
      #pragma unroll
      for (int f = 0; f < 3; f++)
        #pragma unroll
        for (int j = 0; j < 4; j++) oacc[f][j] = 0.f;
      #pragma unroll
      for (int kg = 0; kg < 8; kg++){
        uint32_t b0,b1,b2,b3;
        uint32_t bP = sb + 4u*(vtb + (uint32_t)bpR*68 + kg*8 + bpK);
        ldsm4(bP, b0,b1,b2,b3);
        mma16(oacc[0], pa[kg][0],pa[kg][1],pa[kg][2],pa[kg][3], b0,b1);
        mma16(oacc[1], pa[kg][0],pa[kg][1],pa[kg][2],pa[kg][3], b2,b3);
        uint32_t bQ = sb + 4u*(vtb + (uint32_t)(16 + bRow)*68 + kg*8 + bCoff);
        ldsm2(bQ, b0,b1);
        mma16(oacc[2], pa[kg][0],pa[kg][1],pa[kg][2],pa[kg][3], b0,b1);
      }
      #pragma unroll
      for (int f = 0; f < 3; f++){
        int uc = hh*12 + f*4 + qc;
        u[OALLO + (mrow+qr)*76 + uc]   = pkbf(oacc[f][0], oacc[f][1]);
        u[OALLO + (mrow+qr+8)*76 + uc] = pkbf(oacc[f][2], oacc[f][3]);
      }
    }
    CPA_WAIT0();
    GROUPBAR(gid);   // staged next buf + KS/VT reuse, group-scoped
  }
  __syncthreads();   // OALL + WoT cross-group visibility

  // ---------------- fold (K=144): prefetch w1c0 (group rows), GEMM, stats ----------------
  float x2r[8][4];
  {
    cpcopyg(sb + 4u*(BUF0O + (uint32_t)gid*64u*68u),
            g_wscratch + GW1 + gid*64*68, 1088, gtid);
    CPA_COMMIT();

    #pragma unroll
    for (int f = 0; f < 8; f++)
      #pragma unroll
      for (int j = 0; j < 4; j++) x2r[f][j] = 0.f;

    uint32_t aB = sb + 4u*(OALLO + (uint32_t)(mrow + aRow)*76 + aCoff);
    #pragma unroll
    for (int ks = 0; ks < 9; ks++){
      uint32_t a0,a1,a2,a3;
      ldsm4(aB + ks*32, a0,a1,a2,a3);
      #pragma unroll
      for (int p = 0; p < 4; p++){
        uint32_t b0,b1,b2,b3;
        uint32_t bP = sb + 4u*(WOTO + (uint32_t)(nhalf*64 + p*16 + bpR)*76 + bpK);
        ldsm4(bP + ks*32, b0,b1,b2,b3);
        mma16(x2r[2*p],   a0,a1,a2,a3, b0,b1);
        mma16(x2r[2*p+1], a0,a1,a2,a3, b2,b3);
      }
    }
    int r0 = mrow + qr, r1 = r0 + 8;
    float s0 = 0.f, q0 = 0.f, s1 = 0.f, q1 = 0.f;
    #pragma unroll
    for (int f = 0; f < 8; f++){
      int cc = nhalf*64 + f*8 + 2*qc;
      float2 bv = *(const float2*)&bo[cc];
      float2 xa = *(const float2*)&xb[r0*DM + cc];
      float2 xc = *(const float2*)&xb[r1*DM + cc];
      x2r[f][0] += xa.x + bv.x;  x2r[f][1] += xa.y + bv.y;
      x2r[f][2] += xc.x + bv.x;  x2r[f][3] += xc.y + bv.y;
      s0 += x2r[f][0] + x2r[f][1];
      q0 += x2r[f][0]*x2r[f][0] + x2r[f][1]*x2r[f][1];
      s1 += x2r[f][2] + x2r[f][3];
      q1 += x2r[f][2]*x2r[f][2] + x2r[f][3]*x2r[f][3];
    }
    s0 += __shfl_xor_sync(0xffffffffu, s0, 1); s0 += __shfl_xor_sync(0xffffffffu, s0, 2);
    q0 += __shfl_xor_sync(0xffffffffu, q0, 1); q0 += __shfl_xor_sync(0xffffffffu, q0, 2);
    s1 += __shfl_xor_sync(0xffffffffu, s1, 1); s1 += __shfl_xor_sync(0xffffffffu, s1, 2);
    q1 += __shfl_xor_sync(0xffffffffu, q1, 1); q1 += __shfl_xor_sync(0xffffffffu, q1, 2);
    if (qc == 0){
      st[nhalf*128 + r0] = s0;        st[nhalf*128 + r1] = s1;
      st[256 + nhalf*128 + r0] = q0;  st[256 + nhalf*128 + r1] = q1;
    }
  }
  __syncthreads();   // stats cross-group

  // issue w2c0 + w1c1 (group rows) — overlaps LN2
  cpcopyg(sb + 4u*(OALLO + (uint32_t)gid*64u*68u),
          g_wscratch + GW2 + gid*64*68, 1088, gtid);
  cpcopyg(sb + 4u*(BUF1O + (uint32_t)gid*64u*68u),
          g_wscratch + GW1 + 8704 + gid*64*68, 1088, gtid);
  CPA_COMMIT();

  // ---------------- LN2 finalize -> HS ----------------
  {
    int r0 = mrow + qr, r1 = r0 + 8;
    float S0 = st[r0] + st[128 + r0], Q0 = st[256 + r0] + st[384 + r0];
    float S1 = st[r1] + st[128 + r1], Q1 = st[256 + r1] + st[384 + r1];
    float mu0 = S0 * (1.f/DM), rs0 = rsqrtf(Q0*(1.f/DM) - mu0*mu0 + EPSF);
    float mu1 = S1 * (1.f/DM), rs1 = rsqrtf(Q1*(1.f/DM) - mu1*mu1 + EPSF);
    #pragma unroll
    for (int f = 0; f < 8; f++){
      int cc = nhalf*64 + f*8 + 2*qc;
      float2 gv = *(const float2*)&g2[cc];
      float2 ev = *(const float2*)&be2[cc];
      u[HSO + r0*68 + (cc>>1)] = pkbf((x2r[f][0]-mu0)*rs0*gv.x + ev.x,
                                      (x2r[f][1]-mu0)*rs0*gv.y + ev.y);
      u[HSO + r1*68 + (cc>>1)] = pkbf((x2r[f][2]-mu1)*rs1*gv.x + ev.x,
                                      (x2r[f][3]-mu1)*rs1*gv.y + ev.y);
    }
  }
  PAIRBAR(wl);       // HS rows [mrow,mrow+16) complete (both col halves)
  CPA_WAIT1();       // w1c0 done (w2c0/w1c1 still in flight)
  GROUPBAR(gid);     // w1c0 visible group-wide

  // ---------------- FFN: 4 chunks, scoped barriers ----------------
  float dacc[8][4];
  #pragma unroll
  for (int f = 0; f < 8; f++)
    #pragma unroll
    for (int j = 0; j < 4; j++) dacc[f][j] = 0.f;

  const uint32_t w1s[2] = { BUF0O, BUF1O };
  const uint32_t w2s[2] = { OALLO, 37504u };

  for (int cb = 0; cb < 4; cb++){
    // U GEMM cb (w1 rows group-private)
    {
      float uacc[8][4];
      #pragma unroll
      for (int f = 0; f < 8; f++)
        #pragma unroll
        for (int j = 0; j < 4; j++) uacc[f][j] = 0.f;

      uint32_t aB = sb + 4u*(HSO + (uint32_t)(mrow + aRow)*68 + aCoff);
      #pragma unroll
      for (int ks = 0; ks < 8; ks++){
        uint32_t a0,a1,a2,a3;
        ldsm4(aB + ks*32, a0,a1,a2,a3);
        #pragma unroll
        for (int p = 0; p < 4; p++){
          uint32_t b0,b1,b2,b3;
          uint32_t bP = sb + 4u*(w1s[cb & 1] + (uint32_t)(nhalf*64 + p*16 + bpR)*68 + bpK);
          ldsm4(bP + ks*32, b0,b1,b2,b3);
          mma16(uacc[2*p],   a0,a1,a2,a3, b0,b1);
          mma16(uacc[2*p+1], a0,a1,a2,a3, b2,b3);
        }
      }
      int r0 = mrow + qr, r1 = r0 + 8;
      #pragma unroll
      for (int f = 0; f < 8; f++){
        int cc = nhalf*64 + f*8 + 2*qc;
        float2 bv = *(const float2*)&b1[cb*128 + cc];
        u[UO + r0*68 + (cc>>1)] = pkbf(fmaxf(uacc[f][0] + bv.x, 0.f),
                                       fmaxf(uacc[f][1] + bv.y, 0.f));
        u[UO + r1*68 + (cc>>1)] = pkbf(fmaxf(uacc[f][2] + bv.x, 0.f),
                                       fmaxf(uacc[f][3] + bv.y, 0.f));
      }
    }
    PAIRBAR(wl);     // U rows [mrow,mrow+16) complete for this pair
    GROUPBAR(gid);   // group's w1[cb] reads done -> slot reusable

    // issue next weights (group rows), then guarantee w2[cb]
    if (cb < 3){
      cpcopyg(sb + 4u*(w2s[(cb+1) & 1] + (uint32_t)gid*64u*68u),
              g_wscratch + GW2 + (cb+1)*8704 + gid*64*68, 1088, gtid);
      if (cb < 2)
        cpcopyg(sb + 4u*(w1s[cb & 1] + (uint32_t)gid*64u*68u),
                g_wscratch + GW1 + (cb+2)*8704 + gid*64*68, 1088, gtid);
      CPA_COMMIT();
      CPA_WAIT1();   // all but newest done -> w2[cb] ready
    } else {
      CPA_WAIT0();
    }
    GROUPBAR(gid);   // w2[cb] visible group-wide

    // D2 GEMM cb (w2 rows group-private; U rows pair-private)
    {
      uint32_t aB = sb + 4u*(UO + (uint32_t)(mrow + aRow)*68 + aCoff);
      #pragma unroll
      for (int ks = 0; ks < 8; ks++){
        uint32_t a0,a1,a2,a3;
        ldsm4(aB + ks*32, a0,a1,a2,a3);
        #pragma unroll
        for (int p = 0; p < 4; p++){
          uint32_t b0,b1,b2,b3;
          uint32_t bP = sb + 4u*(w2s[cb & 1] + (uint32_t)(nhalf*64 + p*16 + bpR)*68 + bpK);
          ldsm4(bP + ks*32, b0,b1,b2,b3);
          mma16(dacc[2*p],   a0,a1,a2,a3, b0,b1);
          mma16(dacc[2*p+1], a0,a1,a2,a3, b2,b3);
        }
      }
    }
    PAIRBAR(wl);     // pair's U reads done -> U slot reusable next cb
  }

  // ---------------- epilogue: out = x2 + D2 + b2 ----------------
  {
    int r0 = mrow + qr, r1 = r0 + 8;
    #pragma unroll
    for (int f = 0; f < 8; f++){
      int cc = nhalf*64 + f*8 + 2*qc;
      float2 bv = *(const float2*)&b2[cc];
      float2 o0 = make_float2(x2r[f][0] + dacc[f][0] + bv.x,
                              x2r[f][1] + dacc[f][1] + bv.y);
      float2 o1 = make_float2(x2r[f][2] + dacc[f][2] + bv.x,
                              x2r[f][3] + dacc[f][3] + bv.y);
      *(float2*)&ob[r0*DM + cc] = o0;
      *(float2*)&ob[r1*DM + cc] = o1;
    }
  }
}

extern "C" void kernel_launch(void* const* d_in, const int* in_sizes, int n_in,
                              void* d_out, int out_size)
{
  (void)in_sizes; (void)n_in; (void)out_size;
  prep_weights<<<128, 256>>>(
      (const float*)d_in[1], (const float*)d_in[2], (const float*)d_in[3],
      (const float*)d_in[4], (const float*)d_in[6], (const float*)d_in[8]);
  cudaFuncSetAttribute(decoder_block_kernel,
                       cudaFuncAttributeMaxDynamicSharedMemorySize,
                       SMEM_U32 * 4);
  decoder_block_kernel<<<NB, THREADS, SMEM_U32 * 4>>>(
      (const float*)d_in[0],  (const float*)d_in[5],  (const float*)d_in[7],
      (const float*)d_in[9],  (const float*)d_in[10], (const float*)d_in[11],
      (const float*)d_in[12], (const float*)d_in[13],
      (float*)d_out);
}

// round 16
// speedup vs baseline: 7.2108x; 1.0114x over previous
#include <cuda_runtime.h>
#include <cstdint>

// Fused transformer decoder block. prep kernel packs weights bf16x2; main
// kernel: 1 CTA/batch, 512 threads, mma.sync m16n8k16 bf16 + ldmatrix,
// cp.async pipelined weight staging. FFN: U stays in registers (C->A
// repack), D2 computed as own-K-half partials over all N, combined via an
// fp32 x2 stash in smem. B=512,T=128,D=128,H=6,Dh=21.

#define NB 512
#define TT 128
#define DM 128
#define NH 6
#define DF 512
#define EPSF 1e-5f
#define SCALE 0.21821789023599236f
#define THREADS 512

// global scratch offsets (u32)
#define GQKV 0                 // 3 pairs x [144][68]
#define GWOT 29376             // [128][76]
#define GW1  39104             // 4 chunks x [128][68]
#define GW2  73920             // 4 chunks x [128][68]
#define GTOT 108736
__device__ __align__(16) uint32_t g_wscratch[GTOT];

__device__ __forceinline__ uint32_t pkbf(float lo, float hi){
  uint32_t r; asm("cvt.rn.bf16x2.f32 %0, %1, %2;" : "=r"(r) : "f"(hi), "f"(lo));
  return r;
}
__device__ __forceinline__ void mma16(float* d, uint32_t a0, uint32_t a1,
                                      uint32_t a2, uint32_t a3,
                                      uint32_t b0, uint32_t b1){
  asm volatile("mma.sync.aligned.m16n8k16.row.col.f32.bf16.bf16.f32 "
    "{%0,%1,%2,%3},{%4,%5,%6,%7},{%8,%9},{%0,%1,%2,%3};"
    : "+f"(d[0]), "+f"(d[1]), "+f"(d[2]), "+f"(d[3])
    : "r"(a0), "r"(a1), "r"(a2), "r"(a3), "r"(b0), "r"(b1));
}
__device__ __forceinline__ void ldsm4(uint32_t addr, uint32_t& a0, uint32_t& a1,
                                      uint32_t& a2, uint32_t& a3){
  asm volatile("ldmatrix.sync.aligned.m8n8.x4.shared.b16 {%0,%1,%2,%3},[%4];"
    : "=r"(a0),"=r"(a1),"=r"(a2),"=r"(a3) : "r"(addr));
}
__device__ __forceinline__ void ldsm2(uint32_t addr, uint32_t& b0, uint32_t& b1){
  asm volatile("ldmatrix.sync.aligned.m8n8.x2.shared.b16 {%0,%1},[%2];"
    : "=r"(b0),"=r"(b1) : "r"(addr));
}
__device__ __forceinline__ uint32_t smem_u32_of(const void* p){
  uint32_t a;
  asm("{ .reg .u64 t; cvta.to.shared.u64 t, %1; cvt.u32.u64 %0, t; }" : "=r"(a) : "l"(p));
  return a;
}
__device__ __forceinline__ void cpa16(uint32_t sdst, const uint32_t* gsrc){
  asm volatile("cp.async.cg.shared.global [%0],[%1],16;" :: "r"(sdst), "l"(gsrc));
}
__device__ __forceinline__ void cpcopyg(uint32_t sdst, const uint32_t* gsrc,
                                        int nchunks, int gtid){
  for (int i = gtid; i < nchunks; i += 256)
    cpa16(sdst + 16u*(uint32_t)i, gsrc + 4*i);
}
#define CPA_COMMIT()  asm volatile("cp.async.commit_group;" ::: "memory")
#define CPA_WAIT0()   asm volatile("cp.async.wait_group 0;" ::: "memory")
#define CPA_WAIT1()   asm volatile("cp.async.wait_group 1;" ::: "memory")
#define GROUPBAR(g)   asm volatile("bar.sync %0, 256;" :: "r"(1 + (g)) : "memory")
#define PAIRBAR(id)   asm volatile("bar.sync %0, 64;"  :: "r"(3 + (id)) : "memory")

// ================= prep kernel =================
extern "C" __global__ void prep_weights(const float* __restrict__ Wq,
                                        const float* __restrict__ Wk,
                                        const float* __restrict__ Wv,
                                        const float* __restrict__ Wo,
                                        const float* __restrict__ W1,
                                        const float* __restrict__ W2)
{
  int tid = blockIdx.x*blockDim.x + threadIdx.x;
  int NT  = gridDim.x*blockDim.x;
  for (int idx = tid; idx < 3*144*68; idx += NT){
    int p = idx / (144*68), rem = idx - p*(144*68);
    int nn = rem / 68, k2 = rem - nn*68;
    uint32_t val = 0u;
    if (k2 < 64){
      int hh = p*2 + (nn >= 72 ? 1 : 0);
      int n0 = (nn >= 72) ? nn - 72 : nn;
      const float* Wsrc = 0; int col = 0;
      if (n0 < 21)                  { Wsrc = Wq + hh*2688; col = n0; }
      else if (n0 >= 24 && n0 < 45) { Wsrc = Wk + hh*2688; col = n0 - 24; }
      else if (n0 >= 48 && n0 < 69) { Wsrc = Wv + hh*2688; col = n0 - 48; }
      if (Wsrc) val = pkbf(Wsrc[(2*k2)*21 + col], Wsrc[(2*k2+1)*21 + col]);
    }
    g_wscratch[GQKV + p*9792 + nn*68 + k2] = val;
  }
  for (int idx = tid; idx < 128*76; idx += NT){
    int n = idx / 76, k2 = idx - n*76;
    uint32_t val = 0u;
    if (k2 < 72){
      int head = k2 / 12, within = k2 - head*12;
      int e0 = 2*within;
      float lo = (e0     < 21) ? Wo[(head*21 + e0    )*DM + n] : 0.f;
      float hi = (e0 + 1 < 21) ? Wo[(head*21 + e0 + 1)*DM + n] : 0.f;
      val = pkbf(lo, hi);
    }
    g_wscratch[GWOT + idx] = val;
  }
  for (int idx = tid; idx < 4*128*68; idx += NT){
    int c = idx / (128*68), rem = idx - c*(128*68);
    int n = rem / 68, k2 = rem - n*68;
    uint32_t val = 0u;
    if (k2 < 64)
      val = pkbf(W1[(2*k2)*DF + c*128 + n], W1[(2*k2+1)*DF + c*128 + n]);
    g_wscratch[GW1 + c*8704 + n*68 + k2] = val;
  }
  for (int idx = tid; idx < 4*128*68; idx += NT){
    int c = idx / (128*68), rem = idx - c*(128*68);
    int n = rem / 68, k2 = rem - n*68;
    uint32_t val = 0u;
    if (k2 < 64)
      val = pkbf(W2[(c*128 + 2*k2)*DM + n], W2[(c*128 + 2*k2+1)*DM + n]);
    g_wscratch[GW2 + c*8704 + n*68 + k2] = val;
  }
}

// ================= main kernel =================
// smem (u32): HS 0(8704) | STAT 8704(512) | BUF0 9216(9792) | BUF1 19008(9792)
//   | OALL/w2 28800(9728) | XS2 38528 (128x132 fp32 = 16896)
// Attention-time overlays inside XS2 region: KS0 38528, KS1 41088,
//   VT0 43648, VT1 45280. WoT overlays BUF1 during fold.
#define HSO   0
#define STATO 8704
#define BUF0O 9216
#define BUF1O 19008
#define OALLO 28800
#define XS2O  38528
#define KS0O  38528
#define KS1O  41088
#define VT0O  43648
#define VT1O  45280
#define WOTO  19008
#define SMEM_U32 55424   // 221696 bytes

extern "C" __global__ void __launch_bounds__(THREADS, 1)
decoder_block_kernel(const float* __restrict__ gx,
                     const float* __restrict__ bo,
                     const float* __restrict__ b1,
                     const float* __restrict__ b2,
                     const float* __restrict__ g1,
                     const float* __restrict__ be1,
                     const float* __restrict__ g2,
                     const float* __restrict__ be2,
                     float* __restrict__ gout)
{
  extern __shared__ float sm[];
  uint32_t* u = (uint32_t*)sm;

  const int tid   = threadIdx.x;
  const int lane  = tid & 31;
  const int w     = tid >> 5;
  const int b     = blockIdx.x;
  const int qr    = lane >> 2;
  const int qc    = lane & 3;
  const int gid   = w >> 3;
  const int wl    = w & 7;
  const int gtid  = tid & 255;
  const int mrow  = wl * 16;
  const int nhalf = gid;

  const int aRow  = (lane & 7) + 8*((lane >> 3) & 1);
  const int aCoff = 4*(lane >> 4);
  const int bRow  = lane & 7;
  const int bCoff = 4*((lane >> 3) & 1);
  const int bpR   = (lane & 7) + ((lane >> 4) << 3);
  const int bpK   = ((lane >> 3) & 1) * 4;

  const uint32_t sb = smem_u32_of(sm);
  float* st  = (float*)&u[STATO];
  float* xs2 = (float*)&u[XS2O];

  const uint32_t ksb = gid ? KS1O : KS0O;
  const uint32_t vtb = gid ? VT1O : VT0O;

  const float* xb = gx   + (size_t)b * (TT * DM);
  float*       ob = gout + (size_t)b * (TT * DM);

  // ---------------- init: pair-0 copy (group rows), KS pads, LN1 ----------------
  {
    cpcopyg(sb + 4u*(BUF0O + (uint32_t)gid*72u*68u),
            g_wscratch + GQKV + gid*72*68, 1224, gtid);
    CPA_COMMIT();

    for (int idx = tid; idx < 2048; idx += THREADS){
      int r = idx >> 3, j = idx & 7;
      uint32_t base = (j < 4) ? KS0O : KS1O;
      u[base + r*20 + 12 + (j & 3)] = 0u;
    }
    float2 ga = *(const float2*)&g1[2*lane];
    float2 gb = *(const float2*)&g1[64 + 2*lane];
    float2 ea = *(const float2*)&be1[2*lane];
    float2 eb = *(const float2*)&be1[64 + 2*lane];
    for (int r = w; r < TT; r += 16){
      float2 xa = *(const float2*)&xb[r*DM + 2*lane];
      float2 xc = *(const float2*)&xb[r*DM + 64 + 2*lane];
      float s  = xa.x + xa.y + xc.x + xc.y;
      float s2 = xa.x*xa.x + xa.y*xa.y + xc.x*xc.x + xc.y*xc.y;
      #pragma unroll
      for (int o = 16; o > 0; o >>= 1){
        s  += __shfl_xor_sync(0xffffffffu, s, o);
        s2 += __shfl_xor_sync(0xffffffffu, s2, o);
      }
      float mu = s * (1.f/DM);
      float rs = rsqrtf(s2 * (1.f/DM) - mu*mu + EPSF);
      u[HSO + r*68 + lane]      = pkbf((xa.x - mu)*rs*ga.x + ea.x,
                                       (xa.y - mu)*rs*ga.y + ea.y);
      u[HSO + r*68 + 32 + lane] = pkbf((xc.x - mu)*rs*gb.x + eb.x,
                                       (xc.y - mu)*rs*gb.y + eb.y);
    }
    CPA_WAIT0();
  }
  __syncthreads();

  // ---------------- attention: 3 head pairs (unchanged from R15) ----------------
  for (int pr = 0; pr < 3; pr++){
    const int hh = pr*2 + gid;
    const uint32_t wbuf = (pr & 1) ? BUF1O : BUF0O;
    const uint32_t wrow = (uint32_t)gid * 72u;

    if (pr < 2)
      cpcopyg(sb + 4u*(((pr & 1) ? BUF0O : BUF1O) + wrow*68u),
              g_wscratch + GQKV + (pr+1)*9792 + gid*72*68, 1224, gtid);
    else
      cpcopyg(sb + 4u*(WOTO + (uint32_t)gid*64u*76u),
              g_wscratch + GWOT + gid*64*76, 1216, gtid);
    CPA_COMMIT();

    float qacc[9][4];
    #pragma unroll
    for (int f = 0; f < 9; f++)
      #pragma unroll
      for (int j = 0; j < 4; j++) qacc[f][j] = 0.f;
    {
      uint32_t aB = sb + 4u*(HSO + (uint32_t)(mrow + aRow)*68 + aCoff);
      uint32_t bP[4], b8;
      #pragma unroll
      for (int p = 0; p < 4; p++)
        bP[p] = sb + 4u*(wbuf + (wrow + p*16 + bpR)*68 + bpK);
      b8 = sb + 4u*(wbuf + (wrow + 64 + bRow)*68 + bCoff);
      #pragma unroll
      for (int ks = 0; ks < 8; ks++){
        uint32_t a0,a1,a2,a3, b0,b1,b2,b3;
        ldsm4(aB + ks*32, a0,a1,a2,a3);
        #pragma unroll
        for (int p = 0; p < 4; p++){
          ldsm4(bP[p] + ks*32, b0,b1,b2,b3);
          mma16(qacc[2*p],   a0,a1,a2,a3, b0,b1);
          mma16(qacc[2*p+1], a0,a1,a2,a3, b2,b3);
        }
        ldsm2(b8 + ks*32, b0,b1);
        mma16(qacc[8], a0,a1,a2,a3, b0,b1);
      }
    }

    uint32_t aq[2][4];
    aq[0][0] = pkbf(qacc[0][0]*SCALE, qacc[0][1]*SCALE);
    aq[0][1] = pkbf(qacc[0][2]*SCALE, qacc[0][3]*SCALE);
    aq[0][2] = pkbf(qacc[1][0]*SCALE, qacc[1][1]*SCALE);
    aq[0][3] = pkbf(qacc[1][2]*SCALE, qacc[1][3]*SCALE);
    aq[1][0] = pkbf(qacc[2][0]*SCALE, qacc[2][1]*SCALE);
    aq[1][1] = pkbf(qacc[2][2]*SCALE, qacc[2][3]*SCALE);
    aq[1][2] = 0u; aq[1][3] = 0u;
    #pragma unroll
    for (int f = 0; f < 3; f++){
      int e2 = (f*8 + 2*qc) >> 1;
      u[ksb + (mrow+qr)*20 + e2]   = pkbf(qacc[3+f][0], qacc[3+f][1]);
      u[ksb + (mrow+qr+8)*20 + e2] = pkbf(qacc[3+f][2], qacc[3+f][3]);
    }
    #pragma unroll
    for (int f = 0; f < 3; f++){
      int e0 = f*8 + 2*qc;
      #pragma unroll
      for (int h = 0; h < 2; h++){
        float v0 = qacc[6+f][2*h], v1 = qacc[6+f][2*h+1];
        float p0 = __shfl_xor_sync(0xffffffffu, v0, 4);
        float p1 = __shfl_xor_sync(0xffffffffu, v1, 4);
        if (!(qr & 1)){
          int t2 = (mrow + qr + 8*h) >> 1;
          u[vtb + e0*68 + t2]     = pkbf(v0, p0);
          u[vtb + (e0+1)*68 + t2] = pkbf(v1, p1);
        }
      }
    }
    GROUPBAR(gid);

    float sacc[16][4];
    #pragma unroll
    for (int f = 0; f < 16; f++)
      #pragma unroll
      for (int j = 0; j < 4; j++) sacc[f][j] = 0.f;
    #pragma unroll
    for (int kg = 0; kg < 2; kg++){
      #pragma unroll
      for (int p = 0; p < 8; p++){
        uint32_t b0,b1,b2,b3;
        uint32_t bP = sb + 4u*(ksb + (uint32_t)(p*16 + bpR)*20 + kg*8 + bpK);
        ldsm4(bP, b0,b1,b2,b3);
        mma16(sacc[2*p],   aq[kg][0],aq[kg][1],aq[kg][2],aq[kg][3], b0,b1);
        mma16(sacc[2*p+1], aq[kg][0],aq[kg][1],aq[kg][2],aq[kg][3], b2,b3);
      }
    }

    uint32_t pa[8][4];
    {
      int r0 = mrow + qr, r1 = r0 + 8;
      float mx0 = -1e30f, mx1 = -1e30f;
      #pragma unroll
      for (int f = 0; f < 16; f++){
        int c0 = f*8 + 2*qc;
        if (c0     > r0) sacc[f][0] = -1e30f;
        if (c0 + 1 > r0) sacc[f][1] = -1e30f;
        if (c0     > r1) sacc[f][2] = -1e30f;
        if (c0 + 1 > r1) sacc[f][3] = -1e30f;
        mx0 = fmaxf(mx0, fmaxf(sacc[f][0], sacc[f][1]));
        mx1 = fmaxf(mx1, fmaxf(sacc[f][2], sacc[f][3]));
      }
      mx0 = fmaxf(mx0, __shfl_xor_sync(0xffffffffu, mx0, 1));
      mx0 = fmaxf(mx0, __shfl_xor_sync(0xffffffffu, mx0, 2));
      mx1 = fmaxf(mx1, __shfl_xor_sync(0xffffffffu, mx1, 1));
      mx1 = fmaxf(mx1, __shfl_xor_sync(0xffffffffu, mx1, 2));
      float s0 = 0.f, s1 = 0.f;
      #pragma unroll
      for (int f = 0; f < 16; f++){
        sacc[f][0] = __expf(sacc[f][0] - mx0);
        sacc[f][1] = __expf(sacc[f][1] - mx0);
        sacc[f][2] = __expf(sacc[f][2] - mx1);
        sacc[f][3] = __expf(sacc[f][3] - mx1);
        s0 += sacc[f][0] + sacc[f][1];
        s1 += sacc[f][2] + sacc[f][3];
      }
      s0 += __shfl_xor_sync(0xffffffffu, s0, 1);
      s0 += __shfl_xor_sync(0xffffffffu, s0, 2);
      s1 += __shfl_xor_sync(0xffffffffu, s1, 1);
      s1 += __shfl_xor_sync(0xffffffffu, s1, 2);
      float inv0 = 1.f / s0, inv1 = 1.f / s1;
      #pragma unroll
      for (int g = 0; g < 8; g++){
        pa[g][0] = pkbf(sacc[2*g][0]*inv0,   sacc[2*g][1]*inv0);
        pa[g][1] = pkbf(sacc[2*g][2]*inv1,   sacc[2*g][3]*inv1);
        pa[g][2] = pkbf(sacc[2*g+1][0]*inv0, sacc[2*g+1][1]*inv0);
        pa[g][3] = pkbf(sacc[2*g+1][2]*inv1, sacc[2*g+1][3]*inv1);
      }
    }

    {
      float oacc[3][4];
      #pragma unroll
      for (int f = 0; f < 3; f++)
        #pragma unroll
        for (int j = 0; j < 4; j++) oacc[f][j] = 0.f;
      #pragma unroll
      for (int kg = 0; kg < 8; kg++){
        uint32_t b0,b1,b2,b3;
        uint32_t bP = sb + 4u*(vtb + (uint32_t)bpR*68 + kg*8 + bpK);
        ldsm4(bP, b0,b1,b2,b3);
        mma16(oacc[0], pa[kg][0],pa[kg][1],pa[kg][2],pa[kg][3], b0,b1);
        mma16(oacc[1], pa[kg][0],pa[kg][1],pa[kg][2],pa[kg][3], b2,b3);
        uint32_t bQ = sb + 4u*(vtb + (uint32_t)(16 + bRow)*68 + kg*8 + bCoff);
        ldsm2(bQ, b0,b1);
        mma16(oacc[2], pa[kg][0],pa[kg][1],pa[kg][2],pa[kg][3], b0,b1);
      }
      #pragma unroll
      for (int f = 0; f < 3; f++){
        int uc = hh*12 + f*4 + qc;
        u[OALLO + (mrow+qr)*76 + uc]   = pkbf(oacc[f][0], oacc[f][1]);
        u[OALLO + (mrow+qr+8)*76 + uc] = pkbf(oacc[f][2], oacc[f][3]);
      }
    }
    CPA_WAIT0();
    GROUPBAR(gid);
  }
  __syncthreads();   // OALL + WoT cross-group visibility

  // ---------------- fold (K=144) -> x2 frags; LN2 stats ----------------
  float x2r[8][4];
  {
    cpcopyg(sb + 4u*(BUF0O + (uint32_t)gid*64u*68u),
            g_wscratch + GW1 + gid*64*68, 1088, gtid);     // w1c0
    CPA_COMMIT();

    #pragma unroll
    for (int f = 0; f < 8; f++)
      #pragma unroll
      for (int j = 0; j < 4; j++) x2r[f][j] = 0.f;

    uint32_t aB = sb + 4u*(OALLO + (uint32_t)(mrow + aRow)*76 + aCoff);
    #pragma unroll
    for (int ks = 0; ks < 9; ks++){
      uint32_t a0,a1,a2,a3;
      ldsm4(aB + ks*32, a0,a1,a2,a3);
      #pragma unroll
      for (int p = 0; p < 4; p++){
        uint32_t b0,b1,b2,b3;
        uint32_t bP = sb + 4u*(WOTO + (uint32_t)(nhalf*64 + p*16 + bpR)*76 + bpK);
        ldsm4(bP + ks*32, b0,b1,b2,b3);
        mma16(x2r[2*p],   a0,a1,a2,a3, b0,b1);
        mma16(x2r[2*p+1], a0,a1,a2,a3, b2,b3);
      }
    }
    int r0 = mrow + qr, r1 = r0 + 8;
    float s0 = 0.f, q0 = 0.f, s1 = 0.f, q1 = 0.f;
    #pragma unroll
    for (int f = 0; f < 8; f++){
      int cc = nhalf*64 + f*8 + 2*qc;
      float2 bv = *(const float2*)&bo[cc];
      float2 xa = *(const float2*)&xb[r0*DM + cc];
      float2 xc = *(const float2*)&xb[r1*DM + cc];
      x2r[f][0] += xa.x + bv.x;  x2r[f][1] += xa.y + bv.y;
      x2r[f][2] += xc.x + bv.x;  x2r[f][3] += xc.y + bv.y;
      s0 += x2r[f][0] + x2r[f][1];
      q0 += x2r[f][0]*x2r[f][0] + x2r[f][1]*x2r[f][1];
      s1 += x2r[f][2] + x2r[f][3];
      q1 += x2r[f][2]*x2r[f][2] + x2r[f][3]*x2r[f][3];
    }
    s0 += __shfl_xor_sync(0xffffffffu, s0, 1); s0 += __shfl_xor_sync(0xffffffffu, s0, 2);
    q0 += __shfl_xor_sync(0xffffffffu, q0, 1); q0 += __shfl_xor_sync(0xffffffffu, q0, 2);
    s1 += __shfl_xor_sync(0xffffffffu, s1, 1); s1 += __shfl_xor_sync(0xffffffffu, s1, 2);
    q1 += __shfl_xor_sync(0xffffffffu, q1, 1); q1 += __shfl_xor_sync(0xffffffffu, q1, 2);
    if (qc == 0){
      st[nhalf*128 + r0] = s0;        st[nhalf*128 + r1] = s1;
      st[256 + nhalf*128 + r0] = q0;  st[256 + nhalf*128 + r1] = q1;
    }
  }
  __syncthreads();   // stats; fold reads of OALL/WoT complete

  // issue w2c0 -> OALLO, w1c1 -> BUF1 (overlaps LN2)
  cpcopyg(sb + 4u*(OALLO + (uint32_t)gid*64u*68u),
          g_wscratch + GW2 + gid*64*68, 1088, gtid);
  cpcopyg(sb + 4u*(BUF1O + (uint32_t)gid*64u*68u),
          g_wscratch + GW1 + 8704 + gid*64*68, 1088, gtid);
  CPA_COMMIT();

  // ---------------- LN2 -> HS ; stash x2 fp32 -> XS2 ----------------
  {
    int r0 = mrow + qr, r1 = r0 + 8;
    float S0 = st[r0] + st[128 + r0], Q0 = st[256 + r0] + st[384 + r0];
    float S1 = st[r1] + st[128 + r1], Q1 = st[256 + r1] + st[384 + r1];
    float mu0 = S0 * (1.f/DM), rs0 = rsqrtf(Q0*(1.f/DM) - mu0*mu0 + EPSF);
    float mu1 = S1 * (1.f/DM), rs1 = rsqrtf(Q1*(1.f/DM) - mu1*mu1 + EPSF);
    #pragma unroll
    for (int f = 0; f < 8; f++){
      int cc = nhalf*64 + f*8 + 2*qc;
      float2 gv = *(const float2*)&g2[cc];
      float2 ev = *(const float2*)&be2[cc];
      u[HSO + r0*68 + (cc>>1)] = pkbf((x2r[f][0]-mu0)*rs0*gv.x + ev.x,
                                      (x2r[f][1]-mu0)*rs0*gv.y + ev.y);
      u[HSO + r1*68 + (cc>>1)] = pkbf((x2r[f][2]-mu1)*rs1*gv.x + ev.x,
                                      (x2r[f][3]-mu1)*rs1*gv.y + ev.y);
      *(float2*)&xs2[r0*132 + cc] = make_float2(x2r[f][0], x2r[f][1]);
      *(float2*)&xs2[r1*132 + cc] = make_float2(x2r[f][2], x2r[f][3]);
    }
  }
  PAIRBAR(wl);       // HS + XS2 rows [mrow,mrow+16) complete (both halves)
  CPA_WAIT1();       // w1c0 done
  GROUPBAR(gid);     // w1c0 visible group-wide

  // ---------------- FFN: 4 chunks; U in registers; dacc = own-K partials ----------------
  float dacc[16][4];
  #pragma unroll
  for (int f = 0; f < 16; f++)
    #pragma unroll
    for (int j = 0; j < 4; j++) dacc[f][j] = 0.f;

  const uint32_t w1s[2] = { BUF0O, BUF1O };

  for (int cb = 0; cb < 4; cb++){
    // U GEMM cb (A=HS, B=w1[cb] own-half rows) -> uacc -> ua regs
    uint32_t ua[4][4];
    {
      float uacc[8][4];
      #pragma unroll
      for (int f = 0; f < 8; f++)
        #pragma unroll
        for (int j = 0; j < 4; j++) uacc[f][j] = 0.f;

      uint32_t aB = sb + 4u*(HSO + (uint32_t)(mrow + aRow)*68 + aCoff);
      #pragma unroll
      for (int ks = 0; ks < 8; ks++){
        uint32_t a0,a1,a2,a3;
        ldsm4(aB + ks*32, a0,a1,a2,a3);
        #pragma unroll
        for (int p = 0; p < 4; p++){
          uint32_t b0,b1,b2,b3;
          uint32_t bP = sb + 4u*(w1s[cb & 1] + (uint32_t)(nhalf*64 + p*16 + bpR)*68 + bpK);
          ldsm4(bP + ks*32, b0,b1,b2,b3);
          mma16(uacc[2*p],   a0,a1,a2,a3, b0,b1);
          mma16(uacc[2*p+1], a0,a1,a2,a3, b2,b3);
        }
      }
      // bias + relu + repack C->A (own K-half kg groups)
      #pragma unroll
      for (int j = 0; j < 4; j++){
        int cc0 = nhalf*64 + (2*j)*8 + 2*qc;
        float2 bA = *(const float2*)&b1[cb*128 + cc0];
        float2 bB = *(const float2*)&b1[cb*128 + cc0 + 8];
        float a00 = fmaxf(uacc[2*j][0] + bA.x, 0.f);
        float a01 = fmaxf(uacc[2*j][1] + bA.y, 0.f);
        float a10 = fmaxf(uacc[2*j][2] + bA.x, 0.f);
        float a11 = fmaxf(uacc[2*j][3] + bA.y, 0.f);
        float c00 = fmaxf(uacc[2*j+1][0] + bB.x, 0.f);
        float c01 = fmaxf(uacc[2*j+1][1] + bB.y, 0.f);
        float c10 = fmaxf(uacc[2*j+1][2] + bB.x, 0.f);
        float c11 = fmaxf(uacc[2*j+1][3] + bB.y, 0.f);
        ua[j][0] = pkbf(a00, a01);
        ua[j][1] = pkbf(a10, a11);
        ua[j][2] = pkbf(c00, c01);
        ua[j][3] = pkbf(c10, c11);
      }
    }
    CPA_WAIT0();       // w2[cb] (+w1[cb+1]) arrived
    __syncthreads();   // w2[cb] visible block-wide (both groups' copy halves)

    // D2 partial: own K-half (4 kg), ALL 128 output cols
    #pragma unroll
    for (int j = 0; j < 4; j++){
      #pragma unroll
      for (int p = 0; p < 8; p++){
        uint32_t b0,b1,b2,b3;
        uint32_t bP = sb + 4u*(OALLO + (uint32_t)(p*16 + bpR)*68
                               + (uint32_t)(nhalf*4 + j)*8 + bpK);
        ldsm4(bP, b0,b1,b2,b3);
        mma16(dacc[2*p],   ua[j][0],ua[j][1],ua[j][2],ua[j][3], b0,b1);
        mma16(dacc[2*p+1], ua[j][0],ua[j][1],ua[j][2],ua[j][3], b2,b3);
      }
    }
    __syncthreads();   // w2[cb] reads done -> slot reusable

    if (cb < 3){
      cpcopyg(sb + 4u*(OALLO + (uint32_t)gid*64u*68u),
              g_wscratch + GW2 + (cb+1)*8704 + gid*64*68, 1088, gtid);
      if (cb < 2)
        cpcopyg(sb + 4u*(w1s[cb & 1] + (uint32_t)gid*64u*68u),
                g_wscratch + GW1 + (cb+2)*8704 + gid*64*68, 1088, gtid);
      CPA_COMMIT();
    }
  }

  // ---------------- combine partials + epilogue ----------------
  if (nhalf == 0){
    int r0 = mrow + qr, r1 = r0 + 8;
    #pragma unroll
    for (int g = 0; g < 16; g++){
      int col = (g >> 1)*16 + (g & 1)*8 + 2*qc;
      float2 v0 = *(const float2*)&xs2[r0*132 + col];
      float2 v1 = *(const float2*)&xs2[r1*132 + col];
      v0.x += dacc[g][0]; v0.y += dacc[g][1];
      v1.x += dacc[g][2]; v1.y += dacc[g][3];
      *(float2*)&xs2[r0*132 + col] = v0;
      *(float2*)&xs2[r1*132 + col] = v1;
    }
  }
  PAIRBAR(wl);
  if (nhalf == 1){
    int r0 = mrow + qr, r1 = r0 + 8;
    #pragma unroll
    for (int g = 0; g < 16; g++){
      int col = (g >> 1)*16 + (g & 1)*8 + 2*qc;
      float2 bv = *(const float2*)&b2[col];
      float2 v0 = *(const float2*)&xs2[r0*132 + col];
      float2 v1 = *(const float2*)&xs2[r1*132 + col];
      float2 o0 = make_float2(v0.x + dacc[g][0] + bv.x, v0.y + dacc[g][1] + bv.y);
      float2 o1 = make_float2(v1.x + dacc[g][2] + bv.x, v1.y + dacc[g][3] + bv.y);
      *(float2*)&ob[r0*DM + col] = o0;
      *(float2*)&ob[r1*DM + col] = o1;
    }
  }
}

extern "C" void kernel_launch(void* const* d_in, const int* in_sizes, int n_in,
                              void* d_out, int out_size)
{
  (void)in_sizes; (void)n_in; (void)out_size;
  prep_weights<<<128, 256>>>(
      (const float*)d_in[1], (const float*)d_in[2], (const float*)d_in[3],
      (const float*)d_in[4], (const float*)d_in[6], (const float*)d_in[8]);
  cudaFuncSetAttribute(decoder_block_kernel,
                       cudaFuncAttributeMaxDynamicSharedMemorySize,
                       SMEM_U32 * 4);
  decoder_block_kernel<<<NB, THREADS, SMEM_U32 * 4>>>(
      (const float*)d_in[0],  (const float*)d_in[5],  (const float*)d_in[7],
      (const float*)d_in[9],  (const float*)d_in[10], (const float*)d_in[11],
      (const float*)d_in[12], (const float*)d_in[13],
      (float*)d_out);
}